// round 7
// baseline (speedup 1.0000x reference)
#include <cuda_runtime.h>
#include <cuda_bf16.h>
#include <math.h>
#include <stdint.h>

#define BB   2
#define SS   2048
#define DD   2048
#define HQ   32
#define HKV  8
#define DH   64
#define KDIM 2048

// ---------------------------------------------------------------------------
// Scratch (allocation-free rule: __device__ globals)
// ---------------------------------------------------------------------------
__device__ __nv_bfloat16 g_Xh[(size_t)BB * SS * DD];
__device__ __nv_bfloat16 g_Xl[(size_t)BB * SS * DD];
__device__ __nv_bfloat16 g_Wqh[(size_t)HQ * DH * DD];
__device__ __nv_bfloat16 g_Wql[(size_t)HQ * DH * DD];
__device__ __nv_bfloat16 g_Wkh[(size_t)HKV * DH * DD];
__device__ __nv_bfloat16 g_Wkl[(size_t)HKV * DH * DD];
__device__ __nv_bfloat16 g_Wvh[(size_t)HKV * DH * DD];
__device__ __nv_bfloat16 g_Wvl[(size_t)HKV * DH * DD];
__device__ __nv_bfloat16 g_Woh[(size_t)DD * DD];
__device__ __nv_bfloat16 g_Wol[(size_t)DD * DD];
__device__ __nv_bfloat16 g_Oh[(size_t)BB * SS * DD];
__device__ __nv_bfloat16 g_Ol[(size_t)BB * SS * DD];

__device__ __nv_bfloat16 g_Qbh[(size_t)BB * HQ  * SS * DH];
__device__ __nv_bfloat16 g_Qbl[(size_t)BB * HQ  * SS * DH];
__device__ __nv_bfloat16 g_Kbh[(size_t)BB * HKV * SS * DH];
__device__ __nv_bfloat16 g_Kbl[(size_t)BB * HKV * SS * DH];
__device__ __nv_bfloat16 g_Vbh[(size_t)BB * HKV * SS * DH];
__device__ __nv_bfloat16 g_Vbl[(size_t)BB * HKV * SS * DH];

// ---------------------------------------------------------------------------
// helpers
// ---------------------------------------------------------------------------
__device__ __forceinline__ uint32_t s2u(const void* p) {
    uint32_t r;
    asm("{ .reg .u64 t; cvta.to.shared.u64 t, %1; cvt.u32.u64 %0, t; }"
        : "=r"(r) : "l"(p));
    return r;
}

#define LDM4(r, addr)                                                         \
    asm volatile("ldmatrix.sync.aligned.m8n8.x4.shared.b16 {%0,%1,%2,%3}, [%4];" \
        : "=r"((r)[0]), "=r"((r)[1]), "=r"((r)[2]), "=r"((r)[3]) : "r"(addr))

#define LDM4T(r, addr)                                                        \
    asm volatile("ldmatrix.sync.aligned.m8n8.x4.trans.shared.b16 {%0,%1,%2,%3}, [%4];" \
        : "=r"((r)[0]), "=r"((r)[1]), "=r"((r)[2]), "=r"((r)[3]) : "r"(addr))

#define MMA_BF16(c, a, b0, b1)                                                \
    asm volatile("mma.sync.aligned.m16n8k16.row.col.f32.bf16.bf16.f32 "       \
        "{%0,%1,%2,%3}, {%4,%5,%6,%7}, {%8,%9}, {%0,%1,%2,%3};"               \
        : "+f"((c)[0]), "+f"((c)[1]), "+f"((c)[2]), "+f"((c)[3])              \
        : "r"((a)[0]), "r"((a)[1]), "r"((a)[2]), "r"((a)[3]), "r"(b0), "r"(b1))

#define CP_ASYNC16(dst, src)                                                  \
    asm volatile("cp.async.cg.shared.global [%0], [%1], 16;" :: "r"(dst), "l"(src))

__device__ __forceinline__ uint32_t pack_bf2(float a, float b) {
    __nv_bfloat162 t = __floats2bfloat162_rn(a, b);
    return *reinterpret_cast<uint32_t*>(&t);
}

__device__ __forceinline__ void split2_store(__nv_bfloat16* H, __nv_bfloat16* L,
                                             size_t base, float x1, float x2)
{
    __nv_bfloat16 h1 = __float2bfloat16(x1);
    __nv_bfloat16 h2 = __float2bfloat16(x2);
    __nv_bfloat16 l1 = __float2bfloat16(x1 - __bfloat162float(h1));
    __nv_bfloat16 l2 = __float2bfloat16(x2 - __bfloat162float(h2));
    *reinterpret_cast<__nv_bfloat162*>(H + base) = __nv_bfloat162(h1, h2);
    *reinterpret_cast<__nv_bfloat162*>(L + base) = __nv_bfloat162(l1, l2);
}

// ---------------------------------------------------------------------------
// merged input splits: one launch handles x, Wq, Wk, Wv, Wo
// ---------------------------------------------------------------------------
struct SplitJobs {
    const float4* in[5];
    __nv_bfloat162* hi[5];
    __nv_bfloat162* lo[5];
    int blk_end[5];    // cumulative block counts
};

__global__ void split_all(SplitJobs jobs)
{
    int bx = blockIdx.x;
    int job = 0;
#pragma unroll
    for (int k = 0; k < 5; ++k)
        if (bx >= jobs.blk_end[k]) job = k + 1;
    int blk0 = (job == 0) ? 0 : jobs.blk_end[job - 1];
    int i = (bx - blk0) * blockDim.x + threadIdx.x;

    float4 a = jobs.in[job][i];
    __nv_bfloat16 h0 = __float2bfloat16(a.x);
    __nv_bfloat16 h1 = __float2bfloat16(a.y);
    __nv_bfloat16 h2 = __float2bfloat16(a.z);
    __nv_bfloat16 h3 = __float2bfloat16(a.w);
    __nv_bfloat16 l0 = __float2bfloat16(a.x - __bfloat162float(h0));
    __nv_bfloat16 l1 = __float2bfloat16(a.y - __bfloat162float(h1));
    __nv_bfloat16 l2 = __float2bfloat16(a.z - __bfloat162float(h2));
    __nv_bfloat16 l3 = __float2bfloat16(a.w - __bfloat162float(h3));
    jobs.hi[job][2 * i + 0] = __nv_bfloat162(h0, h1);
    jobs.hi[job][2 * i + 1] = __nv_bfloat162(h2, h3);
    jobs.lo[job][2 * i + 0] = __nv_bfloat162(l0, l1);
    jobs.lo[job][2 * i + 1] = __nv_bfloat162(l2, l3);
}

// ---------------------------------------------------------------------------
// core 3-term bf16 MMA loop (CTA 128x128x2048), 3-stage pipeline, 1 sync/iter
// ---------------------------------------------------------------------------
#define ROWB   80
#define MATB   10240
#define STAGEB 40960
#define GSTG   3
#define KITERS (KDIM / 32)

struct GemmCore {
    float c[2][8][4];
    uint32_t a_off, b_off;
};

__device__ __forceinline__ void gemm_mainloop(
    uint32_t sb, int tid, int lane, int wm, int wn,
    const __nv_bfloat16* Ah_g, const __nv_bfloat16* Al_g,
    const __nv_bfloat16* Bh_g, const __nv_bfloat16* Bl_g,
    int m0, int n0, GemmCore& g)
{
#pragma unroll
    for (int i = 0; i < 2; ++i)
#pragma unroll
        for (int j = 0; j < 8; ++j)
#pragma unroll
            for (int r = 0; r < 4; ++r) g.c[i][j][r] = 0.f;

    g.a_off = (uint32_t)((wm * 32 + (lane & 15)) * ROWB + (lane >> 4) * 16);
    g.b_off = (uint32_t)((wn * 64 + (lane >> 4) * 8 + (lane & 7)) * ROWB +
                         ((lane >> 3) & 1) * 16);

    const __nv_bfloat16* srcs[4] = { Ah_g, Al_g, Bh_g, Bl_g };
    const int rowbase[4] = { m0, m0, n0, n0 };

    auto load_stage = [&](int s, int k0) {
#pragma unroll
        for (int i = 0; i < 8; ++i) {
            const int mat = i >> 1;
            const int rem = ((i & 1) << 8) + tid;
            const int row = rem >> 2;
            const int seg = rem & 3;
            uint32_t d = sb + s * STAGEB + mat * MATB + row * ROWB + seg * 16;
            const __nv_bfloat16* p =
                srcs[mat] + (size_t)(rowbase[mat] + row) * KDIM + k0 + seg * 8;
            CP_ASYNC16(d, p);
        }
        asm volatile("cp.async.commit_group;");
    };

    load_stage(0, 0);
    load_stage(1, 32);

    for (int it = 0; it < KITERS; ++it) {
        if (it + 1 < KITERS) {
            asm volatile("cp.async.wait_group 1;");
        } else {
            asm volatile("cp.async.wait_group 0;");
        }
        __syncthreads();
        if (it + 2 < KITERS) {
            int s = (it + 2) % GSTG;
            load_stage(s, (it + 2) * 32);
        }

        const uint32_t st = sb + (it % GSTG) * STAGEB;
#pragma unroll
        for (int kk = 0; kk < 2; ++kk) {
            const uint32_t koff = kk * 32;
            uint32_t ah[2][4], al[2][4], bh[4][4], bl[4][4];
#pragma unroll
            for (int i = 0; i < 2; ++i) {
                LDM4(ah[i], st + 0    + g.a_off + i * (16 * ROWB) + koff);
                LDM4(al[i], st + MATB + g.a_off + i * (16 * ROWB) + koff);
            }
#pragma unroll
            for (int j2 = 0; j2 < 4; ++j2) {
                LDM4(bh[j2], st + 2 * MATB + g.b_off + j2 * (16 * ROWB) + koff);
                LDM4(bl[j2], st + 3 * MATB + g.b_off + j2 * (16 * ROWB) + koff);
            }
#pragma unroll
            for (int i = 0; i < 2; ++i)
#pragma unroll
                for (int j = 0; j < 8; ++j) {
                    const uint32_t* bhp = &bh[j >> 1][(j & 1) * 2];
                    const uint32_t* blp = &bl[j >> 1][(j & 1) * 2];
                    MMA_BF16(g.c[i][j], ah[i], bhp[0], bhp[1]);
                    MMA_BF16(g.c[i][j], ah[i], blp[0], blp[1]);
                    MMA_BF16(g.c[i][j], al[i], bhp[0], bhp[1]);
                }
        }
    }
}

// ---------------------------------------------------------------------------
// merged QKV projection: grid (24, 32)
// bx 0..15 -> Q (rope, 1/8), 16..19 -> K (rope), 20..23 -> V
// ---------------------------------------------------------------------------
__global__ __launch_bounds__(256)
void qkv_gemm(const __nv_bfloat16* __restrict__ Xh_g,
              const __nv_bfloat16* __restrict__ Xl_g,
              const __nv_bfloat16* __restrict__ Wqh_g, const __nv_bfloat16* __restrict__ Wql_g,
              const __nv_bfloat16* __restrict__ Wkh_g, const __nv_bfloat16* __restrict__ Wkl_g,
              const __nv_bfloat16* __restrict__ Wvh_g, const __nv_bfloat16* __restrict__ Wvl_g,
              __nv_bfloat16* __restrict__ Qh, __nv_bfloat16* __restrict__ Ql,
              __nv_bfloat16* __restrict__ Kh, __nv_bfloat16* __restrict__ Kl,
              __nv_bfloat16* __restrict__ Vh, __nv_bfloat16* __restrict__ Vl)
{
    extern __shared__ __align__(128) char smem[];
    const uint32_t sb = s2u(smem);

    const int tid  = threadIdx.x;
    const int lane = tid & 31;
    const int w    = tid >> 5;
    const int wm   = w & 3;
    const int wn   = w >> 2;
    const int bx   = blockIdx.x;
    const int m0   = blockIdx.y * 128;

    const __nv_bfloat16 *Bh_g, *Bl_g;
    __nv_bfloat16 *dH, *dL;
    int n0, Hn;
    bool rope;
    float scale;
    if (bx < 16) {
        Bh_g = Wqh_g; Bl_g = Wql_g; dH = Qh; dL = Ql;
        n0 = bx * 128; Hn = HQ; rope = true; scale = 0.125f;
    } else if (bx < 20) {
        Bh_g = Wkh_g; Bl_g = Wkl_g; dH = Kh; dL = Kl;
        n0 = (bx - 16) * 128; Hn = HKV; rope = true; scale = 1.0f;
    } else {
        Bh_g = Wvh_g; Bl_g = Wvl_g; dH = Vh; dL = Vl;
        n0 = (bx - 20) * 128; Hn = HKV; rope = false; scale = 1.0f;
    }

    GemmCore g;
    gemm_mainloop(sb, tid, lane, wm, wn, Xh_g, Xl_g, Bh_g, Bl_g, m0, n0, g);

#pragma unroll
    for (int i = 0; i < 2; ++i) {
        const int r0 = m0 + wm * 32 + i * 16 + (lane >> 2);
#pragma unroll
        for (int j = 0; j < 8; ++j) {
            const int col = n0 + wn * 64 + j * 8 + (lane & 3) * 2;
#pragma unroll
            for (int half = 0; half < 2; ++half) {
                const int row = r0 + half * 8;
                float x1 = g.c[i][j][half * 2];
                float x2 = g.c[i][j][half * 2 + 1];
                const int bidx = row >> 11;
                const int sRow = row & (SS - 1);
                const int hh = col >> 6, d0 = col & 63;
                size_t base = ((((size_t)bidx * Hn + hh) * SS + sRow) << 6) + d0;
                if (rope) {
                    float inv = exp2f(-(float)d0 * (13.287712379549449f / 64.0f));
                    float sn, cs;
                    sincosf((float)sRow * inv, &sn, &cs);
                    float y1 = x1 * cs - x2 * sn;
                    float y2 = x1 * sn + x2 * cs;
                    x1 = y1 * scale;
                    x2 = y2 * scale;
                }
                split2_store(dH, dL, base, x1, x2);
            }
        }
    }
}

// ---------------------------------------------------------------------------
// output projection: fp32 flat result
// ---------------------------------------------------------------------------
__global__ __launch_bounds__(256)
void wo_gemm(const __nv_bfloat16* __restrict__ Ah_g,
             const __nv_bfloat16* __restrict__ Al_g,
             const __nv_bfloat16* __restrict__ Bh_g,
             const __nv_bfloat16* __restrict__ Bl_g,
             float* __restrict__ dst)
{
    extern __shared__ __align__(128) char smem[];
    const uint32_t sb = s2u(smem);

    const int tid  = threadIdx.x;
    const int lane = tid & 31;
    const int w    = tid >> 5;
    const int wm   = w & 3;
    const int wn   = w >> 2;
    const int m0   = blockIdx.y * 128;
    const int n0   = blockIdx.x * 128;

    GemmCore g;
    gemm_mainloop(sb, tid, lane, wm, wn, Ah_g, Al_g, Bh_g, Bl_g, m0, n0, g);

#pragma unroll
    for (int i = 0; i < 2; ++i) {
        const int r0 = m0 + wm * 32 + i * 16 + (lane >> 2);
#pragma unroll
        for (int j = 0; j < 8; ++j) {
            const int col = n0 + wn * 64 + j * 8 + (lane & 3) * 2;
#pragma unroll
            for (int half = 0; half < 2; ++half) {
                const int row = r0 + half * 8;
                *reinterpret_cast<float2*>(dst + (size_t)row * DD + col) =
                    make_float2(g.c[i][j][half * 2], g.c[i][j][half * 2 + 1]);
            }
        }
    }
}

// ---------------------------------------------------------------------------
// MMA flash attention (causal, GQA): BM=128, BN=128, Dh=64, 8 warps
// 3-stage KV ring (Q staged through slot 0), 1 sync per iteration
// ---------------------------------------------------------------------------
#define FROW   144
#define KTILE  18432               // 128 rows * 144 B
#define KVSTG  73728               // 4 * KTILE (Kh,Kl,Vh,Vl)
#define FSMEM  (3 * KVSTG)         // 221184

__global__ __launch_bounds__(256)
void flash_mma(const __nv_bfloat16* __restrict__ Qh_g,
               const __nv_bfloat16* __restrict__ Ql_g,
               const __nv_bfloat16* __restrict__ Kh_g,
               const __nv_bfloat16* __restrict__ Kl_g,
               const __nv_bfloat16* __restrict__ Vh_g,
               const __nv_bfloat16* __restrict__ Vl_g,
               __nv_bfloat16* __restrict__ OhP,
               __nv_bfloat16* __restrict__ OlP)
{
    extern __shared__ __align__(128) char fsm[];
    const uint32_t sb = s2u(fsm);

    const int tid  = threadIdx.x;
    const int lane = tid & 31;
    const int w    = tid >> 5;
    const int qi   = gridDim.x - 1 - blockIdx.x;   // longest CTAs first
    const int qb   = qi * 128;
    const int h    = blockIdx.y;
    const int b    = blockIdx.z;
    const int kh   = h >> 2;

    const size_t qoff  = (((size_t)b * HQ + h) * SS + qb) * 64;
    const size_t kvrow = ((size_t)b * HKV + kh) * SS;

    const uint32_t a_off =
        (uint32_t)((w * 16 + (lane & 15)) * FROW + (lane >> 4) * 16);
    const uint32_t kb_off =
        (uint32_t)(((lane >> 4) * 8 + (lane & 7)) * FROW + ((lane >> 3) & 1) * 16);
    const uint32_t v_off =
        (uint32_t)((lane & 15) * FROW + (lane >> 4) * 16);

    // ---- prologue: Q through ring slot 0 into registers ----
#pragma unroll
    for (int i = 0; i < 8; ++i) {
        int idx = tid + 256 * i;
        int mat = idx >> 10;
        int rem = idx & 1023;
        int row = rem >> 3;
        int seg = rem & 7;
        uint32_t d = sb + mat * KTILE + row * FROW + seg * 16;
        const __nv_bfloat16* p = (mat ? Ql_g : Qh_g) + qoff + row * 64 + seg * 8;
        CP_ASYNC16(d, p);
    }
    asm volatile("cp.async.commit_group;");
    asm volatile("cp.async.wait_group 0;");
    __syncthreads();

    uint32_t qh[4][4], ql[4][4];
#pragma unroll
    for (int kc = 0; kc < 4; ++kc) {
        LDM4(qh[kc], sb + a_off + kc * 32);
        LDM4(ql[kc], sb + KTILE + a_off + kc * 32);
    }
    __syncthreads();   // all warps own Q frags before slot 0 is recycled

    auto load_kv = [&](int s, int j0) {
        const __nv_bfloat16* srcs[4] = { Kh_g, Kl_g, Vh_g, Vl_g };
        const size_t off = (kvrow + j0) * 64;
#pragma unroll
        for (int i = 0; i < 16; ++i) {
            int idx = tid + 256 * i;
            int mat = idx >> 10;
            int rem = idx & 1023;
            int row = rem >> 3;
            int seg = rem & 7;
            uint32_t d = sb + s * KVSTG + mat * KTILE + row * FROW + seg * 16;
            CP_ASYNC16(d, srcs[mat] + off + row * 64 + seg * 8);
        }
        asm volatile("cp.async.commit_group;");
    };

    const int nb = qb / 128 + 1;
    load_kv(0, 0);
    if (nb > 1) load_kv(1, 128);

    float o[8][4];
#pragma unroll
    for (int j = 0; j < 8; ++j)
#pragma unroll
        for (int r = 0; r < 4; ++r) o[j][r] = 0.f;
    float mi[2] = { -1e30f, -1e30f };
    float li[2] = { 0.f, 0.f };

    const int row0 = qb + w * 16 + (lane >> 2);

    for (int it = 0; it < nb; ++it) {
        if (it + 1 < nb) {
            asm volatile("cp.async.wait_group 1;");
        } else {
            asm volatile("cp.async.wait_group 0;");
        }
        __syncthreads();
        if (it + 2 < nb) load_kv((it + 2) % 3, (it + 2) * 128);

        const uint32_t kvb = sb + (it % 3) * KVSTG;
        const int j0 = it * 128;

        // ---- S = Q.K^T (3-term) ----
        float s[16][4];
#pragma unroll
        for (int j = 0; j < 16; ++j)
#pragma unroll
            for (int r = 0; r < 4; ++r) s[j][r] = 0.f;

#pragma unroll
        for (int jh = 0; jh < 2; ++jh) {
#pragma unroll
            for (int kc = 0; kc < 4; ++kc) {
                uint32_t bh[4][4], bl[4][4];
#pragma unroll
                for (int j2 = 0; j2 < 4; ++j2) {
                    uint32_t ba = kvb + (jh * 4 + j2) * (16 * FROW) + kb_off + kc * 32;
                    LDM4(bh[j2], ba);
                    LDM4(bl[j2], ba + KTILE);
                }
#pragma unroll
                for (int j = 0; j < 8; ++j) {
                    float* cs = s[jh * 8 + j];
                    const uint32_t* bhp = &bh[j >> 1][(j & 1) * 2];
                    const uint32_t* blp = &bl[j >> 1][(j & 1) * 2];
                    MMA_BF16(cs, qh[kc], bhp[0], bhp[1]);
                    MMA_BF16(cs, qh[kc], blp[0], blp[1]);
                    MMA_BF16(cs, ql[kc], bhp[0], bhp[1]);
                }
            }
        }

        // ---- causal mask (diagonal block = last iteration) ----
        if (j0 == qb) {
#pragma unroll
            for (int j = 0; j < 16; ++j)
#pragma unroll
                for (int r = 0; r < 4; ++r) {
                    int col = j0 + j * 8 + (lane & 3) * 2 + (r & 1);
                    int row = row0 + (r >> 1) * 8;
                    if (col > row) s[j][r] = -1e30f;
                }
        }

        // ---- online softmax ----
#pragma unroll
        for (int h2 = 0; h2 < 2; ++h2) {
            float mt = -1e30f;
#pragma unroll
            for (int j = 0; j < 16; ++j) {
                mt = fmaxf(mt, s[j][h2 * 2]);
                mt = fmaxf(mt, s[j][h2 * 2 + 1]);
            }
            mt = fmaxf(mt, __shfl_xor_sync(0xffffffffu, mt, 1));
            mt = fmaxf(mt, __shfl_xor_sync(0xffffffffu, mt, 2));
            float mnew  = fmaxf(mi[h2], mt);
            float alpha = __expf(mi[h2] - mnew);
            mi[h2] = mnew;
            float sum = 0.f;
#pragma unroll
            for (int j = 0; j < 16; ++j) {
                float p0 = __expf(s[j][h2 * 2]     - mnew);
                float p1 = __expf(s[j][h2 * 2 + 1] - mnew);
                s[j][h2 * 2]     = p0;
                s[j][h2 * 2 + 1] = p1;
                sum += p0 + p1;
            }
#pragma unroll
            for (int j = 0; j < 8; ++j) {
                o[j][h2 * 2]     *= alpha;
                o[j][h2 * 2 + 1] *= alpha;
            }
            sum += __shfl_xor_sync(0xffffffffu, sum, 1);
            sum += __shfl_xor_sync(0xffffffffu, sum, 2);
            li[h2] = li[h2] * alpha + sum;
        }

        // ---- P fragments (hi/lo) ----
        uint32_t ph[8][4], pl[8][4];
#pragma unroll
        for (int kc = 0; kc < 8; ++kc) {
            const int jt = 2 * kc;
            float a0 = s[jt][0],     a1 = s[jt][1];
            float a2 = s[jt][2],     a3 = s[jt][3];
            float b0 = s[jt + 1][0], b1 = s[jt + 1][1];
            float b2 = s[jt + 1][2], b3 = s[jt + 1][3];
            ph[kc][0] = pack_bf2(a0, a1);
            ph[kc][1] = pack_bf2(a2, a3);
            ph[kc][2] = pack_bf2(b0, b1);
            ph[kc][3] = pack_bf2(b2, b3);
            __nv_bfloat162 t;
            t = *reinterpret_cast<__nv_bfloat162*>(&ph[kc][0]);
            pl[kc][0] = pack_bf2(a0 - __bfloat162float(t.x), a1 - __bfloat162float(t.y));
            t = *reinterpret_cast<__nv_bfloat162*>(&ph[kc][1]);
            pl[kc][1] = pack_bf2(a2 - __bfloat162float(t.x), a3 - __bfloat162float(t.y));
            t = *reinterpret_cast<__nv_bfloat162*>(&ph[kc][2]);
            pl[kc][2] = pack_bf2(b0 - __bfloat162float(t.x), b1 - __bfloat162float(t.y));
            t = *reinterpret_cast<__nv_bfloat162*>(&ph[kc][3]);
            pl[kc][3] = pack_bf2(b2 - __bfloat162float(t.x), b3 - __bfloat162float(t.y));
        }

        // ---- O += P.V (3-term) ----
        const uint32_t vbase = kvb + 2 * KTILE;
#pragma unroll
        for (int kc = 0; kc < 8; ++kc) {
#pragma unroll
            for (int np = 0; np < 4; ++np) {
                uint32_t vh4[4], vl4[4];
                uint32_t va = vbase + kc * (16 * FROW) + v_off + np * 32;
                LDM4T(vh4, va);
                LDM4T(vl4, va + KTILE);
                MMA_BF16(o[2 * np],     ph[kc], vh4[0], vh4[1]);
                MMA_BF16(o[2 * np],     ph[kc], vl4[0], vl4[1]);
                MMA_BF16(o[2 * np],     pl[kc], vh4[0], vh4[1]);
                MMA_BF16(o[2 * np + 1], ph[kc], vh4[2], vh4[3]);
                MMA_BF16(o[2 * np + 1], ph[kc], vl4[2], vl4[3]);
                MMA_BF16(o[2 * np + 1], pl[kc], vh4[2], vh4[3]);
            }
        }
    }

    // ---- finalize: bf16 hi/lo attention output (flat [b][s][h*64+d]) ----
    float inv0 = 1.0f / li[0];
    float inv1 = 1.0f / li[1];
#pragma unroll
    for (int j = 0; j < 8; ++j) {
        const int col = j * 8 + (lane & 3) * 2;
        size_t base0 = ((size_t)(b * SS + row0)) * DD + h * 64 + col;
        size_t base1 = ((size_t)(b * SS + row0 + 8)) * DD + h * 64 + col;
        split2_store(OhP, OlP, base0, o[j][0] * inv0, o[j][1] * inv0);
        split2_store(OhP, OlP, base1, o[j][2] * inv1, o[j][3] * inv1);
    }
}

// ---------------------------------------------------------------------------
// Host
// ---------------------------------------------------------------------------
extern "C" void kernel_launch(void* const* d_in, const int* in_sizes, int n_in,
                              void* d_out, int out_size)
{
    const float* x  = (const float*)d_in[0];
    const float* Wq = (const float*)d_in[1];
    const float* Wk = (const float*)d_in[2];
    const float* Wv = (const float*)d_in[3];
    const float* Wo = (const float*)d_in[4];
    float* out = (float*)d_out;

    __nv_bfloat16 *Xh, *Xl, *Wqh, *Wql, *Wkh, *Wkl, *Wvh, *Wvl, *Woh, *Wol, *Oh, *Ol;
    __nv_bfloat16 *Qbh, *Qbl, *Kbh, *Kbl, *Vbh, *Vbl;
    cudaGetSymbolAddress((void**)&Xh, g_Xh);
    cudaGetSymbolAddress((void**)&Xl, g_Xl);
    cudaGetSymbolAddress((void**)&Wqh, g_Wqh);
    cudaGetSymbolAddress((void**)&Wql, g_Wql);
    cudaGetSymbolAddress((void**)&Wkh, g_Wkh);
    cudaGetSymbolAddress((void**)&Wkl, g_Wkl);
    cudaGetSymbolAddress((void**)&Wvh, g_Wvh);
    cudaGetSymbolAddress((void**)&Wvl, g_Wvl);
    cudaGetSymbolAddress((void**)&Woh, g_Woh);
    cudaGetSymbolAddress((void**)&Wol, g_Wol);
    cudaGetSymbolAddress((void**)&Oh, g_Oh);
    cudaGetSymbolAddress((void**)&Ol, g_Ol);
    cudaGetSymbolAddress((void**)&Qbh, g_Qbh);
    cudaGetSymbolAddress((void**)&Qbl, g_Qbl);
    cudaGetSymbolAddress((void**)&Kbh, g_Kbh);
    cudaGetSymbolAddress((void**)&Kbl, g_Kbl);
    cudaGetSymbolAddress((void**)&Vbh, g_Vbh);
    cudaGetSymbolAddress((void**)&Vbl, g_Vbl);

    const int SMEM_DYN = GSTG * STAGEB;   // 122880
    cudaFuncSetAttribute(qkv_gemm, cudaFuncAttributeMaxDynamicSharedMemorySize, SMEM_DYN);
    cudaFuncSetAttribute(wo_gemm,  cudaFuncAttributeMaxDynamicSharedMemorySize, SMEM_DYN);
    cudaFuncSetAttribute(flash_mma, cudaFuncAttributeMaxDynamicSharedMemorySize, FSMEM);

    // single merged split launch (x, Wq, Wk, Wv, Wo)
    {
        SplitJobs jobs;
        jobs.in[0] = (const float4*)x;  jobs.hi[0] = (__nv_bfloat162*)Xh;  jobs.lo[0] = (__nv_bfloat162*)Xl;
        jobs.in[1] = (const float4*)Wq; jobs.hi[1] = (__nv_bfloat162*)Wqh; jobs.lo[1] = (__nv_bfloat162*)Wql;
        jobs.in[2] = (const float4*)Wk; jobs.hi[2] = (__nv_bfloat162*)Wkh; jobs.lo[2] = (__nv_bfloat162*)Wkl;
        jobs.in[3] = (const float4*)Wv; jobs.hi[3] = (__nv_bfloat162*)Wvh; jobs.lo[3] = (__nv_bfloat162*)Wvl;
        jobs.in[4] = (const float4*)Wo; jobs.hi[4] = (__nv_bfloat162*)Woh; jobs.lo[4] = (__nv_bfloat162*)Wol;
        int n4s[5] = { BB * SS * DD / 4, HQ * DH * DD / 4, HKV * DH * DD / 4,
                       HKV * DH * DD / 4, DD * DD / 4 };
        int cum = 0;
        for (int k = 0; k < 5; ++k) { cum += n4s[k] / 256; jobs.blk_end[k] = cum; }
        split_all<<<cum, 256>>>(jobs);
    }

    // merged QKV projection (fused RoPE/scale/split epilogue)
    qkv_gemm<<<dim3(24, 32), 256, SMEM_DYN>>>(Xh, Xl,
        Wqh, Wql, Wkh, Wkl, Wvh, Wvl,
        Qbh, Qbl, Kbh, Kbl, Vbh, Vbl);

    // MMA flash attention (causal), outputs bf16 hi/lo
    flash_mma<<<dim3(SS / 128, HQ, BB), 256, FSMEM>>>(Qbh, Qbl, Kbh, Kbl, Vbh, Vbl, Oh, Ol);

    // output projection -> fp32 result
    wo_gemm<<<dim3(16, 32), 256, SMEM_DYN>>>(Oh, Ol, Woh, Wol, out);
}

// round 8
// speedup vs baseline: 1.0951x; 1.0951x over previous
#include <cuda_runtime.h>
#include <cuda_bf16.h>
#include <math.h>
#include <stdint.h>

#define BB   2
#define SS   2048
#define DD   2048
#define HQ   32
#define HKV  8
#define DH   64
#define KDIM 2048

// ---------------------------------------------------------------------------
// Scratch (allocation-free rule: __device__ globals)
// ---------------------------------------------------------------------------
__device__ __nv_bfloat16 g_Xh[(size_t)BB * SS * DD];
__device__ __nv_bfloat16 g_Xl[(size_t)BB * SS * DD];
__device__ __nv_bfloat16 g_Wqh[(size_t)HQ * DH * DD];
__device__ __nv_bfloat16 g_Wql[(size_t)HQ * DH * DD];
__device__ __nv_bfloat16 g_Wkh[(size_t)HKV * DH * DD];
__device__ __nv_bfloat16 g_Wkl[(size_t)HKV * DH * DD];
__device__ __nv_bfloat16 g_Wvh[(size_t)HKV * DH * DD];
__device__ __nv_bfloat16 g_Wvl[(size_t)HKV * DH * DD];
__device__ __nv_bfloat16 g_Woh[(size_t)DD * DD];
__device__ __nv_bfloat16 g_Wol[(size_t)DD * DD];
__device__ __nv_bfloat16 g_Oh[(size_t)BB * SS * DD];
__device__ __nv_bfloat16 g_Ol[(size_t)BB * SS * DD];

__device__ __nv_bfloat16 g_Qbh[(size_t)BB * HQ  * SS * DH];
__device__ __nv_bfloat16 g_Qbl[(size_t)BB * HQ  * SS * DH];
__device__ __nv_bfloat16 g_Kbh[(size_t)BB * HKV * SS * DH];
__device__ __nv_bfloat16 g_Kbl[(size_t)BB * HKV * SS * DH];
__device__ __nv_bfloat16 g_Vbh[(size_t)BB * HKV * SS * DH];
__device__ __nv_bfloat16 g_Vbl[(size_t)BB * HKV * SS * DH];

// ---------------------------------------------------------------------------
// helpers
// ---------------------------------------------------------------------------
__device__ __forceinline__ uint32_t s2u(const void* p) {
    uint32_t r;
    asm("{ .reg .u64 t; cvta.to.shared.u64 t, %1; cvt.u32.u64 %0, t; }"
        : "=r"(r) : "l"(p));
    return r;
}

#define LDM4(r, addr)                                                         \
    asm volatile("ldmatrix.sync.aligned.m8n8.x4.shared.b16 {%0,%1,%2,%3}, [%4];" \
        : "=r"((r)[0]), "=r"((r)[1]), "=r"((r)[2]), "=r"((r)[3]) : "r"(addr))

#define LDM4T(r, addr)                                                        \
    asm volatile("ldmatrix.sync.aligned.m8n8.x4.trans.shared.b16 {%0,%1,%2,%3}, [%4];" \
        : "=r"((r)[0]), "=r"((r)[1]), "=r"((r)[2]), "=r"((r)[3]) : "r"(addr))

#define MMA_BF16(c, a, b0, b1)                                                \
    asm volatile("mma.sync.aligned.m16n8k16.row.col.f32.bf16.bf16.f32 "       \
        "{%0,%1,%2,%3}, {%4,%5,%6,%7}, {%8,%9}, {%0,%1,%2,%3};"               \
        : "+f"((c)[0]), "+f"((c)[1]), "+f"((c)[2]), "+f"((c)[3])              \
        : "r"((a)[0]), "r"((a)[1]), "r"((a)[2]), "r"((a)[3]), "r"(b0), "r"(b1))

#define CP_ASYNC16(dst, src)                                                  \
    asm volatile("cp.async.cg.shared.global [%0], [%1], 16;" :: "r"(dst), "l"(src))

__device__ __forceinline__ uint32_t pack_bf2(float a, float b) {
    __nv_bfloat162 t = __floats2bfloat162_rn(a, b);
    return *reinterpret_cast<uint32_t*>(&t);
}

__device__ __forceinline__ void split2_store(__nv_bfloat16* H, __nv_bfloat16* L,
                                             size_t base, float x1, float x2)
{
    __nv_bfloat16 h1 = __float2bfloat16(x1);
    __nv_bfloat16 h2 = __float2bfloat16(x2);
    __nv_bfloat16 l1 = __float2bfloat16(x1 - __bfloat162float(h1));
    __nv_bfloat16 l2 = __float2bfloat16(x2 - __bfloat162float(h2));
    *reinterpret_cast<__nv_bfloat162*>(H + base) = __nv_bfloat162(h1, h2);
    *reinterpret_cast<__nv_bfloat162*>(L + base) = __nv_bfloat162(l1, l2);
}

// ---------------------------------------------------------------------------
// merged input splits
// ---------------------------------------------------------------------------
struct SplitJobs {
    const float4* in[5];
    __nv_bfloat162* hi[5];
    __nv_bfloat162* lo[5];
    int blk_end[5];
};

__global__ void split_all(SplitJobs jobs)
{
    int bx = blockIdx.x;
    int job = 0;
#pragma unroll
    for (int k = 0; k < 5; ++k)
        if (bx >= jobs.blk_end[k]) job = k + 1;
    int blk0 = (job == 0) ? 0 : jobs.blk_end[job - 1];
    int i = (bx - blk0) * blockDim.x + threadIdx.x;

    float4 a = jobs.in[job][i];
    __nv_bfloat16 h0 = __float2bfloat16(a.x);
    __nv_bfloat16 h1 = __float2bfloat16(a.y);
    __nv_bfloat16 h2 = __float2bfloat16(a.z);
    __nv_bfloat16 h3 = __float2bfloat16(a.w);
    __nv_bfloat16 l0 = __float2bfloat16(a.x - __bfloat162float(h0));
    __nv_bfloat16 l1 = __float2bfloat16(a.y - __bfloat162float(h1));
    __nv_bfloat16 l2 = __float2bfloat16(a.z - __bfloat162float(h2));
    __nv_bfloat16 l3 = __float2bfloat16(a.w - __bfloat162float(h3));
    jobs.hi[job][2 * i + 0] = __nv_bfloat162(h0, h1);
    jobs.hi[job][2 * i + 1] = __nv_bfloat162(h2, h3);
    jobs.lo[job][2 * i + 0] = __nv_bfloat162(l0, l1);
    jobs.lo[job][2 * i + 1] = __nv_bfloat162(l2, l3);
}

// ---------------------------------------------------------------------------
// core 3-term bf16 MMA loop (CTA 128x128x2048), 2-stage, 2 CTAs/SM (80 KB)
// ---------------------------------------------------------------------------
#define ROWB   80
#define MATB   10240
#define STAGEB 40960
#define KITERS (KDIM / 32)

struct GemmCore {
    float c[2][8][4];
    uint32_t a_off, b_off;
};

__device__ __forceinline__ void gemm_mainloop(
    uint32_t sb, int tid, int lane, int wm, int wn,
    const __nv_bfloat16* Ah_g, const __nv_bfloat16* Al_g,
    const __nv_bfloat16* Bh_g, const __nv_bfloat16* Bl_g,
    int m0, int n0, GemmCore& g)
{
#pragma unroll
    for (int i = 0; i < 2; ++i)
#pragma unroll
        for (int j = 0; j < 8; ++j)
#pragma unroll
            for (int r = 0; r < 4; ++r) g.c[i][j][r] = 0.f;

    g.a_off = (uint32_t)((wm * 32 + (lane & 15)) * ROWB + (lane >> 4) * 16);
    g.b_off = (uint32_t)((wn * 64 + (lane >> 4) * 8 + (lane & 7)) * ROWB +
                         ((lane >> 3) & 1) * 16);

    const __nv_bfloat16* srcs[4] = { Ah_g, Al_g, Bh_g, Bl_g };
    const int rowbase[4] = { m0, m0, n0, n0 };

    auto load_stage = [&](int s, int k0) {
#pragma unroll
        for (int i = 0; i < 8; ++i) {
            const int mat = i >> 1;
            const int rem = ((i & 1) << 8) + tid;
            const int row = rem >> 2;
            const int seg = rem & 3;
            uint32_t d = sb + s * STAGEB + mat * MATB + row * ROWB + seg * 16;
            const __nv_bfloat16* p =
                srcs[mat] + (size_t)(rowbase[mat] + row) * KDIM + k0 + seg * 8;
            CP_ASYNC16(d, p);
        }
        asm volatile("cp.async.commit_group;");
    };

    load_stage(0, 0);

    for (int it = 0; it < KITERS; ++it) {
        if (it + 1 < KITERS) {
            load_stage((it + 1) & 1, (it + 1) * 32);
            asm volatile("cp.async.wait_group 1;");
        } else {
            asm volatile("cp.async.wait_group 0;");
        }
        __syncthreads();

        const uint32_t st = sb + (it & 1) * STAGEB;
#pragma unroll
        for (int kk = 0; kk < 2; ++kk) {
            const uint32_t koff = kk * 32;
            uint32_t ah[2][4], al[2][4], bh[4][4], bl[4][4];
#pragma unroll
            for (int i = 0; i < 2; ++i) {
                LDM4(ah[i], st + 0    + g.a_off + i * (16 * ROWB) + koff);
                LDM4(al[i], st + MATB + g.a_off + i * (16 * ROWB) + koff);
            }
#pragma unroll
            for (int j2 = 0; j2 < 4; ++j2) {
                LDM4(bh[j2], st + 2 * MATB + g.b_off + j2 * (16 * ROWB) + koff);
                LDM4(bl[j2], st + 3 * MATB + g.b_off + j2 * (16 * ROWB) + koff);
            }
#pragma unroll
            for (int i = 0; i < 2; ++i)
#pragma unroll
                for (int j = 0; j < 8; ++j) {
                    const uint32_t* bhp = &bh[j >> 1][(j & 1) * 2];
                    const uint32_t* blp = &bl[j >> 1][(j & 1) * 2];
                    MMA_BF16(g.c[i][j], ah[i], bhp[0], bhp[1]);
                    MMA_BF16(g.c[i][j], ah[i], blp[0], blp[1]);
                    MMA_BF16(g.c[i][j], al[i], bhp[0], bhp[1]);
                }
        }
        __syncthreads();
    }
}

// ---------------------------------------------------------------------------
// merged QKV projection: grid (24, 32)
// ---------------------------------------------------------------------------
__global__ __launch_bounds__(256)
void qkv_gemm(const __nv_bfloat16* __restrict__ Xh_g,
              const __nv_bfloat16* __restrict__ Xl_g,
              const __nv_bfloat16* __restrict__ Wqh_g, const __nv_bfloat16* __restrict__ Wql_g,
              const __nv_bfloat16* __restrict__ Wkh_g, const __nv_bfloat16* __restrict__ Wkl_g,
              const __nv_bfloat16* __restrict__ Wvh_g, const __nv_bfloat16* __restrict__ Wvl_g,
              __nv_bfloat16* __restrict__ Qh, __nv_bfloat16* __restrict__ Ql,
              __nv_bfloat16* __restrict__ Kh, __nv_bfloat16* __restrict__ Kl,
              __nv_bfloat16* __restrict__ Vh, __nv_bfloat16* __restrict__ Vl)
{
    extern __shared__ __align__(128) char smem[];
    const uint32_t sb = s2u(smem);

    const int tid  = threadIdx.x;
    const int lane = tid & 31;
    const int w    = tid >> 5;
    const int wm   = w & 3;
    const int wn   = w >> 2;
    const int bx   = blockIdx.x;
    const int m0   = blockIdx.y * 128;

    const __nv_bfloat16 *Bh_g, *Bl_g;
    __nv_bfloat16 *dH, *dL;
    int n0, Hn;
    bool rope;
    float scale;
    if (bx < 16) {
        Bh_g = Wqh_g; Bl_g = Wql_g; dH = Qh; dL = Ql;
        n0 = bx * 128; Hn = HQ; rope = true; scale = 0.125f;
    } else if (bx < 20) {
        Bh_g = Wkh_g; Bl_g = Wkl_g; dH = Kh; dL = Kl;
        n0 = (bx - 16) * 128; Hn = HKV; rope = true; scale = 1.0f;
    } else {
        Bh_g = Wvh_g; Bl_g = Wvl_g; dH = Vh; dL = Vl;
        n0 = (bx - 20) * 128; Hn = HKV; rope = false; scale = 1.0f;
    }

    GemmCore g;
    gemm_mainloop(sb, tid, lane, wm, wn, Xh_g, Xl_g, Bh_g, Bl_g, m0, n0, g);

#pragma unroll
    for (int i = 0; i < 2; ++i) {
        const int r0 = m0 + wm * 32 + i * 16 + (lane >> 2);
#pragma unroll
        for (int j = 0; j < 8; ++j) {
            const int col = n0 + wn * 64 + j * 8 + (lane & 3) * 2;
#pragma unroll
            for (int half = 0; half < 2; ++half) {
                const int row = r0 + half * 8;
                float x1 = g.c[i][j][half * 2];
                float x2 = g.c[i][j][half * 2 + 1];
                const int bidx = row >> 11;
                const int sRow = row & (SS - 1);
                const int hh = col >> 6, d0 = col & 63;
                size_t base = ((((size_t)bidx * Hn + hh) * SS + sRow) << 6) + d0;
                if (rope) {
                    float inv = exp2f(-(float)d0 * (13.287712379549449f / 64.0f));
                    float sn, cs;
                    sincosf((float)sRow * inv, &sn, &cs);
                    float y1 = x1 * cs - x2 * sn;
                    float y2 = x1 * sn + x2 * cs;
                    x1 = y1 * scale;
                    x2 = y2 * scale;
                }
                split2_store(dH, dL, base, x1, x2);
            }
        }
    }
}

// ---------------------------------------------------------------------------
// output projection: fp32 flat result
// ---------------------------------------------------------------------------
__global__ __launch_bounds__(256)
void wo_gemm(const __nv_bfloat16* __restrict__ Ah_g,
             const __nv_bfloat16* __restrict__ Al_g,
             const __nv_bfloat16* __restrict__ Bh_g,
             const __nv_bfloat16* __restrict__ Bl_g,
             float* __restrict__ dst)
{
    extern __shared__ __align__(128) char smem[];
    const uint32_t sb = s2u(smem);

    const int tid  = threadIdx.x;
    const int lane = tid & 31;
    const int w    = tid >> 5;
    const int wm   = w & 3;
    const int wn   = w >> 2;
    const int m0   = blockIdx.y * 128;
    const int n0   = blockIdx.x * 128;

    GemmCore g;
    gemm_mainloop(sb, tid, lane, wm, wn, Ah_g, Al_g, Bh_g, Bl_g, m0, n0, g);

#pragma unroll
    for (int i = 0; i < 2; ++i) {
        const int r0 = m0 + wm * 32 + i * 16 + (lane >> 2);
#pragma unroll
        for (int j = 0; j < 8; ++j) {
            const int col = n0 + wn * 64 + j * 8 + (lane & 3) * 2;
#pragma unroll
            for (int half = 0; half < 2; ++half) {
                const int row = r0 + half * 8;
                *reinterpret_cast<float2*>(dst + (size_t)row * DD + col) =
                    make_float2(g.c[i][j][half * 2], g.c[i][j][half * 2 + 1]);
            }
        }
    }
}

// ---------------------------------------------------------------------------
// MMA flash attention (causal, GQA): BM=128 (8 warps x 16 rows), BN=64, Dh=64
// 3-stage KV ring of 36KB slots; Q staged through slot 0 into registers.
// smem 110592 -> 2 CTAs/SM; __launch_bounds__(256,2) caps regs at 128.
// ---------------------------------------------------------------------------
#define FROW   144
#define QTILE  18432               // 128 rows * 144 B
#define FTILE  9216                // 64 rows * 144 B (per matrix)
#define KVSTG  36864               // 4 * FTILE (Kh,Kl,Vh,Vl)
#define FSMEM  (3 * KVSTG)         // 110592

__global__ __launch_bounds__(256, 2)
void flash_mma(const __nv_bfloat16* __restrict__ Qh_g,
               const __nv_bfloat16* __restrict__ Ql_g,
               const __nv_bfloat16* __restrict__ Kh_g,
               const __nv_bfloat16* __restrict__ Kl_g,
               const __nv_bfloat16* __restrict__ Vh_g,
               const __nv_bfloat16* __restrict__ Vl_g,
               __nv_bfloat16* __restrict__ OhP,
               __nv_bfloat16* __restrict__ OlP)
{
    extern __shared__ __align__(128) char fsm[];
    const uint32_t sb = s2u(fsm);

    const int tid  = threadIdx.x;
    const int lane = tid & 31;
    const int w    = tid >> 5;
    const int qi   = gridDim.x - 1 - blockIdx.x;   // longest CTAs first
    const int qb   = qi * 128;
    const int h    = blockIdx.y;
    const int b    = blockIdx.z;
    const int kh   = h >> 2;

    const size_t qoff  = (((size_t)b * HQ + h) * SS + qb) * 64;
    const size_t kvrow = ((size_t)b * HKV + kh) * SS;

    const uint32_t a_off =
        (uint32_t)((w * 16 + (lane & 15)) * FROW + (lane >> 4) * 16);
    const uint32_t kb_off =
        (uint32_t)(((lane >> 4) * 8 + (lane & 7)) * FROW + ((lane >> 3) & 1) * 16);
    const uint32_t v_off =
        (uint32_t)((lane & 15) * FROW + (lane >> 4) * 16);

    // ---- prologue: Q (hi/lo = 2*QTILE = one ring slot) through slot 0 ----
#pragma unroll
    for (int i = 0; i < 8; ++i) {
        int idx = tid + 256 * i;
        int mat = idx >> 10;
        int rem = idx & 1023;
        int row = rem >> 3;
        int seg = rem & 7;
        uint32_t d = sb + mat * QTILE + row * FROW + seg * 16;
        const __nv_bfloat16* p = (mat ? Ql_g : Qh_g) + qoff + row * 64 + seg * 8;
        CP_ASYNC16(d, p);
    }
    asm volatile("cp.async.commit_group;");
    asm volatile("cp.async.wait_group 0;");
    __syncthreads();

    uint32_t qh[4][4], ql[4][4];
#pragma unroll
    for (int kc = 0; kc < 4; ++kc) {
        LDM4(qh[kc], sb + a_off + kc * 32);
        LDM4(ql[kc], sb + QTILE + a_off + kc * 32);
    }
    __syncthreads();   // all warps own Q frags before slot 0 is recycled

    auto load_kv = [&](int s, int j0) {
        const __nv_bfloat16* srcs[4] = { Kh_g, Kl_g, Vh_g, Vl_g };
        const size_t off = (kvrow + j0) * 64;
#pragma unroll
        for (int i = 0; i < 8; ++i) {
            int idx = tid + 256 * i;
            int mat = idx >> 9;
            int rem = idx & 511;
            int row = rem >> 3;
            int seg = rem & 7;
            uint32_t d = sb + s * KVSTG + mat * FTILE + row * FROW + seg * 16;
            CP_ASYNC16(d, srcs[mat] + off + row * 64 + seg * 8);
        }
        asm volatile("cp.async.commit_group;");
    };

    const int nb = qb / 64 + 2;
    load_kv(0, 0);
    if (nb > 1) load_kv(1, 64);

    float o[8][4];
#pragma unroll
    for (int j = 0; j < 8; ++j)
#pragma unroll
        for (int r = 0; r < 4; ++r) o[j][r] = 0.f;
    float mi[2] = { -1e30f, -1e30f };
    float li[2] = { 0.f, 0.f };

    const int row0 = qb + w * 16 + (lane >> 2);

    for (int it = 0; it < nb; ++it) {
        if (it + 1 < nb) {
            asm volatile("cp.async.wait_group 1;");
        } else {
            asm volatile("cp.async.wait_group 0;");
        }
        __syncthreads();
        if (it + 2 < nb) load_kv((it + 2) % 3, (it + 2) * 64);

        const uint32_t kvb = sb + (it % 3) * KVSTG;
        const int j0 = it * 64;

        // ---- S = Q.K^T (3-term) ----
        float s[8][4];
#pragma unroll
        for (int j = 0; j < 8; ++j)
#pragma unroll
            for (int r = 0; r < 4; ++r) s[j][r] = 0.f;

#pragma unroll
        for (int kc = 0; kc < 4; ++kc) {
            uint32_t bh[4][4], bl[4][4];
#pragma unroll
            for (int j2 = 0; j2 < 4; ++j2) {
                uint32_t ba = kvb + j2 * (16 * FROW) + kb_off + kc * 32;
                LDM4(bh[j2], ba);
                LDM4(bl[j2], ba + FTILE);
            }
#pragma unroll
            for (int j = 0; j < 8; ++j) {
                const uint32_t* bhp = &bh[j >> 1][(j & 1) * 2];
                const uint32_t* blp = &bl[j >> 1][(j & 1) * 2];
                MMA_BF16(s[j], qh[kc], bhp[0], bhp[1]);
                MMA_BF16(s[j], qh[kc], blp[0], blp[1]);
                MMA_BF16(s[j], ql[kc], bhp[0], bhp[1]);
            }
        }

        // ---- causal mask (only warps whose rows the block can cross) ----
        if (j0 + 63 > qb + w * 16) {
#pragma unroll
            for (int j = 0; j < 8; ++j)
#pragma unroll
                for (int r = 0; r < 4; ++r) {
                    int col = j0 + j * 8 + (lane & 3) * 2 + (r & 1);
                    int row = row0 + (r >> 1) * 8;
                    if (col > row) s[j][r] = -1e30f;
                }
        }

        // ---- online softmax ----
#pragma unroll
        for (int h2 = 0; h2 < 2; ++h2) {
            float mt = -1e30f;
#pragma unroll
            for (int j = 0; j < 8; ++j) {
                mt = fmaxf(mt, s[j][h2 * 2]);
                mt = fmaxf(mt, s[j][h2 * 2 + 1]);
            }
            mt = fmaxf(mt, __shfl_xor_sync(0xffffffffu, mt, 1));
            mt = fmaxf(mt, __shfl_xor_sync(0xffffffffu, mt, 2));
            float mnew  = fmaxf(mi[h2], mt);
            float alpha = __expf(mi[h2] - mnew);
            mi[h2] = mnew;
            float sum = 0.f;
#pragma unroll
            for (int j = 0; j < 8; ++j) {
                float p0 = __expf(s[j][h2 * 2]     - mnew);
                float p1 = __expf(s[j][h2 * 2 + 1] - mnew);
                s[j][h2 * 2]     = p0;
                s[j][h2 * 2 + 1] = p1;
                sum += p0 + p1;
                o[j][h2 * 2]     *= alpha;
                o[j][h2 * 2 + 1] *= alpha;
            }
            sum += __shfl_xor_sync(0xffffffffu, sum, 1);
            sum += __shfl_xor_sync(0xffffffffu, sum, 2);
            li[h2] = li[h2] * alpha + sum;
        }

        // ---- P fragments (hi/lo) ----
        uint32_t ph[4][4], pl[4][4];
#pragma unroll
        for (int kc = 0; kc < 4; ++kc) {
            const int jt = 2 * kc;
            float a0 = s[jt][0],     a1 = s[jt][1];
            float a2 = s[jt][2],     a3 = s[jt][3];
            float b0 = s[jt + 1][0], b1 = s[jt + 1][1];
            float b2 = s[jt + 1][2], b3 = s[jt + 1][3];
            ph[kc][0] = pack_bf2(a0, a1);
            ph[kc][1] = pack_bf2(a2, a3);
            ph[kc][2] = pack_bf2(b0, b1);
            ph[kc][3] = pack_bf2(b2, b3);
            __nv_bfloat162 t;
            t = *reinterpret_cast<__nv_bfloat162*>(&ph[kc][0]);
            pl[kc][0] = pack_bf2(a0 - __bfloat162float(t.x), a1 - __bfloat162float(t.y));
            t = *reinterpret_cast<__nv_bfloat162*>(&ph[kc][1]);
            pl[kc][1] = pack_bf2(a2 - __bfloat162float(t.x), a3 - __bfloat162float(t.y));
            t = *reinterpret_cast<__nv_bfloat162*>(&ph[kc][2]);
            pl[kc][2] = pack_bf2(b0 - __bfloat162float(t.x), b1 - __bfloat162float(t.y));
            t = *reinterpret_cast<__nv_bfloat162*>(&ph[kc][3]);
            pl[kc][3] = pack_bf2(b2 - __bfloat162float(t.x), b3 - __bfloat162float(t.y));
        }

        // ---- O += P.V (3-term) ----
        const uint32_t vbase = kvb + 2 * FTILE;
#pragma unroll
        for (int kc = 0; kc < 4; ++kc) {
#pragma unroll
            for (int np = 0; np < 4; ++np) {
                uint32_t vh4[4], vl4[4];
                uint32_t va = vbase + kc * (16 * FROW) + v_off + np * 32;
                LDM4T(vh4, va);
                LDM4T(vl4, va + FTILE);
                MMA_BF16(o[2 * np],     ph[kc], vh4[0], vh4[1]);
                MMA_BF16(o[2 * np],     ph[kc], vl4[0], vl4[1]);
                MMA_BF16(o[2 * np],     pl[kc], vh4[0], vh4[1]);
                MMA_BF16(o[2 * np + 1], ph[kc], vh4[2], vh4[3]);
                MMA_BF16(o[2 * np + 1], ph[kc], vl4[2], vl4[3]);
                MMA_BF16(o[2 * np + 1], pl[kc], vh4[2], vh4[3]);
            }
        }
    }

    // ---- finalize: bf16 hi/lo attention output (flat [b][s][h*64+d]) ----
    float inv0 = 1.0f / li[0];
    float inv1 = 1.0f / li[1];
#pragma unroll
    for (int j = 0; j < 8; ++j) {
        const int col = j * 8 + (lane & 3) * 2;
        size_t base0 = ((size_t)(b * SS + row0)) * DD + h * 64 + col;
        size_t base1 = ((size_t)(b * SS + row0 + 8)) * DD + h * 64 + col;
        split2_store(OhP, OlP, base0, o[j][0] * inv0, o[j][1] * inv0);
        split2_store(OhP, OlP, base1, o[j][2] * inv1, o[j][3] * inv1);
    }
}

// ---------------------------------------------------------------------------
// Host
// ---------------------------------------------------------------------------
extern "C" void kernel_launch(void* const* d_in, const int* in_sizes, int n_in,
                              void* d_out, int out_size)
{
    const float* x  = (const float*)d_in[0];
    const float* Wq = (const float*)d_in[1];
    const float* Wk = (const float*)d_in[2];
    const float* Wv = (const float*)d_in[3];
    const float* Wo = (const float*)d_in[4];
    float* out = (float*)d_out;

    __nv_bfloat16 *Xh, *Xl, *Wqh, *Wql, *Wkh, *Wkl, *Wvh, *Wvl, *Woh, *Wol, *Oh, *Ol;
    __nv_bfloat16 *Qbh, *Qbl, *Kbh, *Kbl, *Vbh, *Vbl;
    cudaGetSymbolAddress((void**)&Xh, g_Xh);
    cudaGetSymbolAddress((void**)&Xl, g_Xl);
    cudaGetSymbolAddress((void**)&Wqh, g_Wqh);
    cudaGetSymbolAddress((void**)&Wql, g_Wql);
    cudaGetSymbolAddress((void**)&Wkh, g_Wkh);
    cudaGetSymbolAddress((void**)&Wkl, g_Wkl);
    cudaGetSymbolAddress((void**)&Wvh, g_Wvh);
    cudaGetSymbolAddress((void**)&Wvl, g_Wvl);
    cudaGetSymbolAddress((void**)&Woh, g_Woh);
    cudaGetSymbolAddress((void**)&Wol, g_Wol);
    cudaGetSymbolAddress((void**)&Oh, g_Oh);
    cudaGetSymbolAddress((void**)&Ol, g_Ol);
    cudaGetSymbolAddress((void**)&Qbh, g_Qbh);
    cudaGetSymbolAddress((void**)&Qbl, g_Qbl);
    cudaGetSymbolAddress((void**)&Kbh, g_Kbh);
    cudaGetSymbolAddress((void**)&Kbl, g_Kbl);
    cudaGetSymbolAddress((void**)&Vbh, g_Vbh);
    cudaGetSymbolAddress((void**)&Vbl, g_Vbl);

    const int SMEM_DYN = 2 * STAGEB;   // 81920 -> 2 CTAs/SM
    cudaFuncSetAttribute(qkv_gemm, cudaFuncAttributeMaxDynamicSharedMemorySize, SMEM_DYN);
    cudaFuncSetAttribute(wo_gemm,  cudaFuncAttributeMaxDynamicSharedMemorySize, SMEM_DYN);
    cudaFuncSetAttribute(flash_mma, cudaFuncAttributeMaxDynamicSharedMemorySize, FSMEM);

    // single merged split launch (x, Wq, Wk, Wv, Wo)
    {
        SplitJobs jobs;
        jobs.in[0] = (const float4*)x;  jobs.hi[0] = (__nv_bfloat162*)Xh;  jobs.lo[0] = (__nv_bfloat162*)Xl;
        jobs.in[1] = (const float4*)Wq; jobs.hi[1] = (__nv_bfloat162*)Wqh; jobs.lo[1] = (__nv_bfloat162*)Wql;
        jobs.in[2] = (const float4*)Wk; jobs.hi[2] = (__nv_bfloat162*)Wkh; jobs.lo[2] = (__nv_bfloat162*)Wkl;
        jobs.in[3] = (const float4*)Wv; jobs.hi[3] = (__nv_bfloat162*)Wvh; jobs.lo[3] = (__nv_bfloat162*)Wvl;
        jobs.in[4] = (const float4*)Wo; jobs.hi[4] = (__nv_bfloat162*)Woh; jobs.lo[4] = (__nv_bfloat162*)Wol;
        int n4s[5] = { BB * SS * DD / 4, HQ * DH * DD / 4, HKV * DH * DD / 4,
                       HKV * DH * DD / 4, DD * DD / 4 };
        int cum = 0;
        for (int k = 0; k < 5; ++k) { cum += n4s[k] / 256; jobs.blk_end[k] = cum; }
        split_all<<<cum, 256>>>(jobs);
    }

    // merged QKV projection (fused RoPE/scale/split epilogue)
    qkv_gemm<<<dim3(24, 32), 256, SMEM_DYN>>>(Xh, Xl,
        Wqh, Wql, Wkh, Wkl, Wvh, Wvl,
        Qbh, Qbl, Kbh, Kbl, Vbh, Vbl);

    // MMA flash attention (causal), outputs bf16 hi/lo
    flash_mma<<<dim3(SS / 128, HQ, BB), 256, FSMEM>>>(Qbh, Qbl, Kbh, Kbl, Vbh, Vbl, Oh, Ol);

    // output projection -> fp32 result
    wo_gemm<<<dim3(16, 32), 256, SMEM_DYN>>>(Oh, Ol, Woh, Wol, out);
}

// round 9
// speedup vs baseline: 1.2033x; 1.0988x over previous
#include <cuda_runtime.h>
#include <cuda_bf16.h>
#include <math.h>
#include <stdint.h>

#define BB   2
#define SS   2048
#define DD   2048
#define HQ   32
#define HKV  8
#define DH   64
#define KDIM 2048

// ---------------------------------------------------------------------------
// Scratch (allocation-free rule: __device__ globals)
// ---------------------------------------------------------------------------
__device__ __nv_bfloat16 g_Xh[(size_t)BB * SS * DD];
__device__ __nv_bfloat16 g_Xl[(size_t)BB * SS * DD];
__device__ __nv_bfloat16 g_Wqh[(size_t)HQ * DH * DD];
__device__ __nv_bfloat16 g_Wql[(size_t)HQ * DH * DD];
__device__ __nv_bfloat16 g_Wkh[(size_t)HKV * DH * DD];
__device__ __nv_bfloat16 g_Wkl[(size_t)HKV * DH * DD];
__device__ __nv_bfloat16 g_Wvh[(size_t)HKV * DH * DD];
__device__ __nv_bfloat16 g_Wvl[(size_t)HKV * DH * DD];
__device__ __nv_bfloat16 g_Woh[(size_t)DD * DD];
__device__ __nv_bfloat16 g_Wol[(size_t)DD * DD];
__device__ __nv_bfloat16 g_Oh[(size_t)BB * SS * DD];
__device__ __nv_bfloat16 g_Ol[(size_t)BB * SS * DD];

__device__ __nv_bfloat16 g_Qbh[(size_t)BB * HQ  * SS * DH];
__device__ __nv_bfloat16 g_Qbl[(size_t)BB * HQ  * SS * DH];
__device__ __nv_bfloat16 g_Kbh[(size_t)BB * HKV * SS * DH];
__device__ __nv_bfloat16 g_Kbl[(size_t)BB * HKV * SS * DH];
__device__ __nv_bfloat16 g_Vbh[(size_t)BB * HKV * SS * DH];
__device__ __nv_bfloat16 g_Vbl[(size_t)BB * HKV * SS * DH];

// ---------------------------------------------------------------------------
// helpers
// ---------------------------------------------------------------------------
__device__ __forceinline__ uint32_t s2u(const void* p) {
    uint32_t r;
    asm("{ .reg .u64 t; cvta.to.shared.u64 t, %1; cvt.u32.u64 %0, t; }"
        : "=r"(r) : "l"(p));
    return r;
}

#define LDM4(r, addr)                                                         \
    asm volatile("ldmatrix.sync.aligned.m8n8.x4.shared.b16 {%0,%1,%2,%3}, [%4];" \
        : "=r"((r)[0]), "=r"((r)[1]), "=r"((r)[2]), "=r"((r)[3]) : "r"(addr))

#define LDM4T(r, addr)                                                        \
    asm volatile("ldmatrix.sync.aligned.m8n8.x4.trans.shared.b16 {%0,%1,%2,%3}, [%4];" \
        : "=r"((r)[0]), "=r"((r)[1]), "=r"((r)[2]), "=r"((r)[3]) : "r"(addr))

#define MMA_BF16(c, a, b0, b1)                                                \
    asm volatile("mma.sync.aligned.m16n8k16.row.col.f32.bf16.bf16.f32 "       \
        "{%0,%1,%2,%3}, {%4,%5,%6,%7}, {%8,%9}, {%0,%1,%2,%3};"               \
        : "+f"((c)[0]), "+f"((c)[1]), "+f"((c)[2]), "+f"((c)[3])              \
        : "r"((a)[0]), "r"((a)[1]), "r"((a)[2]), "r"((a)[3]), "r"(b0), "r"(b1))

#define CP_ASYNC16(dst, src)                                                  \
    asm volatile("cp.async.cg.shared.global [%0], [%1], 16;" :: "r"(dst), "l"(src))

__device__ __forceinline__ uint32_t pack_bf2(float a, float b) {
    __nv_bfloat162 t = __floats2bfloat162_rn(a, b);
    return *reinterpret_cast<uint32_t*>(&t);
}

__device__ __forceinline__ void split2_store(__nv_bfloat16* H, __nv_bfloat16* L,
                                             size_t base, float x1, float x2)
{
    __nv_bfloat16 h1 = __float2bfloat16(x1);
    __nv_bfloat16 h2 = __float2bfloat16(x2);
    __nv_bfloat16 l1 = __float2bfloat16(x1 - __bfloat162float(h1));
    __nv_bfloat16 l2 = __float2bfloat16(x2 - __bfloat162float(h2));
    *reinterpret_cast<__nv_bfloat162*>(H + base) = __nv_bfloat162(h1, h2);
    *reinterpret_cast<__nv_bfloat162*>(L + base) = __nv_bfloat162(l1, l2);
}

// ---------------------------------------------------------------------------
// merged input splits
// ---------------------------------------------------------------------------
struct SplitJobs {
    const float4* in[5];
    __nv_bfloat162* hi[5];
    __nv_bfloat162* lo[5];
    int blk_end[5];
};

__global__ void split_all(SplitJobs jobs)
{
    int bx = blockIdx.x;
    int job = 0;
#pragma unroll
    for (int k = 0; k < 5; ++k)
        if (bx >= jobs.blk_end[k]) job = k + 1;
    int blk0 = (job == 0) ? 0 : jobs.blk_end[job - 1];
    int i = (bx - blk0) * blockDim.x + threadIdx.x;

    float4 a = jobs.in[job][i];
    __nv_bfloat16 h0 = __float2bfloat16(a.x);
    __nv_bfloat16 h1 = __float2bfloat16(a.y);
    __nv_bfloat16 h2 = __float2bfloat16(a.z);
    __nv_bfloat16 h3 = __float2bfloat16(a.w);
    __nv_bfloat16 l0 = __float2bfloat16(a.x - __bfloat162float(h0));
    __nv_bfloat16 l1 = __float2bfloat16(a.y - __bfloat162float(h1));
    __nv_bfloat16 l2 = __float2bfloat16(a.z - __bfloat162float(h2));
    __nv_bfloat16 l3 = __float2bfloat16(a.w - __bfloat162float(h3));
    jobs.hi[job][2 * i + 0] = __nv_bfloat162(h0, h1);
    jobs.hi[job][2 * i + 1] = __nv_bfloat162(h2, h3);
    jobs.lo[job][2 * i + 0] = __nv_bfloat162(l0, l1);
    jobs.lo[job][2 * i + 1] = __nv_bfloat162(l2, l3);
}

// ---------------------------------------------------------------------------
// core 3-term bf16 MMA loop (CTA 128x128x2048)
// XOR-swizzled smem (64B rows, chunk ^ ((row>>1)&3)), 3-stage, 1 sync/iter,
// 96KB smem -> 2 CTAs/SM.
// ---------------------------------------------------------------------------
#define MATB   8192                 // 128 rows * 64 B
#define STAGEB 32768                // 4 * MATB
#define GSTG   3
#define KITERS (KDIM / 32)

struct GemmCore {
    float c[2][8][4];
};

__device__ __forceinline__ void gemm_mainloop(
    uint32_t sb, int tid, int lane, int wm, int wn,
    const __nv_bfloat16* Ah_g, const __nv_bfloat16* Al_g,
    const __nv_bfloat16* Bh_g, const __nv_bfloat16* Bl_g,
    int m0, int n0, GemmCore& g)
{
#pragma unroll
    for (int i = 0; i < 2; ++i)
#pragma unroll
        for (int j = 0; j < 8; ++j)
#pragma unroll
            for (int r = 0; r < 4; ++r) g.c[i][j][r] = 0.f;

    // per-lane ldmatrix addressing (swizzled)
    const int a_row = wm * 32 + (lane & 15);
    const uint32_t a_base = (uint32_t)a_row * 64;
    const uint32_t a_swz  = (uint32_t)(((lane >> 4) ^ ((a_row >> 1) & 3)) << 4);

    const int b_row = wn * 64 + (lane >> 4) * 8 + (lane & 7);
    const uint32_t b_base = (uint32_t)b_row * 64;
    const uint32_t b_swz  = (uint32_t)((((lane >> 3) & 1) ^ ((b_row >> 1) & 3)) << 4);

    const __nv_bfloat16* srcs[4] = { Ah_g, Al_g, Bh_g, Bl_g };
    const int rowbase[4] = { m0, m0, n0, n0 };

    auto load_stage = [&](int s, int k0) {
#pragma unroll
        for (int i = 0; i < 8; ++i) {
            const int mat = i >> 1;
            const int rem = ((i & 1) << 8) + tid;
            const int row = rem >> 2;
            const int seg = rem & 3;
            uint32_t d = sb + s * STAGEB + mat * MATB + row * 64 +
                         ((seg ^ ((row >> 1) & 3)) << 4);
            const __nv_bfloat16* p =
                srcs[mat] + (size_t)(rowbase[mat] + row) * KDIM + k0 + seg * 8;
            CP_ASYNC16(d, p);
        }
        asm volatile("cp.async.commit_group;");
    };

    load_stage(0, 0);
    load_stage(1, 32);

    for (int it = 0; it < KITERS; ++it) {
        if (it + 1 < KITERS) {
            asm volatile("cp.async.wait_group 1;");
        } else {
            asm volatile("cp.async.wait_group 0;");
        }
        __syncthreads();
        if (it + 2 < KITERS) {
            load_stage((it + 2) % GSTG, (it + 2) * 32);
        }

        const uint32_t st = sb + (it % GSTG) * STAGEB;
#pragma unroll
        for (int kk = 0; kk < 2; ++kk) {
            const uint32_t ksw = (uint32_t)(kk << 5);
            uint32_t ah[2][4], al[2][4], bh[4][4], bl[4][4];
#pragma unroll
            for (int i = 0; i < 2; ++i) {
                uint32_t aa = st + a_base + i * 1024 + (a_swz ^ ksw);
                LDM4(ah[i], aa);
                LDM4(al[i], aa + MATB);
            }
#pragma unroll
            for (int j2 = 0; j2 < 4; ++j2) {
                uint32_t ba = st + 2 * MATB + b_base + j2 * 1024 + (b_swz ^ ksw);
                LDM4(bh[j2], ba);
                LDM4(bl[j2], ba + MATB);
            }
#pragma unroll
            for (int i = 0; i < 2; ++i)
#pragma unroll
                for (int j = 0; j < 8; ++j) {
                    const uint32_t* bhp = &bh[j >> 1][(j & 1) * 2];
                    const uint32_t* blp = &bl[j >> 1][(j & 1) * 2];
                    MMA_BF16(g.c[i][j], ah[i], bhp[0], bhp[1]);
                    MMA_BF16(g.c[i][j], ah[i], blp[0], blp[1]);
                    MMA_BF16(g.c[i][j], al[i], bhp[0], bhp[1]);
                }
        }
    }
}

// ---------------------------------------------------------------------------
// merged QKV projection: grid (24, 32)
// ---------------------------------------------------------------------------
__global__ __launch_bounds__(256, 2)
void qkv_gemm(const __nv_bfloat16* __restrict__ Xh_g,
              const __nv_bfloat16* __restrict__ Xl_g,
              const __nv_bfloat16* __restrict__ Wqh_g, const __nv_bfloat16* __restrict__ Wql_g,
              const __nv_bfloat16* __restrict__ Wkh_g, const __nv_bfloat16* __restrict__ Wkl_g,
              const __nv_bfloat16* __restrict__ Wvh_g, const __nv_bfloat16* __restrict__ Wvl_g,
              __nv_bfloat16* __restrict__ Qh, __nv_bfloat16* __restrict__ Ql,
              __nv_bfloat16* __restrict__ Kh, __nv_bfloat16* __restrict__ Kl,
              __nv_bfloat16* __restrict__ Vh, __nv_bfloat16* __restrict__ Vl)
{
    extern __shared__ __align__(128) char smem[];
    const uint32_t sb = s2u(smem);

    const int tid  = threadIdx.x;
    const int lane = tid & 31;
    const int w    = tid >> 5;
    const int wm   = w & 3;
    const int wn   = w >> 2;
    const int bx   = blockIdx.x;
    const int m0   = blockIdx.y * 128;

    const __nv_bfloat16 *Bh_g, *Bl_g;
    __nv_bfloat16 *dH, *dL;
    int n0, Hn;
    bool rope;
    float scale;
    if (bx < 16) {
        Bh_g = Wqh_g; Bl_g = Wql_g; dH = Qh; dL = Ql;
        n0 = bx * 128; Hn = HQ; rope = true; scale = 0.125f;
    } else if (bx < 20) {
        Bh_g = Wkh_g; Bl_g = Wkl_g; dH = Kh; dL = Kl;
        n0 = (bx - 16) * 128; Hn = HKV; rope = true; scale = 1.0f;
    } else {
        Bh_g = Wvh_g; Bl_g = Wvl_g; dH = Vh; dL = Vl;
        n0 = (bx - 20) * 128; Hn = HKV; rope = false; scale = 1.0f;
    }

    GemmCore g;
    gemm_mainloop(sb, tid, lane, wm, wn, Xh_g, Xl_g, Bh_g, Bl_g, m0, n0, g);

#pragma unroll
    for (int i = 0; i < 2; ++i) {
        const int r0 = m0 + wm * 32 + i * 16 + (lane >> 2);
#pragma unroll
        for (int j = 0; j < 8; ++j) {
            const int col = n0 + wn * 64 + j * 8 + (lane & 3) * 2;
#pragma unroll
            for (int half = 0; half < 2; ++half) {
                const int row = r0 + half * 8;
                float x1 = g.c[i][j][half * 2];
                float x2 = g.c[i][j][half * 2 + 1];
                const int bidx = row >> 11;
                const int sRow = row & (SS - 1);
                const int hh = col >> 6, d0 = col & 63;
                size_t base = ((((size_t)bidx * Hn + hh) * SS + sRow) << 6) + d0;
                if (rope) {
                    float inv = exp2f(-(float)d0 * (13.287712379549449f / 64.0f));
                    float sn, cs;
                    sincosf((float)sRow * inv, &sn, &cs);
                    float y1 = x1 * cs - x2 * sn;
                    float y2 = x1 * sn + x2 * cs;
                    x1 = y1 * scale;
                    x2 = y2 * scale;
                }
                split2_store(dH, dL, base, x1, x2);
            }
        }
    }
}

// ---------------------------------------------------------------------------
// output projection: fp32 flat result
// ---------------------------------------------------------------------------
__global__ __launch_bounds__(256, 2)
void wo_gemm(const __nv_bfloat16* __restrict__ Ah_g,
             const __nv_bfloat16* __restrict__ Al_g,
             const __nv_bfloat16* __restrict__ Bh_g,
             const __nv_bfloat16* __restrict__ Bl_g,
             float* __restrict__ dst)
{
    extern __shared__ __align__(128) char smem[];
    const uint32_t sb = s2u(smem);

    const int tid  = threadIdx.x;
    const int lane = tid & 31;
    const int w    = tid >> 5;
    const int wm   = w & 3;
    const int wn   = w >> 2;
    const int m0   = blockIdx.y * 128;
    const int n0   = blockIdx.x * 128;

    GemmCore g;
    gemm_mainloop(sb, tid, lane, wm, wn, Ah_g, Al_g, Bh_g, Bl_g, m0, n0, g);

#pragma unroll
    for (int i = 0; i < 2; ++i) {
        const int r0 = m0 + wm * 32 + i * 16 + (lane >> 2);
#pragma unroll
        for (int j = 0; j < 8; ++j) {
            const int col = n0 + wn * 64 + j * 8 + (lane & 3) * 2;
#pragma unroll
            for (int half = 0; half < 2; ++half) {
                const int row = r0 + half * 8;
                *reinterpret_cast<float2*>(dst + (size_t)row * DD + col) =
                    make_float2(g.c[i][j][half * 2], g.c[i][j][half * 2 + 1]);
            }
        }
    }
}

// ---------------------------------------------------------------------------
// MMA flash attention (causal, GQA): BM=128 (8 warps x 16 rows), BN=64, Dh=64
// 3-stage KV ring of 36KB slots; Q staged through slot 0 into registers.
// smem 110592 -> 2 CTAs/SM; __launch_bounds__(256,2) caps regs at 128.
// ---------------------------------------------------------------------------
#define FROW   144
#define QTILE  18432               // 128 rows * 144 B
#define FTILE  9216                // 64 rows * 144 B (per matrix)
#define KVSTG  36864               // 4 * FTILE (Kh,Kl,Vh,Vl)
#define FSMEM  (3 * KVSTG)         // 110592

__global__ __launch_bounds__(256, 2)
void flash_mma(const __nv_bfloat16* __restrict__ Qh_g,
               const __nv_bfloat16* __restrict__ Ql_g,
               const __nv_bfloat16* __restrict__ Kh_g,
               const __nv_bfloat16* __restrict__ Kl_g,
               const __nv_bfloat16* __restrict__ Vh_g,
               const __nv_bfloat16* __restrict__ Vl_g,
               __nv_bfloat16* __restrict__ OhP,
               __nv_bfloat16* __restrict__ OlP)
{
    extern __shared__ __align__(128) char fsm[];
    const uint32_t sb = s2u(fsm);

    const int tid  = threadIdx.x;
    const int lane = tid & 31;
    const int w    = tid >> 5;
    const int qi   = gridDim.x - 1 - blockIdx.x;   // longest CTAs first
    const int qb   = qi * 128;
    const int h    = blockIdx.y;
    const int b    = blockIdx.z;
    const int kh   = h >> 2;

    const size_t qoff  = (((size_t)b * HQ + h) * SS + qb) * 64;
    const size_t kvrow = ((size_t)b * HKV + kh) * SS;

    const uint32_t a_off =
        (uint32_t)((w * 16 + (lane & 15)) * FROW + (lane >> 4) * 16);
    const uint32_t kb_off =
        (uint32_t)(((lane >> 4) * 8 + (lane & 7)) * FROW + ((lane >> 3) & 1) * 16);
    const uint32_t v_off =
        (uint32_t)((lane & 15) * FROW + (lane >> 4) * 16);

    // ---- prologue: Q (hi/lo) through slot 0 ----
#pragma unroll
    for (int i = 0; i < 8; ++i) {
        int idx = tid + 256 * i;
        int mat = idx >> 10;
        int rem = idx & 1023;
        int row = rem >> 3;
        int seg = rem & 7;
        uint32_t d = sb + mat * QTILE + row * FROW + seg * 16;
        const __nv_bfloat16* p = (mat ? Ql_g : Qh_g) + qoff + row * 64 + seg * 8;
        CP_ASYNC16(d, p);
    }
    asm volatile("cp.async.commit_group;");
    asm volatile("cp.async.wait_group 0;");
    __syncthreads();

    uint32_t qh[4][4], ql[4][4];
#pragma unroll
    for (int kc = 0; kc < 4; ++kc) {
        LDM4(qh[kc], sb + a_off + kc * 32);
        LDM4(ql[kc], sb + QTILE + a_off + kc * 32);
    }
    __syncthreads();   // all warps own Q frags before slot 0 is recycled

    auto load_kv = [&](int s, int j0) {
        const __nv_bfloat16* srcs[4] = { Kh_g, Kl_g, Vh_g, Vl_g };
        const size_t off = (kvrow + j0) * 64;
#pragma unroll
        for (int i = 0; i < 8; ++i) {
            int idx = tid + 256 * i;
            int mat = idx >> 9;
            int rem = idx & 511;
            int row = rem >> 3;
            int seg = rem & 7;
            uint32_t d = sb + s * KVSTG + mat * FTILE + row * FROW + seg * 16;
            CP_ASYNC16(d, srcs[mat] + off + row * 64 + seg * 8);
        }
        asm volatile("cp.async.commit_group;");
    };

    const int nb = qb / 64 + 2;
    load_kv(0, 0);
    if (nb > 1) load_kv(1, 64);

    float o[8][4];
#pragma unroll
    for (int j = 0; j < 8; ++j)
#pragma unroll
        for (int r = 0; r < 4; ++r) o[j][r] = 0.f;
    float mi[2] = { -1e30f, -1e30f };
    float li[2] = { 0.f, 0.f };

    const int row0 = qb + w * 16 + (lane >> 2);

    for (int it = 0; it < nb; ++it) {
        if (it + 1 < nb) {
            asm volatile("cp.async.wait_group 1;");
        } else {
            asm volatile("cp.async.wait_group 0;");
        }
        __syncthreads();
        if (it + 2 < nb) load_kv((it + 2) % 3, (it + 2) * 64);

        const uint32_t kvb = sb + (it % 3) * KVSTG;
        const int j0 = it * 64;

        // ---- S = Q.K^T (3-term) ----
        float s[8][4];
#pragma unroll
        for (int j = 0; j < 8; ++j)
#pragma unroll
            for (int r = 0; r < 4; ++r) s[j][r] = 0.f;

#pragma unroll
        for (int kc = 0; kc < 4; ++kc) {
            uint32_t bh[4][4], bl[4][4];
#pragma unroll
            for (int j2 = 0; j2 < 4; ++j2) {
                uint32_t ba = kvb + j2 * (16 * FROW) + kb_off + kc * 32;
                LDM4(bh[j2], ba);
                LDM4(bl[j2], ba + FTILE);
            }
#pragma unroll
            for (int j = 0; j < 8; ++j) {
                const uint32_t* bhp = &bh[j >> 1][(j & 1) * 2];
                const uint32_t* blp = &bl[j >> 1][(j & 1) * 2];
                MMA_BF16(s[j], qh[kc], bhp[0], bhp[1]);
                MMA_BF16(s[j], qh[kc], blp[0], blp[1]);
                MMA_BF16(s[j], ql[kc], bhp[0], bhp[1]);
            }
        }

        // ---- causal mask (only warps whose rows the block can cross) ----
        if (j0 + 63 > qb + w * 16) {
#pragma unroll
            for (int j = 0; j < 8; ++j)
#pragma unroll
                for (int r = 0; r < 4; ++r) {
                    int col = j0 + j * 8 + (lane & 3) * 2 + (r & 1);
                    int row = row0 + (r >> 1) * 8;
                    if (col > row) s[j][r] = -1e30f;
                }
        }

        // ---- online softmax ----
#pragma unroll
        for (int h2 = 0; h2 < 2; ++h2) {
            float mt = -1e30f;
#pragma unroll
            for (int j = 0; j < 8; ++j) {
                mt = fmaxf(mt, s[j][h2 * 2]);
                mt = fmaxf(mt, s[j][h2 * 2 + 1]);
            }
            mt = fmaxf(mt, __shfl_xor_sync(0xffffffffu, mt, 1));
            mt = fmaxf(mt, __shfl_xor_sync(0xffffffffu, mt, 2));
            float mnew  = fmaxf(mi[h2], mt);
            float alpha = __expf(mi[h2] - mnew);
            mi[h2] = mnew;
            float sum = 0.f;
#pragma unroll
            for (int j = 0; j < 8; ++j) {
                float p0 = __expf(s[j][h2 * 2]     - mnew);
                float p1 = __expf(s[j][h2 * 2 + 1] - mnew);
                s[j][h2 * 2]     = p0;
                s[j][h2 * 2 + 1] = p1;
                sum += p0 + p1;
                o[j][h2 * 2]     *= alpha;
                o[j][h2 * 2 + 1] *= alpha;
            }
            sum += __shfl_xor_sync(0xffffffffu, sum, 1);
            sum += __shfl_xor_sync(0xffffffffu, sum, 2);
            li[h2] = li[h2] * alpha + sum;
        }

        // ---- P fragments (hi/lo) ----
        uint32_t ph[4][4], pl[4][4];
#pragma unroll
        for (int kc = 0; kc < 4; ++kc) {
            const int jt = 2 * kc;
            float a0 = s[jt][0],     a1 = s[jt][1];
            float a2 = s[jt][2],     a3 = s[jt][3];
            float b0 = s[jt + 1][0], b1 = s[jt + 1][1];
            float b2 = s[jt + 1][2], b3 = s[jt + 1][3];
            ph[kc][0] = pack_bf2(a0, a1);
            ph[kc][1] = pack_bf2(a2, a3);
            ph[kc][2] = pack_bf2(b0, b1);
            ph[kc][3] = pack_bf2(b2, b3);
            __nv_bfloat162 t;
            t = *reinterpret_cast<__nv_bfloat162*>(&ph[kc][0]);
            pl[kc][0] = pack_bf2(a0 - __bfloat162float(t.x), a1 - __bfloat162float(t.y));
            t = *reinterpret_cast<__nv_bfloat162*>(&ph[kc][1]);
            pl[kc][1] = pack_bf2(a2 - __bfloat162float(t.x), a3 - __bfloat162float(t.y));
            t = *reinterpret_cast<__nv_bfloat162*>(&ph[kc][2]);
            pl[kc][2] = pack_bf2(b0 - __bfloat162float(t.x), b1 - __bfloat162float(t.y));
            t = *reinterpret_cast<__nv_bfloat162*>(&ph[kc][3]);
            pl[kc][3] = pack_bf2(b2 - __bfloat162float(t.x), b3 - __bfloat162float(t.y));
        }

        // ---- O += P.V (3-term) ----
        const uint32_t vbase = kvb + 2 * FTILE;
#pragma unroll
        for (int kc = 0; kc < 4; ++kc) {
#pragma unroll
            for (int np = 0; np < 4; ++np) {
                uint32_t vh4[4], vl4[4];
                uint32_t va = vbase + kc * (16 * FROW) + v_off + np * 32;
                LDM4T(vh4, va);
                LDM4T(vl4, va + FTILE);
                MMA_BF16(o[2 * np],     ph[kc], vh4[0], vh4[1]);
                MMA_BF16(o[2 * np],     ph[kc], vl4[0], vl4[1]);
                MMA_BF16(o[2 * np],     pl[kc], vh4[0], vh4[1]);
                MMA_BF16(o[2 * np + 1], ph[kc], vh4[2], vh4[3]);
                MMA_BF16(o[2 * np + 1], ph[kc], vl4[2], vl4[3]);
                MMA_BF16(o[2 * np + 1], pl[kc], vh4[2], vh4[3]);
            }
        }
    }

    // ---- finalize: bf16 hi/lo attention output (flat [b][s][h*64+d]) ----
    float inv0 = 1.0f / li[0];
    float inv1 = 1.0f / li[1];
#pragma unroll
    for (int j = 0; j < 8; ++j) {
        const int col = j * 8 + (lane & 3) * 2;
        size_t base0 = ((size_t)(b * SS + row0)) * DD + h * 64 + col;
        size_t base1 = ((size_t)(b * SS + row0 + 8)) * DD + h * 64 + col;
        split2_store(OhP, OlP, base0, o[j][0] * inv0, o[j][1] * inv0);
        split2_store(OhP, OlP, base1, o[j][2] * inv1, o[j][3] * inv1);
    }
}

// ---------------------------------------------------------------------------
// Host
// ---------------------------------------------------------------------------
extern "C" void kernel_launch(void* const* d_in, const int* in_sizes, int n_in,
                              void* d_out, int out_size)
{
    const float* x  = (const float*)d_in[0];
    const float* Wq = (const float*)d_in[1];
    const float* Wk = (const float*)d_in[2];
    const float* Wv = (const float*)d_in[3];
    const float* Wo = (const float*)d_in[4];
    float* out = (float*)d_out;

    __nv_bfloat16 *Xh, *Xl, *Wqh, *Wql, *Wkh, *Wkl, *Wvh, *Wvl, *Woh, *Wol, *Oh, *Ol;
    __nv_bfloat16 *Qbh, *Qbl, *Kbh, *Kbl, *Vbh, *Vbl;
    cudaGetSymbolAddress((void**)&Xh, g_Xh);
    cudaGetSymbolAddress((void**)&Xl, g_Xl);
    cudaGetSymbolAddress((void**)&Wqh, g_Wqh);
    cudaGetSymbolAddress((void**)&Wql, g_Wql);
    cudaGetSymbolAddress((void**)&Wkh, g_Wkh);
    cudaGetSymbolAddress((void**)&Wkl, g_Wkl);
    cudaGetSymbolAddress((void**)&Wvh, g_Wvh);
    cudaGetSymbolAddress((void**)&Wvl, g_Wvl);
    cudaGetSymbolAddress((void**)&Woh, g_Woh);
    cudaGetSymbolAddress((void**)&Wol, g_Wol);
    cudaGetSymbolAddress((void**)&Oh, g_Oh);
    cudaGetSymbolAddress((void**)&Ol, g_Ol);
    cudaGetSymbolAddress((void**)&Qbh, g_Qbh);
    cudaGetSymbolAddress((void**)&Qbl, g_Qbl);
    cudaGetSymbolAddress((void**)&Kbh, g_Kbh);
    cudaGetSymbolAddress((void**)&Kbl, g_Kbl);
    cudaGetSymbolAddress((void**)&Vbh, g_Vbh);
    cudaGetSymbolAddress((void**)&Vbl, g_Vbl);

    const int SMEM_DYN = GSTG * STAGEB;   // 98304 -> 2 CTAs/SM
    cudaFuncSetAttribute(qkv_gemm, cudaFuncAttributeMaxDynamicSharedMemorySize, SMEM_DYN);
    cudaFuncSetAttribute(wo_gemm,  cudaFuncAttributeMaxDynamicSharedMemorySize, SMEM_DYN);
    cudaFuncSetAttribute(flash_mma, cudaFuncAttributeMaxDynamicSharedMemorySize, FSMEM);

    // single merged split launch (x, Wq, Wk, Wv, Wo)
    {
        SplitJobs jobs;
        jobs.in[0] = (const float4*)x;  jobs.hi[0] = (__nv_bfloat162*)Xh;  jobs.lo[0] = (__nv_bfloat162*)Xl;
        jobs.in[1] = (const float4*)Wq; jobs.hi[1] = (__nv_bfloat162*)Wqh; jobs.lo[1] = (__nv_bfloat162*)Wql;
        jobs.in[2] = (const float4*)Wk; jobs.hi[2] = (__nv_bfloat162*)Wkh; jobs.lo[2] = (__nv_bfloat162*)Wkl;
        jobs.in[3] = (const float4*)Wv; jobs.hi[3] = (__nv_bfloat162*)Wvh; jobs.lo[3] = (__nv_bfloat162*)Wvl;
        jobs.in[4] = (const float4*)Wo; jobs.hi[4] = (__nv_bfloat162*)Woh; jobs.lo[4] = (__nv_bfloat162*)Wol;
        int n4s[5] = { BB * SS * DD / 4, HQ * DH * DD / 4, HKV * DH * DD / 4,
                       HKV * DH * DD / 4, DD * DD / 4 };
        int cum = 0;
        for (int k = 0; k < 5; ++k) { cum += n4s[k] / 256; jobs.blk_end[k] = cum; }
        split_all<<<cum, 256>>>(jobs);
    }

    // merged QKV projection (fused RoPE/scale/split epilogue)
    qkv_gemm<<<dim3(24, 32), 256, SMEM_DYN>>>(Xh, Xl,
        Wqh, Wql, Wkh, Wkl, Wvh, Wvl,
        Qbh, Qbl, Kbh, Kbl, Vbh, Vbl);

    // MMA flash attention (causal), outputs bf16 hi/lo
    flash_mma<<<dim3(SS / 128, HQ, BB), 256, FSMEM>>>(Qbh, Qbl, Kbh, Kbl, Vbh, Vbl, Oh, Ol);

    // output projection -> fp32 result
    wo_gemm<<<dim3(16, 32), 256, SMEM_DYN>>>(Oh, Ol, Woh, Wol, out);
}

// round 10
// speedup vs baseline: 1.2548x; 1.0428x over previous
#include <cuda_runtime.h>
#include <cuda_bf16.h>
#include <math.h>
#include <stdint.h>

#define BB   2
#define SS   2048
#define DD   2048
#define HQ   32
#define HKV  8
#define DH   64
#define KDIM 2048

// ---------------------------------------------------------------------------
// Scratch (allocation-free rule: __device__ globals)
// ---------------------------------------------------------------------------
__device__ __nv_bfloat16 g_Xh[(size_t)BB * SS * DD];
__device__ __nv_bfloat16 g_Xl[(size_t)BB * SS * DD];
__device__ __nv_bfloat16 g_Wqh[(size_t)HQ * DH * DD];
__device__ __nv_bfloat16 g_Wql[(size_t)HQ * DH * DD];
__device__ __nv_bfloat16 g_Wkh[(size_t)HKV * DH * DD];
__device__ __nv_bfloat16 g_Wkl[(size_t)HKV * DH * DD];
__device__ __nv_bfloat16 g_Wvh[(size_t)HKV * DH * DD];
__device__ __nv_bfloat16 g_Wvl[(size_t)HKV * DH * DD];
__device__ __nv_bfloat16 g_Woh[(size_t)DD * DD];
__device__ __nv_bfloat16 g_Wol[(size_t)DD * DD];
__device__ __nv_bfloat16 g_Oh[(size_t)BB * SS * DD];
__device__ __nv_bfloat16 g_Ol[(size_t)BB * SS * DD];

__device__ __nv_bfloat16 g_Qbh[(size_t)BB * HQ  * SS * DH];
__device__ __nv_bfloat16 g_Qbl[(size_t)BB * HQ  * SS * DH];
__device__ __nv_bfloat16 g_Kbh[(size_t)BB * HKV * SS * DH];
__device__ __nv_bfloat16 g_Kbl[(size_t)BB * HKV * SS * DH];
__device__ __nv_bfloat16 g_Vbh[(size_t)BB * HKV * SS * DH];
__device__ __nv_bfloat16 g_Vbl[(size_t)BB * HKV * SS * DH];

// ---------------------------------------------------------------------------
// helpers
// ---------------------------------------------------------------------------
__device__ __forceinline__ uint32_t s2u(const void* p) {
    uint32_t r;
    asm("{ .reg .u64 t; cvta.to.shared.u64 t, %1; cvt.u32.u64 %0, t; }"
        : "=r"(r) : "l"(p));
    return r;
}

#define LDM4(r, addr)                                                         \
    asm volatile("ldmatrix.sync.aligned.m8n8.x4.shared.b16 {%0,%1,%2,%3}, [%4];" \
        : "=r"((r)[0]), "=r"((r)[1]), "=r"((r)[2]), "=r"((r)[3]) : "r"(addr))

#define LDM4T(r, addr)                                                        \
    asm volatile("ldmatrix.sync.aligned.m8n8.x4.trans.shared.b16 {%0,%1,%2,%3}, [%4];" \
        : "=r"((r)[0]), "=r"((r)[1]), "=r"((r)[2]), "=r"((r)[3]) : "r"(addr))

#define MMA_BF16(c, a, b0, b1)                                                \
    asm volatile("mma.sync.aligned.m16n8k16.row.col.f32.bf16.bf16.f32 "       \
        "{%0,%1,%2,%3}, {%4,%5,%6,%7}, {%8,%9}, {%0,%1,%2,%3};"               \
        : "+f"((c)[0]), "+f"((c)[1]), "+f"((c)[2]), "+f"((c)[3])              \
        : "r"((a)[0]), "r"((a)[1]), "r"((a)[2]), "r"((a)[3]), "r"(b0), "r"(b1))

#define CP_ASYNC16(dst, src)                                                  \
    asm volatile("cp.async.cg.shared.global [%0], [%1], 16;" :: "r"(dst), "l"(src))

__device__ __forceinline__ uint32_t pack_bf2(float a, float b) {
    __nv_bfloat162 t = __floats2bfloat162_rn(a, b);
    return *reinterpret_cast<uint32_t*>(&t);
}

__device__ __forceinline__ void split2_store(__nv_bfloat16* H, __nv_bfloat16* L,
                                             size_t base, float x1, float x2)
{
    __nv_bfloat16 h1 = __float2bfloat16(x1);
    __nv_bfloat16 h2 = __float2bfloat16(x2);
    __nv_bfloat16 l1 = __float2bfloat16(x1 - __bfloat162float(h1));
    __nv_bfloat16 l2 = __float2bfloat16(x2 - __bfloat162float(h2));
    *reinterpret_cast<__nv_bfloat162*>(H + base) = __nv_bfloat162(h1, h2);
    *reinterpret_cast<__nv_bfloat162*>(L + base) = __nv_bfloat162(l1, l2);
}

// ---------------------------------------------------------------------------
// merged input splits
// ---------------------------------------------------------------------------
struct SplitJobs {
    const float4* in[5];
    __nv_bfloat162* hi[5];
    __nv_bfloat162* lo[5];
    int blk_end[5];
};

__global__ void split_all(SplitJobs jobs)
{
    int bx = blockIdx.x;
    int job = 0;
#pragma unroll
    for (int k = 0; k < 5; ++k)
        if (bx >= jobs.blk_end[k]) job = k + 1;
    int blk0 = (job == 0) ? 0 : jobs.blk_end[job - 1];
    int i = (bx - blk0) * blockDim.x + threadIdx.x;

    float4 a = jobs.in[job][i];
    __nv_bfloat16 h0 = __float2bfloat16(a.x);
    __nv_bfloat16 h1 = __float2bfloat16(a.y);
    __nv_bfloat16 h2 = __float2bfloat16(a.z);
    __nv_bfloat16 h3 = __float2bfloat16(a.w);
    __nv_bfloat16 l0 = __float2bfloat16(a.x - __bfloat162float(h0));
    __nv_bfloat16 l1 = __float2bfloat16(a.y - __bfloat162float(h1));
    __nv_bfloat16 l2 = __float2bfloat16(a.z - __bfloat162float(h2));
    __nv_bfloat16 l3 = __float2bfloat16(a.w - __bfloat162float(h3));
    jobs.hi[job][2 * i + 0] = __nv_bfloat162(h0, h1);
    jobs.hi[job][2 * i + 1] = __nv_bfloat162(h2, h3);
    jobs.lo[job][2 * i + 0] = __nv_bfloat162(l0, l1);
    jobs.lo[job][2 * i + 1] = __nv_bfloat162(l2, l3);
}

// ---------------------------------------------------------------------------
// core 3-term bf16 MMA loop (CTA 128x128x2048)
// 4 warps, warp tile 64x64 (better MMA:LDSM ratio).
// XOR-swizzled smem (64B rows), 3-stage, 1 sync/iter, 96KB -> 2 CTAs/SM.
// ---------------------------------------------------------------------------
#define MATB   8192                 // 128 rows * 64 B
#define STAGEB 32768                // 4 * MATB
#define GSTG   3
#define KITERS (KDIM / 32)

struct GemmCore {
    float c[4][8][4];
};

__device__ __forceinline__ void gemm_mainloop(
    uint32_t sb, int tid, int lane, int wm, int wn,
    const __nv_bfloat16* Ah_g, const __nv_bfloat16* Al_g,
    const __nv_bfloat16* Bh_g, const __nv_bfloat16* Bl_g,
    int m0, int n0, GemmCore& g)
{
#pragma unroll
    for (int i = 0; i < 4; ++i)
#pragma unroll
        for (int j = 0; j < 8; ++j)
#pragma unroll
            for (int r = 0; r < 4; ++r) g.c[i][j][r] = 0.f;

    // per-lane ldmatrix addressing (swizzle invariant under 16-row tile steps)
    const int a_row = wm * 64 + (lane & 15);
    const uint32_t a_base = (uint32_t)a_row * 64;
    const uint32_t a_swz  = (uint32_t)(((lane >> 4) ^ ((a_row >> 1) & 3)) << 4);

    const int b_row = wn * 64 + (lane >> 4) * 8 + (lane & 7);
    const uint32_t b_base = (uint32_t)b_row * 64;
    const uint32_t b_swz  = (uint32_t)((((lane >> 3) & 1) ^ ((b_row >> 1) & 3)) << 4);

    const __nv_bfloat16* srcs[4] = { Ah_g, Al_g, Bh_g, Bl_g };
    const int rowbase[4] = { m0, m0, n0, n0 };

    auto load_stage = [&](int s, int k0) {
#pragma unroll
        for (int i = 0; i < 16; ++i) {
            const int idx = tid + 128 * i;
            const int mat = idx >> 9;
            const int rem = idx & 511;
            const int row = rem >> 2;
            const int seg = rem & 3;
            uint32_t d = sb + s * STAGEB + mat * MATB + row * 64 +
                         ((seg ^ ((row >> 1) & 3)) << 4);
            const __nv_bfloat16* p =
                srcs[mat] + (size_t)(rowbase[mat] + row) * KDIM + k0 + seg * 8;
            CP_ASYNC16(d, p);
        }
        asm volatile("cp.async.commit_group;");
    };

    load_stage(0, 0);
    load_stage(1, 32);

    for (int it = 0; it < KITERS; ++it) {
        if (it + 1 < KITERS) {
            asm volatile("cp.async.wait_group 1;");
        } else {
            asm volatile("cp.async.wait_group 0;");
        }
        __syncthreads();
        if (it + 2 < KITERS) {
            load_stage((it + 2) % GSTG, (it + 2) * 32);
        }

        const uint32_t st = sb + (it % GSTG) * STAGEB;
#pragma unroll
        for (int kk = 0; kk < 2; ++kk) {
            const uint32_t ksw = (uint32_t)(kk << 5);
            uint32_t bh[4][4], bl[4][4];
#pragma unroll
            for (int j2 = 0; j2 < 4; ++j2) {
                uint32_t ba = st + 2 * MATB + b_base + j2 * 1024 + (b_swz ^ ksw);
                LDM4(bh[j2], ba);
                LDM4(bl[j2], ba + MATB);
            }
#pragma unroll
            for (int i = 0; i < 4; ++i) {
                uint32_t ah[4], al[4];
                uint32_t aa = st + a_base + i * 1024 + (a_swz ^ ksw);
                LDM4(ah, aa);
                LDM4(al, aa + MATB);
#pragma unroll
                for (int j = 0; j < 8; ++j) {
                    const uint32_t* bhp = &bh[j >> 1][(j & 1) * 2];
                    const uint32_t* blp = &bl[j >> 1][(j & 1) * 2];
                    MMA_BF16(g.c[i][j], ah, bhp[0], bhp[1]);
                    MMA_BF16(g.c[i][j], ah, blp[0], blp[1]);
                    MMA_BF16(g.c[i][j], al, bhp[0], bhp[1]);
                }
            }
        }
    }
}

// ---------------------------------------------------------------------------
// merged QKV projection: grid (24, 32), 128 threads
// ---------------------------------------------------------------------------
__global__ __launch_bounds__(128, 2)
void qkv_gemm(const __nv_bfloat16* __restrict__ Xh_g,
              const __nv_bfloat16* __restrict__ Xl_g,
              const __nv_bfloat16* __restrict__ Wqh_g, const __nv_bfloat16* __restrict__ Wql_g,
              const __nv_bfloat16* __restrict__ Wkh_g, const __nv_bfloat16* __restrict__ Wkl_g,
              const __nv_bfloat16* __restrict__ Wvh_g, const __nv_bfloat16* __restrict__ Wvl_g,
              __nv_bfloat16* __restrict__ Qh, __nv_bfloat16* __restrict__ Ql,
              __nv_bfloat16* __restrict__ Kh, __nv_bfloat16* __restrict__ Kl,
              __nv_bfloat16* __restrict__ Vh, __nv_bfloat16* __restrict__ Vl)
{
    extern __shared__ __align__(128) char smem[];
    const uint32_t sb = s2u(smem);

    const int tid  = threadIdx.x;
    const int lane = tid & 31;
    const int w    = tid >> 5;
    const int wm   = w & 1;
    const int wn   = w >> 1;
    const int bx   = blockIdx.x;
    const int m0   = blockIdx.y * 128;

    const __nv_bfloat16 *Bh_g, *Bl_g;
    __nv_bfloat16 *dH, *dL;
    int n0, Hn;
    bool rope;
    float scale;
    if (bx < 16) {
        Bh_g = Wqh_g; Bl_g = Wql_g; dH = Qh; dL = Ql;
        n0 = bx * 128; Hn = HQ; rope = true; scale = 0.125f;
    } else if (bx < 20) {
        Bh_g = Wkh_g; Bl_g = Wkl_g; dH = Kh; dL = Kl;
        n0 = (bx - 16) * 128; Hn = HKV; rope = true; scale = 1.0f;
    } else {
        Bh_g = Wvh_g; Bl_g = Wvl_g; dH = Vh; dL = Vl;
        n0 = (bx - 20) * 128; Hn = HKV; rope = false; scale = 1.0f;
    }

    GemmCore g;
    gemm_mainloop(sb, tid, lane, wm, wn, Xh_g, Xl_g, Bh_g, Bl_g, m0, n0, g);

#pragma unroll
    for (int i = 0; i < 4; ++i) {
        const int r0 = m0 + wm * 64 + i * 16 + (lane >> 2);
#pragma unroll
        for (int j = 0; j < 8; ++j) {
            const int col = n0 + wn * 64 + j * 8 + (lane & 3) * 2;
#pragma unroll
            for (int half = 0; half < 2; ++half) {
                const int row = r0 + half * 8;
                float x1 = g.c[i][j][half * 2];
                float x2 = g.c[i][j][half * 2 + 1];
                const int bidx = row >> 11;
                const int sRow = row & (SS - 1);
                const int hh = col >> 6, d0 = col & 63;
                size_t base = ((((size_t)bidx * Hn + hh) * SS + sRow) << 6) + d0;
                if (rope) {
                    float inv = exp2f(-(float)d0 * (13.287712379549449f / 64.0f));
                    float sn, cs;
                    sincosf((float)sRow * inv, &sn, &cs);
                    float y1 = x1 * cs - x2 * sn;
                    float y2 = x1 * sn + x2 * cs;
                    x1 = y1 * scale;
                    x2 = y2 * scale;
                }
                split2_store(dH, dL, base, x1, x2);
            }
        }
    }
}

// ---------------------------------------------------------------------------
// output projection: fp32 flat result, 128 threads
// ---------------------------------------------------------------------------
__global__ __launch_bounds__(128, 2)
void wo_gemm(const __nv_bfloat16* __restrict__ Ah_g,
             const __nv_bfloat16* __restrict__ Al_g,
             const __nv_bfloat16* __restrict__ Bh_g,
             const __nv_bfloat16* __restrict__ Bl_g,
             float* __restrict__ dst)
{
    extern __shared__ __align__(128) char smem[];
    const uint32_t sb = s2u(smem);

    const int tid  = threadIdx.x;
    const int lane = tid & 31;
    const int w    = tid >> 5;
    const int wm   = w & 1;
    const int wn   = w >> 1;
    const int m0   = blockIdx.y * 128;
    const int n0   = blockIdx.x * 128;

    GemmCore g;
    gemm_mainloop(sb, tid, lane, wm, wn, Ah_g, Al_g, Bh_g, Bl_g, m0, n0, g);

#pragma unroll
    for (int i = 0; i < 4; ++i) {
        const int r0 = m0 + wm * 64 + i * 16 + (lane >> 2);
#pragma unroll
        for (int j = 0; j < 8; ++j) {
            const int col = n0 + wn * 64 + j * 8 + (lane & 3) * 2;
#pragma unroll
            for (int half = 0; half < 2; ++half) {
                const int row = r0 + half * 8;
                *reinterpret_cast<float2*>(dst + (size_t)row * DD + col) =
                    make_float2(g.c[i][j][half * 2], g.c[i][j][half * 2 + 1]);
            }
        }
    }
}

// ---------------------------------------------------------------------------
// MMA flash attention (causal, GQA): BM=128 (8 warps x 16 rows), BN=64, Dh=64
// 3-stage KV ring of 36KB slots; Q staged through slot 0 into registers.
// smem 110592 -> 2 CTAs/SM; __launch_bounds__(256,2) caps regs at 128.
// ---------------------------------------------------------------------------
#define FROW   144
#define QTILE  18432               // 128 rows * 144 B
#define FTILE  9216                // 64 rows * 144 B (per matrix)
#define KVSTG  36864               // 4 * FTILE (Kh,Kl,Vh,Vl)
#define FSMEM  (3 * KVSTG)         // 110592

__global__ __launch_bounds__(256, 2)
void flash_mma(const __nv_bfloat16* __restrict__ Qh_g,
               const __nv_bfloat16* __restrict__ Ql_g,
               const __nv_bfloat16* __restrict__ Kh_g,
               const __nv_bfloat16* __restrict__ Kl_g,
               const __nv_bfloat16* __restrict__ Vh_g,
               const __nv_bfloat16* __restrict__ Vl_g,
               __nv_bfloat16* __restrict__ OhP,
               __nv_bfloat16* __restrict__ OlP)
{
    extern __shared__ __align__(128) char fsm[];
    const uint32_t sb = s2u(fsm);

    const int tid  = threadIdx.x;
    const int lane = tid & 31;
    const int w    = tid >> 5;
    const int qi   = gridDim.x - 1 - blockIdx.x;   // longest CTAs first
    const int qb   = qi * 128;
    const int h    = blockIdx.y;
    const int b    = blockIdx.z;
    const int kh   = h >> 2;

    const size_t qoff  = (((size_t)b * HQ + h) * SS + qb) * 64;
    const size_t kvrow = ((size_t)b * HKV + kh) * SS;

    const uint32_t a_off =
        (uint32_t)((w * 16 + (lane & 15)) * FROW + (lane >> 4) * 16);
    const uint32_t kb_off =
        (uint32_t)(((lane >> 4) * 8 + (lane & 7)) * FROW + ((lane >> 3) & 1) * 16);
    const uint32_t v_off =
        (uint32_t)((lane & 15) * FROW + (lane >> 4) * 16);

    // ---- prologue: Q (hi/lo) through slot 0 ----
#pragma unroll
    for (int i = 0; i < 8; ++i) {
        int idx = tid + 256 * i;
        int mat = idx >> 10;
        int rem = idx & 1023;
        int row = rem >> 3;
        int seg = rem & 7;
        uint32_t d = sb + mat * QTILE + row * FROW + seg * 16;
        const __nv_bfloat16* p = (mat ? Ql_g : Qh_g) + qoff + row * 64 + seg * 8;
        CP_ASYNC16(d, p);
    }
    asm volatile("cp.async.commit_group;");
    asm volatile("cp.async.wait_group 0;");
    __syncthreads();

    uint32_t qh[4][4], ql[4][4];
#pragma unroll
    for (int kc = 0; kc < 4; ++kc) {
        LDM4(qh[kc], sb + a_off + kc * 32);
        LDM4(ql[kc], sb + QTILE + a_off + kc * 32);
    }
    __syncthreads();   // all warps own Q frags before slot 0 is recycled

    auto load_kv = [&](int s, int j0) {
        const __nv_bfloat16* srcs[4] = { Kh_g, Kl_g, Vh_g, Vl_g };
        const size_t off = (kvrow + j0) * 64;
#pragma unroll
        for (int i = 0; i < 8; ++i) {
            int idx = tid + 256 * i;
            int mat = idx >> 9;
            int rem = idx & 511;
            int row = rem >> 3;
            int seg = rem & 7;
            uint32_t d = sb + s * KVSTG + mat * FTILE + row * FROW + seg * 16;
            CP_ASYNC16(d, srcs[mat] + off + row * 64 + seg * 8);
        }
        asm volatile("cp.async.commit_group;");
    };

    const int nb = qb / 64 + 2;
    load_kv(0, 0);
    if (nb > 1) load_kv(1, 64);

    float o[8][4];
#pragma unroll
    for (int j = 0; j < 8; ++j)
#pragma unroll
        for (int r = 0; r < 4; ++r) o[j][r] = 0.f;
    float mi[2] = { -1e30f, -1e30f };
    float li[2] = { 0.f, 0.f };

    const int row0 = qb + w * 16 + (lane >> 2);

    for (int it = 0; it < nb; ++it) {
        if (it + 1 < nb) {
            asm volatile("cp.async.wait_group 1;");
        } else {
            asm volatile("cp.async.wait_group 0;");
        }
        __syncthreads();
        if (it + 2 < nb) load_kv((it + 2) % 3, (it + 2) * 64);

        const uint32_t kvb = sb + (it % 3) * KVSTG;
        const int j0 = it * 64;

        // ---- S = Q.K^T (3-term) ----
        float s[8][4];
#pragma unroll
        for (int j = 0; j < 8; ++j)
#pragma unroll
            for (int r = 0; r < 4; ++r) s[j][r] = 0.f;

#pragma unroll
        for (int kc = 0; kc < 4; ++kc) {
            uint32_t bh[4][4], bl[4][4];
#pragma unroll
            for (int j2 = 0; j2 < 4; ++j2) {
                uint32_t ba = kvb + j2 * (16 * FROW) + kb_off + kc * 32;
                LDM4(bh[j2], ba);
                LDM4(bl[j2], ba + FTILE);
            }
#pragma unroll
            for (int j = 0; j < 8; ++j) {
                const uint32_t* bhp = &bh[j >> 1][(j & 1) * 2];
                const uint32_t* blp = &bl[j >> 1][(j & 1) * 2];
                MMA_BF16(s[j], qh[kc], bhp[0], bhp[1]);
                MMA_BF16(s[j], qh[kc], blp[0], blp[1]);
                MMA_BF16(s[j], ql[kc], bhp[0], bhp[1]);
            }
        }

        // ---- causal mask (only warps whose rows the block can cross) ----
        if (j0 + 63 > qb + w * 16) {
#pragma unroll
            for (int j = 0; j < 8; ++j)
#pragma unroll
                for (int r = 0; r < 4; ++r) {
                    int col = j0 + j * 8 + (lane & 3) * 2 + (r & 1);
                    int row = row0 + (r >> 1) * 8;
                    if (col > row) s[j][r] = -1e30f;
                }
        }

        // ---- online softmax ----
#pragma unroll
        for (int h2 = 0; h2 < 2; ++h2) {
            float mt = -1e30f;
#pragma unroll
            for (int j = 0; j < 8; ++j) {
                mt = fmaxf(mt, s[j][h2 * 2]);
                mt = fmaxf(mt, s[j][h2 * 2 + 1]);
            }
            mt = fmaxf(mt, __shfl_xor_sync(0xffffffffu, mt, 1));
            mt = fmaxf(mt, __shfl_xor_sync(0xffffffffu, mt, 2));
            float mnew  = fmaxf(mi[h2], mt);
            float alpha = __expf(mi[h2] - mnew);
            mi[h2] = mnew;
            float sum = 0.f;
#pragma unroll
            for (int j = 0; j < 8; ++j) {
                float p0 = __expf(s[j][h2 * 2]     - mnew);
                float p1 = __expf(s[j][h2 * 2 + 1] - mnew);
                s[j][h2 * 2]     = p0;
                s[j][h2 * 2 + 1] = p1;
                sum += p0 + p1;
                o[j][h2 * 2]     *= alpha;
                o[j][h2 * 2 + 1] *= alpha;
            }
            sum += __shfl_xor_sync(0xffffffffu, sum, 1);
            sum += __shfl_xor_sync(0xffffffffu, sum, 2);
            li[h2] = li[h2] * alpha + sum;
        }

        // ---- P fragments (hi/lo) ----
        uint32_t ph[4][4], pl[4][4];
#pragma unroll
        for (int kc = 0; kc < 4; ++kc) {
            const int jt = 2 * kc;
            float a0 = s[jt][0],     a1 = s[jt][1];
            float a2 = s[jt][2],     a3 = s[jt][3];
            float b0 = s[jt + 1][0], b1 = s[jt + 1][1];
            float b2 = s[jt + 1][2], b3 = s[jt + 1][3];
            ph[kc][0] = pack_bf2(a0, a1);
            ph[kc][1] = pack_bf2(a2, a3);
            ph[kc][2] = pack_bf2(b0, b1);
            ph[kc][3] = pack_bf2(b2, b3);
            __nv_bfloat162 t;
            t = *reinterpret_cast<__nv_bfloat162*>(&ph[kc][0]);
            pl[kc][0] = pack_bf2(a0 - __bfloat162float(t.x), a1 - __bfloat162float(t.y));
            t = *reinterpret_cast<__nv_bfloat162*>(&ph[kc][1]);
            pl[kc][1] = pack_bf2(a2 - __bfloat162float(t.x), a3 - __bfloat162float(t.y));
            t = *reinterpret_cast<__nv_bfloat162*>(&ph[kc][2]);
            pl[kc][2] = pack_bf2(b0 - __bfloat162float(t.x), b1 - __bfloat162float(t.y));
            t = *reinterpret_cast<__nv_bfloat162*>(&ph[kc][3]);
            pl[kc][3] = pack_bf2(b2 - __bfloat162float(t.x), b3 - __bfloat162float(t.y));
        }

        // ---- O += P.V (3-term) ----
        const uint32_t vbase = kvb + 2 * FTILE;
#pragma unroll
        for (int kc = 0; kc < 4; ++kc) {
#pragma unroll
            for (int np = 0; np < 4; ++np) {
                uint32_t vh4[4], vl4[4];
                uint32_t va = vbase + kc * (16 * FROW) + v_off + np * 32;
                LDM4T(vh4, va);
                LDM4T(vl4, va + FTILE);
                MMA_BF16(o[2 * np],     ph[kc], vh4[0], vh4[1]);
                MMA_BF16(o[2 * np],     ph[kc], vl4[0], vl4[1]);
                MMA_BF16(o[2 * np],     pl[kc], vh4[0], vh4[1]);
                MMA_BF16(o[2 * np + 1], ph[kc], vh4[2], vh4[3]);
                MMA_BF16(o[2 * np + 1], ph[kc], vl4[2], vl4[3]);
                MMA_BF16(o[2 * np + 1], pl[kc], vh4[2], vh4[3]);
            }
        }
    }

    // ---- finalize: bf16 hi/lo attention output (flat [b][s][h*64+d]) ----
    float inv0 = 1.0f / li[0];
    float inv1 = 1.0f / li[1];
#pragma unroll
    for (int j = 0; j < 8; ++j) {
        const int col = j * 8 + (lane & 3) * 2;
        size_t base0 = ((size_t)(b * SS + row0)) * DD + h * 64 + col;
        size_t base1 = ((size_t)(b * SS + row0 + 8)) * DD + h * 64 + col;
        split2_store(OhP, OlP, base0, o[j][0] * inv0, o[j][1] * inv0);
        split2_store(OhP, OlP, base1, o[j][2] * inv1, o[j][3] * inv1);
    }
}

// ---------------------------------------------------------------------------
// Host
// ---------------------------------------------------------------------------
extern "C" void kernel_launch(void* const* d_in, const int* in_sizes, int n_in,
                              void* d_out, int out_size)
{
    const float* x  = (const float*)d_in[0];
    const float* Wq = (const float*)d_in[1];
    const float* Wk = (const float*)d_in[2];
    const float* Wv = (const float*)d_in[3];
    const float* Wo = (const float*)d_in[4];
    float* out = (float*)d_out;

    __nv_bfloat16 *Xh, *Xl, *Wqh, *Wql, *Wkh, *Wkl, *Wvh, *Wvl, *Woh, *Wol, *Oh, *Ol;
    __nv_bfloat16 *Qbh, *Qbl, *Kbh, *Kbl, *Vbh, *Vbl;
    cudaGetSymbolAddress((void**)&Xh, g_Xh);
    cudaGetSymbolAddress((void**)&Xl, g_Xl);
    cudaGetSymbolAddress((void**)&Wqh, g_Wqh);
    cudaGetSymbolAddress((void**)&Wql, g_Wql);
    cudaGetSymbolAddress((void**)&Wkh, g_Wkh);
    cudaGetSymbolAddress((void**)&Wkl, g_Wkl);
    cudaGetSymbolAddress((void**)&Wvh, g_Wvh);
    cudaGetSymbolAddress((void**)&Wvl, g_Wvl);
    cudaGetSymbolAddress((void**)&Woh, g_Woh);
    cudaGetSymbolAddress((void**)&Wol, g_Wol);
    cudaGetSymbolAddress((void**)&Oh, g_Oh);
    cudaGetSymbolAddress((void**)&Ol, g_Ol);
    cudaGetSymbolAddress((void**)&Qbh, g_Qbh);
    cudaGetSymbolAddress((void**)&Qbl, g_Qbl);
    cudaGetSymbolAddress((void**)&Kbh, g_Kbh);
    cudaGetSymbolAddress((void**)&Kbl, g_Kbl);
    cudaGetSymbolAddress((void**)&Vbh, g_Vbh);
    cudaGetSymbolAddress((void**)&Vbl, g_Vbl);

    const int SMEM_DYN = GSTG * STAGEB;   // 98304 -> 2 CTAs/SM
    cudaFuncSetAttribute(qkv_gemm, cudaFuncAttributeMaxDynamicSharedMemorySize, SMEM_DYN);
    cudaFuncSetAttribute(wo_gemm,  cudaFuncAttributeMaxDynamicSharedMemorySize, SMEM_DYN);
    cudaFuncSetAttribute(flash_mma, cudaFuncAttributeMaxDynamicSharedMemorySize, FSMEM);

    // single merged split launch (x, Wq, Wk, Wv, Wo)
    {
        SplitJobs jobs;
        jobs.in[0] = (const float4*)x;  jobs.hi[0] = (__nv_bfloat162*)Xh;  jobs.lo[0] = (__nv_bfloat162*)Xl;
        jobs.in[1] = (const float4*)Wq; jobs.hi[1] = (__nv_bfloat162*)Wqh; jobs.lo[1] = (__nv_bfloat162*)Wql;
        jobs.in[2] = (const float4*)Wk; jobs.hi[2] = (__nv_bfloat162*)Wkh; jobs.lo[2] = (__nv_bfloat162*)Wkl;
        jobs.in[3] = (const float4*)Wv; jobs.hi[3] = (__nv_bfloat162*)Wvh; jobs.lo[3] = (__nv_bfloat162*)Wvl;
        jobs.in[4] = (const float4*)Wo; jobs.hi[4] = (__nv_bfloat162*)Woh; jobs.lo[4] = (__nv_bfloat162*)Wol;
        int n4s[5] = { BB * SS * DD / 4, HQ * DH * DD / 4, HKV * DH * DD / 4,
                       HKV * DH * DD / 4, DD * DD / 4 };
        int cum = 0;
        for (int k = 0; k < 5; ++k) { cum += n4s[k] / 256; jobs.blk_end[k] = cum; }
        split_all<<<cum, 256>>>(jobs);
    }

    // merged QKV projection (fused RoPE/scale/split epilogue)
    qkv_gemm<<<dim3(24, 32), 128, SMEM_DYN>>>(Xh, Xl,
        Wqh, Wql, Wkh, Wkl, Wvh, Wvl,
        Qbh, Qbl, Kbh, Kbl, Vbh, Vbl);

    // MMA flash attention (causal), outputs bf16 hi/lo
    flash_mma<<<dim3(SS / 128, HQ, BB), 256, FSMEM>>>(Qbh, Qbl, Kbh, Kbl, Vbh, Vbl, Oh, Ol);

    // output projection -> fp32 result
    wo_gemm<<<dim3(16, 32), 128, SMEM_DYN>>>(Oh, Ol, Woh, Wol, out);
}

// round 11
// speedup vs baseline: 1.7743x; 1.4140x over previous
#include <cuda_runtime.h>
#include <cuda_fp16.h>
#include <math.h>
#include <stdint.h>

#define BB   2
#define SS   2048
#define DD   2048
#define HQ   32
#define HKV  8
#define DH   64
#define KDIM 2048

// ---------------------------------------------------------------------------
// Scratch (allocation-free rule: __device__ globals)
// fp16 2-term scheme: A-side operands hi only; B-side (weights/K/V) hi+lo.
// ---------------------------------------------------------------------------
__device__ __half g_Xh[(size_t)BB * SS * DD];
__device__ __half g_Wqh[(size_t)HQ * DH * DD];
__device__ __half g_Wql[(size_t)HQ * DH * DD];
__device__ __half g_Wkh[(size_t)HKV * DH * DD];
__device__ __half g_Wkl[(size_t)HKV * DH * DD];
__device__ __half g_Wvh[(size_t)HKV * DH * DD];
__device__ __half g_Wvl[(size_t)HKV * DH * DD];
__device__ __half g_Woh[(size_t)DD * DD];
__device__ __half g_Wol[(size_t)DD * DD];
__device__ __half g_Oh[(size_t)BB * SS * DD];

__device__ __half g_Qbh[(size_t)BB * HQ  * SS * DH];
__device__ __half g_Kbh[(size_t)BB * HKV * SS * DH];
__device__ __half g_Kbl[(size_t)BB * HKV * SS * DH];
__device__ __half g_Vbh[(size_t)BB * HKV * SS * DH];
__device__ __half g_Vbl[(size_t)BB * HKV * SS * DH];

// ---------------------------------------------------------------------------
// helpers
// ---------------------------------------------------------------------------
__device__ __forceinline__ uint32_t s2u(const void* p) {
    uint32_t r;
    asm("{ .reg .u64 t; cvta.to.shared.u64 t, %1; cvt.u32.u64 %0, t; }"
        : "=r"(r) : "l"(p));
    return r;
}

#define LDM4(r, addr)                                                         \
    asm volatile("ldmatrix.sync.aligned.m8n8.x4.shared.b16 {%0,%1,%2,%3}, [%4];" \
        : "=r"((r)[0]), "=r"((r)[1]), "=r"((r)[2]), "=r"((r)[3]) : "r"(addr))

#define LDM4T(r, addr)                                                        \
    asm volatile("ldmatrix.sync.aligned.m8n8.x4.trans.shared.b16 {%0,%1,%2,%3}, [%4];" \
        : "=r"((r)[0]), "=r"((r)[1]), "=r"((r)[2]), "=r"((r)[3]) : "r"(addr))

#define MMA_F16(c, a, b0, b1)                                                 \
    asm volatile("mma.sync.aligned.m16n8k16.row.col.f32.f16.f16.f32 "         \
        "{%0,%1,%2,%3}, {%4,%5,%6,%7}, {%8,%9}, {%0,%1,%2,%3};"               \
        : "+f"((c)[0]), "+f"((c)[1]), "+f"((c)[2]), "+f"((c)[3])              \
        : "r"((a)[0]), "r"((a)[1]), "r"((a)[2]), "r"((a)[3]), "r"(b0), "r"(b1))

#define CP_ASYNC16(dst, src)                                                  \
    asm volatile("cp.async.cg.shared.global [%0], [%1], 16;" :: "r"(dst), "l"(src))

__device__ __forceinline__ uint32_t pack_h2(float a, float b) {
    __half2 t = __floats2half2_rn(a, b);
    return *reinterpret_cast<uint32_t*>(&t);
}

__device__ __forceinline__ void split2_store(__half* H, __half* L,
                                             size_t base, float x1, float x2)
{
    __half h1 = __float2half_rn(x1);
    __half h2 = __float2half_rn(x2);
    __half l1 = __float2half_rn(x1 - __half2float(h1));
    __half l2 = __float2half_rn(x2 - __half2float(h2));
    *reinterpret_cast<__half2*>(H + base) = __half2(h1, h2);
    *reinterpret_cast<__half2*>(L + base) = __half2(l1, l2);
}

// ---------------------------------------------------------------------------
// merged input splits: job 0 (x) hi only; jobs 1-4 (weights) hi+lo
// ---------------------------------------------------------------------------
struct SplitJobs {
    const float4* in[5];
    __half2* hi[5];
    __half2* lo[5];
    int blk_end[5];
};

__global__ void split_all(SplitJobs jobs)
{
    int bx = blockIdx.x;
    int job = 0;
#pragma unroll
    for (int k = 0; k < 5; ++k)
        if (bx >= jobs.blk_end[k]) job = k + 1;
    int blk0 = (job == 0) ? 0 : jobs.blk_end[job - 1];
    int i = (bx - blk0) * blockDim.x + threadIdx.x;

    float4 a = jobs.in[job][i];
    __half h0 = __float2half_rn(a.x);
    __half h1 = __float2half_rn(a.y);
    __half h2 = __float2half_rn(a.z);
    __half h3 = __float2half_rn(a.w);
    jobs.hi[job][2 * i + 0] = __half2(h0, h1);
    jobs.hi[job][2 * i + 1] = __half2(h2, h3);
    if (jobs.lo[job]) {
        __half l0 = __float2half_rn(a.x - __half2float(h0));
        __half l1 = __float2half_rn(a.y - __half2float(h1));
        __half l2 = __float2half_rn(a.z - __half2float(h2));
        __half l3 = __float2half_rn(a.w - __half2float(h3));
        jobs.lo[job][2 * i + 0] = __half2(l0, l1);
        jobs.lo[job][2 * i + 1] = __half2(l2, l3);
    }
}

// ---------------------------------------------------------------------------
// core 2-term fp16 MMA loop (CTA 128x128x2048)
// 4 warps, warp tile 64x64. Matrices per stage: Ah, Bh, Bl (24KB).
// XOR-swizzled smem (64B rows), 4-stage ring, 1 sync/iter, 96KB -> 2 CTAs/SM.
// ---------------------------------------------------------------------------
#define MATB   8192                 // 128 rows * 64 B
#define STAGEB 24576                // 3 * MATB
#define GSTG   4
#define KITERS (KDIM / 32)

struct GemmCore {
    float c[4][8][4];
};

__device__ __forceinline__ void gemm_mainloop(
    uint32_t sb, int tid, int lane, int wm, int wn,
    const __half* Ah_g,
    const __half* Bh_g, const __half* Bl_g,
    int m0, int n0, GemmCore& g)
{
#pragma unroll
    for (int i = 0; i < 4; ++i)
#pragma unroll
        for (int j = 0; j < 8; ++j)
#pragma unroll
            for (int r = 0; r < 4; ++r) g.c[i][j][r] = 0.f;

    const int a_row = wm * 64 + (lane & 15);
    const uint32_t a_base = (uint32_t)a_row * 64;
    const uint32_t a_swz  = (uint32_t)(((lane >> 4) ^ ((a_row >> 1) & 3)) << 4);

    const int b_row = wn * 64 + (lane >> 4) * 8 + (lane & 7);
    const uint32_t b_base = (uint32_t)b_row * 64;
    const uint32_t b_swz  = (uint32_t)((((lane >> 3) & 1) ^ ((b_row >> 1) & 3)) << 4);

    const __half* srcs[3] = { Ah_g, Bh_g, Bl_g };
    const int rowbase[3] = { m0, n0, n0 };

    auto load_stage = [&](int s, int k0) {
#pragma unroll
        for (int i = 0; i < 12; ++i) {
            const int idx = tid + 128 * i;
            const int mat = idx >> 9;
            const int rem = idx & 511;
            const int row = rem >> 2;
            const int seg = rem & 3;
            uint32_t d = sb + s * STAGEB + mat * MATB + row * 64 +
                         ((seg ^ ((row >> 1) & 3)) << 4);
            const __half* p =
                srcs[mat] + (size_t)(rowbase[mat] + row) * KDIM + k0 + seg * 8;
            CP_ASYNC16(d, p);
        }
        asm volatile("cp.async.commit_group;");
    };

    load_stage(0, 0);
    load_stage(1, 32);
    load_stage(2, 64);

    for (int it = 0; it < KITERS; ++it) {
        if (it + 1 < KITERS) {
            asm volatile("cp.async.wait_group 2;");
        } else {
            asm volatile("cp.async.wait_group 0;");
        }
        __syncthreads();
        if (it + 3 < KITERS) {
            load_stage((it + 3) % GSTG, (it + 3) * 32);
        }

        const uint32_t st = sb + (it % GSTG) * STAGEB;
#pragma unroll
        for (int kk = 0; kk < 2; ++kk) {
            const uint32_t ksw = (uint32_t)(kk << 5);
            uint32_t bh[4][4], bl[4][4];
#pragma unroll
            for (int j2 = 0; j2 < 4; ++j2) {
                uint32_t ba = st + MATB + b_base + j2 * 1024 + (b_swz ^ ksw);
                LDM4(bh[j2], ba);
                LDM4(bl[j2], ba + MATB);
            }
#pragma unroll
            for (int i = 0; i < 4; ++i) {
                uint32_t ah[4];
                LDM4(ah, st + a_base + i * 1024 + (a_swz ^ ksw));
#pragma unroll
                for (int j = 0; j < 8; ++j) {
                    const uint32_t* bhp = &bh[j >> 1][(j & 1) * 2];
                    const uint32_t* blp = &bl[j >> 1][(j & 1) * 2];
                    MMA_F16(g.c[i][j], ah, bhp[0], bhp[1]);
                    MMA_F16(g.c[i][j], ah, blp[0], blp[1]);
                }
            }
        }
    }
}

// ---------------------------------------------------------------------------
// merged QKV projection: grid (24, 32), 128 threads
// Q -> hi only (rope, 1/8); K -> hi+lo (rope); V -> hi+lo
// ---------------------------------------------------------------------------
__global__ __launch_bounds__(128, 2)
void qkv_gemm(const __half* __restrict__ Xh_g,
              const __half* __restrict__ Wqh_g, const __half* __restrict__ Wql_g,
              const __half* __restrict__ Wkh_g, const __half* __restrict__ Wkl_g,
              const __half* __restrict__ Wvh_g, const __half* __restrict__ Wvl_g,
              __half* __restrict__ Qh,
              __half* __restrict__ Kh, __half* __restrict__ Kl,
              __half* __restrict__ Vh, __half* __restrict__ Vl)
{
    extern __shared__ __align__(128) char smem[];
    const uint32_t sb = s2u(smem);

    const int tid  = threadIdx.x;
    const int lane = tid & 31;
    const int w    = tid >> 5;
    const int wm   = w & 1;
    const int wn   = w >> 1;
    const int bx   = blockIdx.x;
    const int m0   = blockIdx.y * 128;

    const __half *Bh_g, *Bl_g;
    __half *dH, *dL;
    int n0, Hn;
    bool rope;
    float scale;
    if (bx < 16) {
        Bh_g = Wqh_g; Bl_g = Wql_g; dH = Qh; dL = nullptr;
        n0 = bx * 128; Hn = HQ; rope = true; scale = 0.125f;
    } else if (bx < 20) {
        Bh_g = Wkh_g; Bl_g = Wkl_g; dH = Kh; dL = Kl;
        n0 = (bx - 16) * 128; Hn = HKV; rope = true; scale = 1.0f;
    } else {
        Bh_g = Wvh_g; Bl_g = Wvl_g; dH = Vh; dL = Vl;
        n0 = (bx - 20) * 128; Hn = HKV; rope = false; scale = 1.0f;
    }

    GemmCore g;
    gemm_mainloop(sb, tid, lane, wm, wn, Xh_g, Bh_g, Bl_g, m0, n0, g);

#pragma unroll
    for (int i = 0; i < 4; ++i) {
        const int r0 = m0 + wm * 64 + i * 16 + (lane >> 2);
#pragma unroll
        for (int j = 0; j < 8; ++j) {
            const int col = n0 + wn * 64 + j * 8 + (lane & 3) * 2;
#pragma unroll
            for (int half = 0; half < 2; ++half) {
                const int row = r0 + half * 8;
                float x1 = g.c[i][j][half * 2];
                float x2 = g.c[i][j][half * 2 + 1];
                const int bidx = row >> 11;
                const int sRow = row & (SS - 1);
                const int hh = col >> 6, d0 = col & 63;
                size_t base = ((((size_t)bidx * Hn + hh) * SS + sRow) << 6) + d0;
                if (rope) {
                    float inv = exp2f(-(float)d0 * (13.287712379549449f / 64.0f));
                    float sn, cs;
                    sincosf((float)sRow * inv, &sn, &cs);
                    float y1 = x1 * cs - x2 * sn;
                    float y2 = x1 * sn + x2 * cs;
                    x1 = y1 * scale;
                    x2 = y2 * scale;
                }
                if (dL) {
                    split2_store(dH, dL, base, x1, x2);
                } else {
                    *reinterpret_cast<__half2*>(dH + base) =
                        __floats2half2_rn(x1, x2);
                }
            }
        }
    }
}

// ---------------------------------------------------------------------------
// output projection: fp32 flat result, 128 threads
// ---------------------------------------------------------------------------
__global__ __launch_bounds__(128, 2)
void wo_gemm(const __half* __restrict__ Ah_g,
             const __half* __restrict__ Bh_g,
             const __half* __restrict__ Bl_g,
             float* __restrict__ dst)
{
    extern __shared__ __align__(128) char smem[];
    const uint32_t sb = s2u(smem);

    const int tid  = threadIdx.x;
    const int lane = tid & 31;
    const int w    = tid >> 5;
    const int wm   = w & 1;
    const int wn   = w >> 1;
    const int m0   = blockIdx.y * 128;
    const int n0   = blockIdx.x * 128;

    GemmCore g;
    gemm_mainloop(sb, tid, lane, wm, wn, Ah_g, Bh_g, Bl_g, m0, n0, g);

#pragma unroll
    for (int i = 0; i < 4; ++i) {
        const int r0 = m0 + wm * 64 + i * 16 + (lane >> 2);
#pragma unroll
        for (int j = 0; j < 8; ++j) {
            const int col = n0 + wn * 64 + j * 8 + (lane & 3) * 2;
#pragma unroll
            for (int half = 0; half < 2; ++half) {
                const int row = r0 + half * 8;
                *reinterpret_cast<float2*>(dst + (size_t)row * DD + col) =
                    make_float2(g.c[i][j][half * 2], g.c[i][j][half * 2 + 1]);
            }
        }
    }
}

// ---------------------------------------------------------------------------
// MMA flash attention (causal, GQA): BM=128 (8 warps x 16 rows), BN=64, Dh=64
// fp16 2-term: Q hi only; K/V hi+lo. 3-stage KV ring; Q staged through slot 0.
// smem 110592 -> 2 CTAs/SM; __launch_bounds__(256,2).
// ---------------------------------------------------------------------------
#define FROW   144
#define QTILE  18432               // 128 rows * 144 B (Q hi)
#define FTILE  9216                // 64 rows * 144 B (per matrix)
#define KVSTG  36864               // 4 * FTILE (Kh,Kl,Vh,Vl)
#define FSMEM  (3 * KVSTG)         // 110592

__global__ __launch_bounds__(256, 2)
void flash_mma(const __half* __restrict__ Qh_g,
               const __half* __restrict__ Kh_g,
               const __half* __restrict__ Kl_g,
               const __half* __restrict__ Vh_g,
               const __half* __restrict__ Vl_g,
               __half* __restrict__ OhP)
{
    extern __shared__ __align__(128) char fsm[];
    const uint32_t sb = s2u(fsm);

    const int tid  = threadIdx.x;
    const int lane = tid & 31;
    const int w    = tid >> 5;
    const int qi   = gridDim.x - 1 - blockIdx.x;   // longest CTAs first
    const int qb   = qi * 128;
    const int h    = blockIdx.y;
    const int b    = blockIdx.z;
    const int kh   = h >> 2;

    const size_t qoff  = (((size_t)b * HQ + h) * SS + qb) * 64;
    const size_t kvrow = ((size_t)b * HKV + kh) * SS;

    const uint32_t a_off =
        (uint32_t)((w * 16 + (lane & 15)) * FROW + (lane >> 4) * 16);
    const uint32_t kb_off =
        (uint32_t)(((lane >> 4) * 8 + (lane & 7)) * FROW + ((lane >> 3) & 1) * 16);
    const uint32_t v_off =
        (uint32_t)((lane & 15) * FROW + (lane >> 4) * 16);

    // ---- prologue: Q hi through slot 0 ----
#pragma unroll
    for (int i = 0; i < 4; ++i) {
        int idx = tid + 256 * i;
        int row = idx >> 3;
        int seg = idx & 7;
        uint32_t d = sb + row * FROW + seg * 16;
        CP_ASYNC16(d, Qh_g + qoff + row * 64 + seg * 8);
    }
    asm volatile("cp.async.commit_group;");
    asm volatile("cp.async.wait_group 0;");
    __syncthreads();

    uint32_t qh[4][4];
#pragma unroll
    for (int kc = 0; kc < 4; ++kc)
        LDM4(qh[kc], sb + a_off + kc * 32);
    __syncthreads();   // all warps own Q frags before slot 0 is recycled

    auto load_kv = [&](int s, int j0) {
        const __half* srcs[4] = { Kh_g, Kl_g, Vh_g, Vl_g };
        const size_t off = (kvrow + j0) * 64;
#pragma unroll
        for (int i = 0; i < 8; ++i) {
            int idx = tid + 256 * i;
            int mat = idx >> 9;
            int rem = idx & 511;
            int row = rem >> 3;
            int seg = rem & 7;
            uint32_t d = sb + s * KVSTG + mat * FTILE + row * FROW + seg * 16;
            CP_ASYNC16(d, srcs[mat] + off + row * 64 + seg * 8);
        }
        asm volatile("cp.async.commit_group;");
    };

    const int nb = qb / 64 + 2;
    load_kv(0, 0);
    if (nb > 1) load_kv(1, 64);

    float o[8][4];
#pragma unroll
    for (int j = 0; j < 8; ++j)
#pragma unroll
        for (int r = 0; r < 4; ++r) o[j][r] = 0.f;
    float mi[2] = { -1e30f, -1e30f };
    float li[2] = { 0.f, 0.f };

    const int row0 = qb + w * 16 + (lane >> 2);

    for (int it = 0; it < nb; ++it) {
        if (it + 1 < nb) {
            asm volatile("cp.async.wait_group 1;");
        } else {
            asm volatile("cp.async.wait_group 0;");
        }
        __syncthreads();
        if (it + 2 < nb) load_kv((it + 2) % 3, (it + 2) * 64);

        const uint32_t kvb = sb + (it % 3) * KVSTG;
        const int j0 = it * 64;

        // ---- S = Q.K^T (2-term) ----
        float s[8][4];
#pragma unroll
        for (int j = 0; j < 8; ++j)
#pragma unroll
            for (int r = 0; r < 4; ++r) s[j][r] = 0.f;

#pragma unroll
        for (int kc = 0; kc < 4; ++kc) {
            uint32_t bh[4][4], bl[4][4];
#pragma unroll
            for (int j2 = 0; j2 < 4; ++j2) {
                uint32_t ba = kvb + j2 * (16 * FROW) + kb_off + kc * 32;
                LDM4(bh[j2], ba);
                LDM4(bl[j2], ba + FTILE);
            }
#pragma unroll
            for (int j = 0; j < 8; ++j) {
                const uint32_t* bhp = &bh[j >> 1][(j & 1) * 2];
                const uint32_t* blp = &bl[j >> 1][(j & 1) * 2];
                MMA_F16(s[j], qh[kc], bhp[0], bhp[1]);
                MMA_F16(s[j], qh[kc], blp[0], blp[1]);
            }
        }

        // ---- causal mask (only warps whose rows the block can cross) ----
        if (j0 + 63 > qb + w * 16) {
#pragma unroll
            for (int j = 0; j < 8; ++j)
#pragma unroll
                for (int r = 0; r < 4; ++r) {
                    int col = j0 + j * 8 + (lane & 3) * 2 + (r & 1);
                    int row = row0 + (r >> 1) * 8;
                    if (col > row) s[j][r] = -1e30f;
                }
        }

        // ---- online softmax ----
#pragma unroll
        for (int h2 = 0; h2 < 2; ++h2) {
            float mt = -1e30f;
#pragma unroll
            for (int j = 0; j < 8; ++j) {
                mt = fmaxf(mt, s[j][h2 * 2]);
                mt = fmaxf(mt, s[j][h2 * 2 + 1]);
            }
            mt = fmaxf(mt, __shfl_xor_sync(0xffffffffu, mt, 1));
            mt = fmaxf(mt, __shfl_xor_sync(0xffffffffu, mt, 2));
            float mnew  = fmaxf(mi[h2], mt);
            float alpha = __expf(mi[h2] - mnew);
            mi[h2] = mnew;
            float sum = 0.f;
#pragma unroll
            for (int j = 0; j < 8; ++j) {
                float p0 = __expf(s[j][h2 * 2]     - mnew);
                float p1 = __expf(s[j][h2 * 2 + 1] - mnew);
                s[j][h2 * 2]     = p0;
                s[j][h2 * 2 + 1] = p1;
                sum += p0 + p1;
                o[j][h2 * 2]     *= alpha;
                o[j][h2 * 2 + 1] *= alpha;
            }
            sum += __shfl_xor_sync(0xffffffffu, sum, 1);
            sum += __shfl_xor_sync(0xffffffffu, sum, 2);
            li[h2] = li[h2] * alpha + sum;
        }

        // ---- P fragments (hi only) ----
        uint32_t ph[4][4];
#pragma unroll
        for (int kc = 0; kc < 4; ++kc) {
            const int jt = 2 * kc;
            ph[kc][0] = pack_h2(s[jt][0],     s[jt][1]);
            ph[kc][1] = pack_h2(s[jt][2],     s[jt][3]);
            ph[kc][2] = pack_h2(s[jt + 1][0], s[jt + 1][1]);
            ph[kc][3] = pack_h2(s[jt + 1][2], s[jt + 1][3]);
        }

        // ---- O += P.V (2-term) ----
        const uint32_t vbase = kvb + 2 * FTILE;
#pragma unroll
        for (int kc = 0; kc < 4; ++kc) {
#pragma unroll
            for (int np = 0; np < 4; ++np) {
                uint32_t vh4[4], vl4[4];
                uint32_t va = vbase + kc * (16 * FROW) + v_off + np * 32;
                LDM4T(vh4, va);
                LDM4T(vl4, va + FTILE);
                MMA_F16(o[2 * np],     ph[kc], vh4[0], vh4[1]);
                MMA_F16(o[2 * np],     ph[kc], vl4[0], vl4[1]);
                MMA_F16(o[2 * np + 1], ph[kc], vh4[2], vh4[3]);
                MMA_F16(o[2 * np + 1], ph[kc], vl4[2], vl4[3]);
            }
        }
    }

    // ---- finalize: fp16 attention output (flat [b][s][h*64+d]) ----
    float inv0 = 1.0f / li[0];
    float inv1 = 1.0f / li[1];
#pragma unroll
    for (int j = 0; j < 8; ++j) {
        const int col = j * 8 + (lane & 3) * 2;
        size_t base0 = ((size_t)(b * SS + row0)) * DD + h * 64 + col;
        size_t base1 = ((size_t)(b * SS + row0 + 8)) * DD + h * 64 + col;
        *reinterpret_cast<__half2*>(OhP + base0) =
            __floats2half2_rn(o[j][0] * inv0, o[j][1] * inv0);
        *reinterpret_cast<__half2*>(OhP + base1) =
            __floats2half2_rn(o[j][2] * inv1, o[j][3] * inv1);
    }
}

// ---------------------------------------------------------------------------
// Host
// ---------------------------------------------------------------------------
extern "C" void kernel_launch(void* const* d_in, const int* in_sizes, int n_in,
                              void* d_out, int out_size)
{
    const float* x  = (const float*)d_in[0];
    const float* Wq = (const float*)d_in[1];
    const float* Wk = (const float*)d_in[2];
    const float* Wv = (const float*)d_in[3];
    const float* Wo = (const float*)d_in[4];
    float* out = (float*)d_out;

    __half *Xh, *Wqh, *Wql, *Wkh, *Wkl, *Wvh, *Wvl, *Woh, *Wol, *Oh;
    __half *Qbh, *Kbh, *Kbl, *Vbh, *Vbl;
    cudaGetSymbolAddress((void**)&Xh, g_Xh);
    cudaGetSymbolAddress((void**)&Wqh, g_Wqh);
    cudaGetSymbolAddress((void**)&Wql, g_Wql);
    cudaGetSymbolAddress((void**)&Wkh, g_Wkh);
    cudaGetSymbolAddress((void**)&Wkl, g_Wkl);
    cudaGetSymbolAddress((void**)&Wvh, g_Wvh);
    cudaGetSymbolAddress((void**)&Wvl, g_Wvl);
    cudaGetSymbolAddress((void**)&Woh, g_Woh);
    cudaGetSymbolAddress((void**)&Wol, g_Wol);
    cudaGetSymbolAddress((void**)&Oh, g_Oh);
    cudaGetSymbolAddress((void**)&Qbh, g_Qbh);
    cudaGetSymbolAddress((void**)&Kbh, g_Kbh);
    cudaGetSymbolAddress((void**)&Kbl, g_Kbl);
    cudaGetSymbolAddress((void**)&Vbh, g_Vbh);
    cudaGetSymbolAddress((void**)&Vbl, g_Vbl);

    const int SMEM_DYN = GSTG * STAGEB;   // 98304 -> 2 CTAs/SM
    cudaFuncSetAttribute(qkv_gemm, cudaFuncAttributeMaxDynamicSharedMemorySize, SMEM_DYN);
    cudaFuncSetAttribute(wo_gemm,  cudaFuncAttributeMaxDynamicSharedMemorySize, SMEM_DYN);
    cudaFuncSetAttribute(flash_mma, cudaFuncAttributeMaxDynamicSharedMemorySize, FSMEM);

    // single merged split launch (x hi-only, weights hi+lo)
    {
        SplitJobs jobs;
        jobs.in[0] = (const float4*)x;  jobs.hi[0] = (__half2*)Xh;  jobs.lo[0] = nullptr;
        jobs.in[1] = (const float4*)Wq; jobs.hi[1] = (__half2*)Wqh; jobs.lo[1] = (__half2*)Wql;
        jobs.in[2] = (const float4*)Wk; jobs.hi[2] = (__half2*)Wkh; jobs.lo[2] = (__half2*)Wkl;
        jobs.in[3] = (const float4*)Wv; jobs.hi[3] = (__half2*)Wvh; jobs.lo[3] = (__half2*)Wvl;
        jobs.in[4] = (const float4*)Wo; jobs.hi[4] = (__half2*)Woh; jobs.lo[4] = (__half2*)Wol;
        int n4s[5] = { BB * SS * DD / 4, HQ * DH * DD / 4, HKV * DH * DD / 4,
                       HKV * DH * DD / 4, DD * DD / 4 };
        int cum = 0;
        for (int k = 0; k < 5; ++k) { cum += n4s[k] / 256; jobs.blk_end[k] = cum; }
        split_all<<<cum, 256>>>(jobs);
    }

    // merged QKV projection (fused RoPE/scale/convert epilogue)
    qkv_gemm<<<dim3(24, 32), 128, SMEM_DYN>>>(Xh,
        Wqh, Wql, Wkh, Wkl, Wvh, Wvl,
        Qbh, Kbh, Kbl, Vbh, Vbl);

    // MMA flash attention (causal), outputs fp16
    flash_mma<<<dim3(SS / 128, HQ, BB), 256, FSMEM>>>(Qbh, Kbh, Kbl, Vbh, Vbl, Oh);

    // output projection -> fp32 result
    wo_gemm<<<dim3(16, 32), 128, SMEM_DYN>>>(Oh, Woh, Wol, out);
}

// round 12
// speedup vs baseline: 1.8814x; 1.0604x over previous
#include <cuda_runtime.h>
#include <cuda_fp16.h>
#include <math.h>
#include <stdint.h>

#define BB   2
#define SS   2048
#define DD   2048
#define HQ   32
#define HKV  8
#define DH   64
#define KDIM 2048

// ---------------------------------------------------------------------------
// Scratch (allocation-free rule: __device__ globals)
// fp16 scheme: A-side hi only; weights hi+lo; K hi+lo (softmax path); V hi only
// ---------------------------------------------------------------------------
__device__ __half g_Xh[(size_t)BB * SS * DD];
__device__ __half g_Wqh[(size_t)HQ * DH * DD];
__device__ __half g_Wql[(size_t)HQ * DH * DD];
__device__ __half g_Wkh[(size_t)HKV * DH * DD];
__device__ __half g_Wkl[(size_t)HKV * DH * DD];
__device__ __half g_Wvh[(size_t)HKV * DH * DD];
__device__ __half g_Wvl[(size_t)HKV * DH * DD];
__device__ __half g_Woh[(size_t)DD * DD];
__device__ __half g_Wol[(size_t)DD * DD];
__device__ __half g_Oh[(size_t)BB * SS * DD];

__device__ __half g_Qbh[(size_t)BB * HQ  * SS * DH];
__device__ __half g_Kbh[(size_t)BB * HKV * SS * DH];
__device__ __half g_Kbl[(size_t)BB * HKV * SS * DH];
__device__ __half g_Vbh[(size_t)BB * HKV * SS * DH];

// ---------------------------------------------------------------------------
// helpers
// ---------------------------------------------------------------------------
__device__ __forceinline__ uint32_t s2u(const void* p) {
    uint32_t r;
    asm("{ .reg .u64 t; cvta.to.shared.u64 t, %1; cvt.u32.u64 %0, t; }"
        : "=r"(r) : "l"(p));
    return r;
}

#define LDM4(r, addr)                                                         \
    asm volatile("ldmatrix.sync.aligned.m8n8.x4.shared.b16 {%0,%1,%2,%3}, [%4];" \
        : "=r"((r)[0]), "=r"((r)[1]), "=r"((r)[2]), "=r"((r)[3]) : "r"(addr))

#define LDM4T(r, addr)                                                        \
    asm volatile("ldmatrix.sync.aligned.m8n8.x4.trans.shared.b16 {%0,%1,%2,%3}, [%4];" \
        : "=r"((r)[0]), "=r"((r)[1]), "=r"((r)[2]), "=r"((r)[3]) : "r"(addr))

#define MMA_F16(c, a, b0, b1)                                                 \
    asm volatile("mma.sync.aligned.m16n8k16.row.col.f32.f16.f16.f32 "         \
        "{%0,%1,%2,%3}, {%4,%5,%6,%7}, {%8,%9}, {%0,%1,%2,%3};"               \
        : "+f"((c)[0]), "+f"((c)[1]), "+f"((c)[2]), "+f"((c)[3])              \
        : "r"((a)[0]), "r"((a)[1]), "r"((a)[2]), "r"((a)[3]), "r"(b0), "r"(b1))

#define CP_ASYNC16(dst, src)                                                  \
    asm volatile("cp.async.cg.shared.global [%0], [%1], 16;" :: "r"(dst), "l"(src))

__device__ __forceinline__ uint32_t pack_h2(float a, float b) {
    __half2 t = __floats2half2_rn(a, b);
    return *reinterpret_cast<uint32_t*>(&t);
}

__device__ __forceinline__ void split2_store(__half* H, __half* L,
                                             size_t base, float x1, float x2)
{
    __half h1 = __float2half_rn(x1);
    __half h2 = __float2half_rn(x2);
    __half l1 = __float2half_rn(x1 - __half2float(h1));
    __half l2 = __float2half_rn(x2 - __half2float(h2));
    *reinterpret_cast<__half2*>(H + base) = __half2(h1, h2);
    *reinterpret_cast<__half2*>(L + base) = __half2(l1, l2);
}

// ---------------------------------------------------------------------------
// merged input splits: job 0 (x) hi only; jobs 1-4 (weights) hi+lo
// ---------------------------------------------------------------------------
struct SplitJobs {
    const float4* in[5];
    __half2* hi[5];
    __half2* lo[5];
    int blk_end[5];
};

__global__ void split_all(SplitJobs jobs)
{
    int bx = blockIdx.x;
    int job = 0;
#pragma unroll
    for (int k = 0; k < 5; ++k)
        if (bx >= jobs.blk_end[k]) job = k + 1;
    int blk0 = (job == 0) ? 0 : jobs.blk_end[job - 1];
    int i = (bx - blk0) * blockDim.x + threadIdx.x;

    float4 a = jobs.in[job][i];
    __half h0 = __float2half_rn(a.x);
    __half h1 = __float2half_rn(a.y);
    __half h2 = __float2half_rn(a.z);
    __half h3 = __float2half_rn(a.w);
    jobs.hi[job][2 * i + 0] = __half2(h0, h1);
    jobs.hi[job][2 * i + 1] = __half2(h2, h3);
    if (jobs.lo[job]) {
        __half l0 = __float2half_rn(a.x - __half2float(h0));
        __half l1 = __float2half_rn(a.y - __half2float(h1));
        __half l2 = __float2half_rn(a.z - __half2float(h2));
        __half l3 = __float2half_rn(a.w - __half2float(h3));
        jobs.lo[job][2 * i + 0] = __half2(l0, l1);
        jobs.lo[job][2 * i + 1] = __half2(l2, l3);
    }
}

// ---------------------------------------------------------------------------
// core 2-term fp16 MMA loop (CTA 128x128x2048)
// 4 warps, warp tile 64x64. Matrices per stage: Ah, Bh, Bl (24KB).
// XOR-swizzled smem (64B rows), 4-stage ring, 1 sync/iter, 96KB -> 2 CTAs/SM.
// ---------------------------------------------------------------------------
#define MATB   8192                 // 128 rows * 64 B
#define STAGEB 24576                // 3 * MATB
#define GSTG   4
#define KITERS (KDIM / 32)

struct GemmCore {
    float c[4][8][4];
};

__device__ __forceinline__ void gemm_mainloop(
    uint32_t sb, int tid, int lane, int wm, int wn,
    const __half* Ah_g,
    const __half* Bh_g, const __half* Bl_g,
    int m0, int n0, GemmCore& g)
{
#pragma unroll
    for (int i = 0; i < 4; ++i)
#pragma unroll
        for (int j = 0; j < 8; ++j)
#pragma unroll
            for (int r = 0; r < 4; ++r) g.c[i][j][r] = 0.f;

    const int a_row = wm * 64 + (lane & 15);
    const uint32_t a_base = (uint32_t)a_row * 64;
    const uint32_t a_swz  = (uint32_t)(((lane >> 4) ^ ((a_row >> 1) & 3)) << 4);

    const int b_row = wn * 64 + (lane >> 4) * 8 + (lane & 7);
    const uint32_t b_base = (uint32_t)b_row * 64;
    const uint32_t b_swz  = (uint32_t)((((lane >> 3) & 1) ^ ((b_row >> 1) & 3)) << 4);

    const __half* srcs[3] = { Ah_g, Bh_g, Bl_g };
    const int rowbase[3] = { m0, n0, n0 };

    auto load_stage = [&](int s, int k0) {
#pragma unroll
        for (int i = 0; i < 12; ++i) {
            const int idx = tid + 128 * i;
            const int mat = idx >> 9;
            const int rem = idx & 511;
            const int row = rem >> 2;
            const int seg = rem & 3;
            uint32_t d = sb + s * STAGEB + mat * MATB + row * 64 +
                         ((seg ^ ((row >> 1) & 3)) << 4);
            const __half* p =
                srcs[mat] + (size_t)(rowbase[mat] + row) * KDIM + k0 + seg * 8;
            CP_ASYNC16(d, p);
        }
        asm volatile("cp.async.commit_group;");
    };

    load_stage(0, 0);
    load_stage(1, 32);
    load_stage(2, 64);

    for (int it = 0; it < KITERS; ++it) {
        if (it + 1 < KITERS) {
            asm volatile("cp.async.wait_group 2;");
        } else {
            asm volatile("cp.async.wait_group 0;");
        }
        __syncthreads();
        if (it + 3 < KITERS) {
            load_stage((it + 3) % GSTG, (it + 3) * 32);
        }

        const uint32_t st = sb + (it % GSTG) * STAGEB;
#pragma unroll
        for (int kk = 0; kk < 2; ++kk) {
            const uint32_t ksw = (uint32_t)(kk << 5);
            uint32_t bh[4][4], bl[4][4];
#pragma unroll
            for (int j2 = 0; j2 < 4; ++j2) {
                uint32_t ba = st + MATB + b_base + j2 * 1024 + (b_swz ^ ksw);
                LDM4(bh[j2], ba);
                LDM4(bl[j2], ba + MATB);
            }
#pragma unroll
            for (int i = 0; i < 4; ++i) {
                uint32_t ah[4];
                LDM4(ah, st + a_base + i * 1024 + (a_swz ^ ksw));
#pragma unroll
                for (int j = 0; j < 8; ++j) {
                    const uint32_t* bhp = &bh[j >> 1][(j & 1) * 2];
                    const uint32_t* blp = &bl[j >> 1][(j & 1) * 2];
                    MMA_F16(g.c[i][j], ah, bhp[0], bhp[1]);
                    MMA_F16(g.c[i][j], ah, blp[0], blp[1]);
                }
            }
        }
    }
}

// ---------------------------------------------------------------------------
// merged QKV projection: grid (24, 32), 128 threads
// Q -> hi only (rope, 1/8); K -> hi+lo (rope); V -> hi only
// ---------------------------------------------------------------------------
__global__ __launch_bounds__(128, 2)
void qkv_gemm(const __half* __restrict__ Xh_g,
              const __half* __restrict__ Wqh_g, const __half* __restrict__ Wql_g,
              const __half* __restrict__ Wkh_g, const __half* __restrict__ Wkl_g,
              const __half* __restrict__ Wvh_g, const __half* __restrict__ Wvl_g,
              __half* __restrict__ Qh,
              __half* __restrict__ Kh, __half* __restrict__ Kl,
              __half* __restrict__ Vh)
{
    extern __shared__ __align__(128) char smem[];
    const uint32_t sb = s2u(smem);

    const int tid  = threadIdx.x;
    const int lane = tid & 31;
    const int w    = tid >> 5;
    const int wm   = w & 1;
    const int wn   = w >> 1;
    const int bx   = blockIdx.x;
    const int m0   = blockIdx.y * 128;

    const __half *Bh_g, *Bl_g;
    __half *dH, *dL;
    int n0, Hn;
    bool rope;
    float scale;
    if (bx < 16) {
        Bh_g = Wqh_g; Bl_g = Wql_g; dH = Qh; dL = nullptr;
        n0 = bx * 128; Hn = HQ; rope = true; scale = 0.125f;
    } else if (bx < 20) {
        Bh_g = Wkh_g; Bl_g = Wkl_g; dH = Kh; dL = Kl;
        n0 = (bx - 16) * 128; Hn = HKV; rope = true; scale = 1.0f;
    } else {
        Bh_g = Wvh_g; Bl_g = Wvl_g; dH = Vh; dL = nullptr;
        n0 = (bx - 20) * 128; Hn = HKV; rope = false; scale = 1.0f;
    }

    GemmCore g;
    gemm_mainloop(sb, tid, lane, wm, wn, Xh_g, Bh_g, Bl_g, m0, n0, g);

#pragma unroll
    for (int i = 0; i < 4; ++i) {
        const int r0 = m0 + wm * 64 + i * 16 + (lane >> 2);
#pragma unroll
        for (int j = 0; j < 8; ++j) {
            const int col = n0 + wn * 64 + j * 8 + (lane & 3) * 2;
#pragma unroll
            for (int half = 0; half < 2; ++half) {
                const int row = r0 + half * 8;
                float x1 = g.c[i][j][half * 2];
                float x2 = g.c[i][j][half * 2 + 1];
                const int bidx = row >> 11;
                const int sRow = row & (SS - 1);
                const int hh = col >> 6, d0 = col & 63;
                size_t base = ((((size_t)bidx * Hn + hh) * SS + sRow) << 6) + d0;
                if (rope) {
                    float inv = exp2f(-(float)d0 * (13.287712379549449f / 64.0f));
                    float sn, cs;
                    sincosf((float)sRow * inv, &sn, &cs);
                    float y1 = x1 * cs - x2 * sn;
                    float y2 = x1 * sn + x2 * cs;
                    x1 = y1 * scale;
                    x2 = y2 * scale;
                }
                if (dL) {
                    split2_store(dH, dL, base, x1, x2);
                } else {
                    *reinterpret_cast<__half2*>(dH + base) =
                        __floats2half2_rn(x1, x2);
                }
            }
        }
    }
}

// ---------------------------------------------------------------------------
// output projection: fp32 flat result, 128 threads
// ---------------------------------------------------------------------------
__global__ __launch_bounds__(128, 2)
void wo_gemm(const __half* __restrict__ Ah_g,
             const __half* __restrict__ Bh_g,
             const __half* __restrict__ Bl_g,
             float* __restrict__ dst)
{
    extern __shared__ __align__(128) char smem[];
    const uint32_t sb = s2u(smem);

    const int tid  = threadIdx.x;
    const int lane = tid & 31;
    const int w    = tid >> 5;
    const int wm   = w & 1;
    const int wn   = w >> 1;
    const int m0   = blockIdx.y * 128;
    const int n0   = blockIdx.x * 128;

    GemmCore g;
    gemm_mainloop(sb, tid, lane, wm, wn, Ah_g, Bh_g, Bl_g, m0, n0, g);

#pragma unroll
    for (int i = 0; i < 4; ++i) {
        const int r0 = m0 + wm * 64 + i * 16 + (lane >> 2);
#pragma unroll
        for (int j = 0; j < 8; ++j) {
            const int col = n0 + wn * 64 + j * 8 + (lane & 3) * 2;
#pragma unroll
            for (int half = 0; half < 2; ++half) {
                const int row = r0 + half * 8;
                *reinterpret_cast<float2*>(dst + (size_t)row * DD + col) =
                    make_float2(g.c[i][j][half * 2], g.c[i][j][half * 2 + 1]);
            }
        }
    }
}

// ---------------------------------------------------------------------------
// MMA flash attention (causal, GQA): BM=128 (8 warps x 16 rows), BN=64, Dh=64
// fp16: Q hi; K hi+lo (2-term QK); V hi (1-term PV).
// 4-stage KV ring of 27KB slots {Kh,Kl,Vh}; Q staged through slot 0.
// smem 110592 -> 2 CTAs/SM; __launch_bounds__(256,2).
// ---------------------------------------------------------------------------
#define FROW   144
#define QTILE  18432               // 128 rows * 144 B (Q hi)
#define FTILE  9216                // 64 rows * 144 B (per matrix)
#define KVSTG  27648               // 3 * FTILE (Kh,Kl,Vh)
#define FSTG   4
#define FSMEM  (FSTG * KVSTG)      // 110592

__global__ __launch_bounds__(256, 2)
void flash_mma(const __half* __restrict__ Qh_g,
               const __half* __restrict__ Kh_g,
               const __half* __restrict__ Kl_g,
               const __half* __restrict__ Vh_g,
               __half* __restrict__ OhP)
{
    extern __shared__ __align__(128) char fsm[];
    const uint32_t sb = s2u(fsm);

    const int tid  = threadIdx.x;
    const int lane = tid & 31;
    const int w    = tid >> 5;
    const int qi   = gridDim.x - 1 - blockIdx.x;   // longest CTAs first
    const int qb   = qi * 128;
    const int h    = blockIdx.y;
    const int b    = blockIdx.z;
    const int kh   = h >> 2;

    const size_t qoff  = (((size_t)b * HQ + h) * SS + qb) * 64;
    const size_t kvrow = ((size_t)b * HKV + kh) * SS;

    const uint32_t a_off =
        (uint32_t)((w * 16 + (lane & 15)) * FROW + (lane >> 4) * 16);
    const uint32_t kb_off =
        (uint32_t)(((lane >> 4) * 8 + (lane & 7)) * FROW + ((lane >> 3) & 1) * 16);
    const uint32_t v_off =
        (uint32_t)((lane & 15) * FROW + (lane >> 4) * 16);

    // ---- prologue: Q hi through slots 0-1 region (QTILE = 2 ring slots area ok) ----
#pragma unroll
    for (int i = 0; i < 4; ++i) {
        int idx = tid + 256 * i;
        int row = idx >> 3;
        int seg = idx & 7;
        uint32_t d = sb + row * FROW + seg * 16;
        CP_ASYNC16(d, Qh_g + qoff + row * 64 + seg * 8);
    }
    asm volatile("cp.async.commit_group;");
    asm volatile("cp.async.wait_group 0;");
    __syncthreads();

    uint32_t qh[4][4];
#pragma unroll
    for (int kc = 0; kc < 4; ++kc)
        LDM4(qh[kc], sb + a_off + kc * 32);
    __syncthreads();   // all warps own Q frags before slots are recycled

    auto load_kv = [&](int s, int j0) {
        const __half* srcs[3] = { Kh_g, Kl_g, Vh_g };
        const size_t off = (kvrow + j0) * 64;
#pragma unroll
        for (int i = 0; i < 6; ++i) {
            int idx = tid + 256 * i;
            int mat = idx >> 9;
            int rem = idx & 511;
            int row = rem >> 3;
            int seg = rem & 7;
            uint32_t d = sb + s * KVSTG + mat * FTILE + row * FROW + seg * 16;
            CP_ASYNC16(d, srcs[mat] + off + row * 64 + seg * 8);
        }
        asm volatile("cp.async.commit_group;");
    };

    const int nb = qb / 64 + 2;
    load_kv(0, 0);
    if (nb > 1) load_kv(1, 64);

    float o[8][4];
#pragma unroll
    for (int j = 0; j < 8; ++j)
#pragma unroll
        for (int r = 0; r < 4; ++r) o[j][r] = 0.f;
    float mi[2] = { -1e30f, -1e30f };
    float li[2] = { 0.f, 0.f };

    const int row0 = qb + w * 16 + (lane >> 2);

    for (int it = 0; it < nb; ++it) {
        if (it + 1 < nb) {
            asm volatile("cp.async.wait_group 1;");
        } else {
            asm volatile("cp.async.wait_group 0;");
        }
        __syncthreads();
        if (it + 2 < nb) load_kv((it + 2) % FSTG, (it + 2) * 64);

        const uint32_t kvb = sb + (it % FSTG) * KVSTG;
        const int j0 = it * 64;

        // ---- S = Q.K^T (2-term) ----
        float s[8][4];
#pragma unroll
        for (int j = 0; j < 8; ++j)
#pragma unroll
            for (int r = 0; r < 4; ++r) s[j][r] = 0.f;

#pragma unroll
        for (int kc = 0; kc < 4; ++kc) {
            uint32_t bh[4][4], bl[4][4];
#pragma unroll
            for (int j2 = 0; j2 < 4; ++j2) {
                uint32_t ba = kvb + j2 * (16 * FROW) + kb_off + kc * 32;
                LDM4(bh[j2], ba);
                LDM4(bl[j2], ba + FTILE);
            }
#pragma unroll
            for (int j = 0; j < 8; ++j) {
                const uint32_t* bhp = &bh[j >> 1][(j & 1) * 2];
                const uint32_t* blp = &bl[j >> 1][(j & 1) * 2];
                MMA_F16(s[j], qh[kc], bhp[0], bhp[1]);
                MMA_F16(s[j], qh[kc], blp[0], blp[1]);
            }
        }

        // ---- causal mask (only warps whose rows the block can cross) ----
        if (j0 + 63 > qb + w * 16) {
#pragma unroll
            for (int j = 0; j < 8; ++j)
#pragma unroll
                for (int r = 0; r < 4; ++r) {
                    int col = j0 + j * 8 + (lane & 3) * 2 + (r & 1);
                    int row = row0 + (r >> 1) * 8;
                    if (col > row) s[j][r] = -1e30f;
                }
        }

        // ---- online softmax ----
#pragma unroll
        for (int h2 = 0; h2 < 2; ++h2) {
            float mt = -1e30f;
#pragma unroll
            for (int j = 0; j < 8; ++j) {
                mt = fmaxf(mt, s[j][h2 * 2]);
                mt = fmaxf(mt, s[j][h2 * 2 + 1]);
            }
            mt = fmaxf(mt, __shfl_xor_sync(0xffffffffu, mt, 1));
            mt = fmaxf(mt, __shfl_xor_sync(0xffffffffu, mt, 2));
            float mnew  = fmaxf(mi[h2], mt);
            float alpha = __expf(mi[h2] - mnew);
            mi[h2] = mnew;
            float sum = 0.f;
#pragma unroll
            for (int j = 0; j < 8; ++j) {
                float p0 = __expf(s[j][h2 * 2]     - mnew);
                float p1 = __expf(s[j][h2 * 2 + 1] - mnew);
                s[j][h2 * 2]     = p0;
                s[j][h2 * 2 + 1] = p1;
                sum += p0 + p1;
                o[j][h2 * 2]     *= alpha;
                o[j][h2 * 2 + 1] *= alpha;
            }
            sum += __shfl_xor_sync(0xffffffffu, sum, 1);
            sum += __shfl_xor_sync(0xffffffffu, sum, 2);
            li[h2] = li[h2] * alpha + sum;
        }

        // ---- P fragments (hi only) ----
        uint32_t ph[4][4];
#pragma unroll
        for (int kc = 0; kc < 4; ++kc) {
            const int jt = 2 * kc;
            ph[kc][0] = pack_h2(s[jt][0],     s[jt][1]);
            ph[kc][1] = pack_h2(s[jt][2],     s[jt][3]);
            ph[kc][2] = pack_h2(s[jt + 1][0], s[jt + 1][1]);
            ph[kc][3] = pack_h2(s[jt + 1][2], s[jt + 1][3]);
        }

        // ---- O += P.V (1-term on V) ----
        const uint32_t vbase = kvb + 2 * FTILE;
#pragma unroll
        for (int kc = 0; kc < 4; ++kc) {
#pragma unroll
            for (int np = 0; np < 4; ++np) {
                uint32_t vh4[4];
                uint32_t va = vbase + kc * (16 * FROW) + v_off + np * 32;
                LDM4T(vh4, va);
                MMA_F16(o[2 * np],     ph[kc], vh4[0], vh4[1]);
                MMA_F16(o[2 * np + 1], ph[kc], vh4[2], vh4[3]);
            }
        }
    }

    // ---- finalize: fp16 attention output (flat [b][s][h*64+d]) ----
    float inv0 = 1.0f / li[0];
    float inv1 = 1.0f / li[1];
#pragma unroll
    for (int j = 0; j < 8; ++j) {
        const int col = j * 8 + (lane & 3) * 2;
        size_t base0 = ((size_t)(b * SS + row0)) * DD + h * 64 + col;
        size_t base1 = ((size_t)(b * SS + row0 + 8)) * DD + h * 64 + col;
        *reinterpret_cast<__half2*>(OhP + base0) =
            __floats2half2_rn(o[j][0] * inv0, o[j][1] * inv0);
        *reinterpret_cast<__half2*>(OhP + base1) =
            __floats2half2_rn(o[j][2] * inv1, o[j][3] * inv1);
    }
}

// ---------------------------------------------------------------------------
// Host
// ---------------------------------------------------------------------------
extern "C" void kernel_launch(void* const* d_in, const int* in_sizes, int n_in,
                              void* d_out, int out_size)
{
    const float* x  = (const float*)d_in[0];
    const float* Wq = (const float*)d_in[1];
    const float* Wk = (const float*)d_in[2];
    const float* Wv = (const float*)d_in[3];
    const float* Wo = (const float*)d_in[4];
    float* out = (float*)d_out;

    __half *Xh, *Wqh, *Wql, *Wkh, *Wkl, *Wvh, *Wvl, *Woh, *Wol, *Oh;
    __half *Qbh, *Kbh, *Kbl, *Vbh;
    cudaGetSymbolAddress((void**)&Xh, g_Xh);
    cudaGetSymbolAddress((void**)&Wqh, g_Wqh);
    cudaGetSymbolAddress((void**)&Wql, g_Wql);
    cudaGetSymbolAddress((void**)&Wkh, g_Wkh);
    cudaGetSymbolAddress((void**)&Wkl, g_Wkl);
    cudaGetSymbolAddress((void**)&Wvh, g_Wvh);
    cudaGetSymbolAddress((void**)&Wvl, g_Wvl);
    cudaGetSymbolAddress((void**)&Woh, g_Woh);
    cudaGetSymbolAddress((void**)&Wol, g_Wol);
    cudaGetSymbolAddress((void**)&Oh, g_Oh);
    cudaGetSymbolAddress((void**)&Qbh, g_Qbh);
    cudaGetSymbolAddress((void**)&Kbh, g_Kbh);
    cudaGetSymbolAddress((void**)&Kbl, g_Kbl);
    cudaGetSymbolAddress((void**)&Vbh, g_Vbh);

    const int SMEM_DYN = GSTG * STAGEB;   // 98304 -> 2 CTAs/SM
    cudaFuncSetAttribute(qkv_gemm, cudaFuncAttributeMaxDynamicSharedMemorySize, SMEM_DYN);
    cudaFuncSetAttribute(wo_gemm,  cudaFuncAttributeMaxDynamicSharedMemorySize, SMEM_DYN);
    cudaFuncSetAttribute(flash_mma, cudaFuncAttributeMaxDynamicSharedMemorySize, FSMEM);

    // single merged split launch (x hi-only, weights hi+lo)
    {
        SplitJobs jobs;
        jobs.in[0] = (const float4*)x;  jobs.hi[0] = (__half2*)Xh;  jobs.lo[0] = nullptr;
        jobs.in[1] = (const float4*)Wq; jobs.hi[1] = (__half2*)Wqh; jobs.lo[1] = (__half2*)Wql;
        jobs.in[2] = (const float4*)Wk; jobs.hi[2] = (__half2*)Wkh; jobs.lo[2] = (__half2*)Wkl;
        jobs.in[3] = (const float4*)Wv; jobs.hi[3] = (__half2*)Wvh; jobs.lo[3] = (__half2*)Wvl;
        jobs.in[4] = (const float4*)Wo; jobs.hi[4] = (__half2*)Woh; jobs.lo[4] = (__half2*)Wol;
        int n4s[5] = { BB * SS * DD / 4, HQ * DH * DD / 4, HKV * DH * DD / 4,
                       HKV * DH * DD / 4, DD * DD / 4 };
        int cum = 0;
        for (int k = 0; k < 5; ++k) { cum += n4s[k] / 256; jobs.blk_end[k] = cum; }
        split_all<<<cum, 256>>>(jobs);
    }

    // merged QKV projection (fused RoPE/scale/convert epilogue)
    qkv_gemm<<<dim3(24, 32), 128, SMEM_DYN>>>(Xh,
        Wqh, Wql, Wkh, Wkl, Wvh, Wvl,
        Qbh, Kbh, Kbl, Vbh);

    // MMA flash attention (causal), outputs fp16
    flash_mma<<<dim3(SS / 128, HQ, BB), 256, FSMEM>>>(Qbh, Kbh, Kbl, Vbh, Oh);

    // output projection -> fp32 result
    wo_gemm<<<dim3(16, 32), 128, SMEM_DYN>>>(Oh, Woh, Wol, out);
}

// round 13
// speedup vs baseline: 2.4540x; 1.3043x over previous
#include <cuda_runtime.h>
#include <cuda_fp16.h>
#include <math.h>
#include <stdint.h>

#define BB   2
#define SS   2048
#define DD   2048
#define HQ   32
#define HKV  8
#define DH   64
#define KDIM 2048

// ---------------------------------------------------------------------------
// Scratch (allocation-free rule: __device__ globals)
// fp16: K path 2-term (softmax-amplified); Q/V/Wo paths 1-term (fp16-storage
// error already dominates there).
// ---------------------------------------------------------------------------
__device__ __half g_Xh[(size_t)BB * SS * DD];
__device__ __half g_Wqh[(size_t)HQ * DH * DD];
__device__ __half g_Wkh[(size_t)HKV * DH * DD];
__device__ __half g_Wkl[(size_t)HKV * DH * DD];
__device__ __half g_Wvh[(size_t)HKV * DH * DD];
__device__ __half g_Woh[(size_t)DD * DD];
__device__ __half g_Oh[(size_t)BB * SS * DD];

__device__ __half g_Qbh[(size_t)BB * HQ  * SS * DH];
__device__ __half g_Kbh[(size_t)BB * HKV * SS * DH];
__device__ __half g_Kbl[(size_t)BB * HKV * SS * DH];
__device__ __half g_Vbh[(size_t)BB * HKV * SS * DH];

// ---------------------------------------------------------------------------
// helpers
// ---------------------------------------------------------------------------
__device__ __forceinline__ uint32_t s2u(const void* p) {
    uint32_t r;
    asm("{ .reg .u64 t; cvta.to.shared.u64 t, %1; cvt.u32.u64 %0, t; }"
        : "=r"(r) : "l"(p));
    return r;
}

#define LDM4(r, addr)                                                         \
    asm volatile("ldmatrix.sync.aligned.m8n8.x4.shared.b16 {%0,%1,%2,%3}, [%4];" \
        : "=r"((r)[0]), "=r"((r)[1]), "=r"((r)[2]), "=r"((r)[3]) : "r"(addr))

#define LDM4T(r, addr)                                                        \
    asm volatile("ldmatrix.sync.aligned.m8n8.x4.trans.shared.b16 {%0,%1,%2,%3}, [%4];" \
        : "=r"((r)[0]), "=r"((r)[1]), "=r"((r)[2]), "=r"((r)[3]) : "r"(addr))

#define MMA_F16(c, a, b0, b1)                                                 \
    asm volatile("mma.sync.aligned.m16n8k16.row.col.f32.f16.f16.f32 "         \
        "{%0,%1,%2,%3}, {%4,%5,%6,%7}, {%8,%9}, {%0,%1,%2,%3};"               \
        : "+f"((c)[0]), "+f"((c)[1]), "+f"((c)[2]), "+f"((c)[3])              \
        : "r"((a)[0]), "r"((a)[1]), "r"((a)[2]), "r"((a)[3]), "r"(b0), "r"(b1))

#define CP_ASYNC16(dst, src)                                                  \
    asm volatile("cp.async.cg.shared.global [%0], [%1], 16;" :: "r"(dst), "l"(src))

__device__ __forceinline__ uint32_t pack_h2(float a, float b) {
    __half2 t = __floats2half2_rn(a, b);
    return *reinterpret_cast<uint32_t*>(&t);
}

__device__ __forceinline__ void split2_store(__half* H, __half* L,
                                             size_t base, float x1, float x2)
{
    __half h1 = __float2half_rn(x1);
    __half h2 = __float2half_rn(x2);
    __half l1 = __float2half_rn(x1 - __half2float(h1));
    __half l2 = __float2half_rn(x2 - __half2float(h2));
    *reinterpret_cast<__half2*>(H + base) = __half2(h1, h2);
    *reinterpret_cast<__half2*>(L + base) = __half2(l1, l2);
}

// ---------------------------------------------------------------------------
// merged input splits: hi always; lo only where non-null (Wk)
// ---------------------------------------------------------------------------
struct SplitJobs {
    const float4* in[5];
    __half2* hi[5];
    __half2* lo[5];
    int blk_end[5];
};

__global__ void split_all(SplitJobs jobs)
{
    int bx = blockIdx.x;
    int job = 0;
#pragma unroll
    for (int k = 0; k < 5; ++k)
        if (bx >= jobs.blk_end[k]) job = k + 1;
    int blk0 = (job == 0) ? 0 : jobs.blk_end[job - 1];
    int i = (bx - blk0) * blockDim.x + threadIdx.x;

    float4 a = jobs.in[job][i];
    __half h0 = __float2half_rn(a.x);
    __half h1 = __float2half_rn(a.y);
    __half h2 = __float2half_rn(a.z);
    __half h3 = __float2half_rn(a.w);
    jobs.hi[job][2 * i + 0] = __half2(h0, h1);
    jobs.hi[job][2 * i + 1] = __half2(h2, h3);
    if (jobs.lo[job]) {
        __half l0 = __float2half_rn(a.x - __half2float(h0));
        __half l1 = __float2half_rn(a.y - __half2float(h1));
        __half l2 = __float2half_rn(a.z - __half2float(h2));
        __half l3 = __float2half_rn(a.w - __half2float(h3));
        jobs.lo[job][2 * i + 0] = __half2(l0, l1);
        jobs.lo[job][2 * i + 1] = __half2(l2, l3);
    }
}

// ---------------------------------------------------------------------------
// core fp16 MMA loop (CTA 128x128x2048), TERMS = 1 or 2 (B-side lo term)
// 4 warps, warp tile 64x64. Stage layout [Ah][Bh][(Bl)], fixed 24KB pitch.
// XOR-swizzled smem (64B rows), 4-stage ring, 1 sync/iter, 96KB -> 2 CTAs/SM.
// ---------------------------------------------------------------------------
#define MATB   8192                 // 128 rows * 64 B
#define STAGEB 24576                // fixed pitch (3 * MATB)
#define GSTG   4
#define KITERS (KDIM / 32)

struct GemmCore {
    float c[4][8][4];
};

template <int TERMS>
__device__ __forceinline__ void gemm_mainloop(
    uint32_t sb, int tid, int lane, int wm, int wn,
    const __half* Ah_g,
    const __half* Bh_g, const __half* Bl_g,
    int m0, int n0, GemmCore& g)
{
#pragma unroll
    for (int i = 0; i < 4; ++i)
#pragma unroll
        for (int j = 0; j < 8; ++j)
#pragma unroll
            for (int r = 0; r < 4; ++r) g.c[i][j][r] = 0.f;

    const int a_row = wm * 64 + (lane & 15);
    const uint32_t a_base = (uint32_t)a_row * 64;
    const uint32_t a_swz  = (uint32_t)(((lane >> 4) ^ ((a_row >> 1) & 3)) << 4);

    const int b_row = wn * 64 + (lane >> 4) * 8 + (lane & 7);
    const uint32_t b_base = (uint32_t)b_row * 64;
    const uint32_t b_swz  = (uint32_t)((((lane >> 3) & 1) ^ ((b_row >> 1) & 3)) << 4);

    const __half* srcs[3] = { Ah_g, Bh_g, Bl_g };
    const int rowbase[3] = { m0, n0, n0 };
    const int NMAT = 1 + TERMS;

    auto load_stage = [&](int s, int k0) {
#pragma unroll
        for (int i = 0; i < 4 * NMAT; ++i) {
            const int idx = tid + 128 * i;
            const int mat = idx >> 9;
            const int rem = idx & 511;
            const int row = rem >> 2;
            const int seg = rem & 3;
            uint32_t d = sb + s * STAGEB + mat * MATB + row * 64 +
                         ((seg ^ ((row >> 1) & 3)) << 4);
            const __half* p =
                srcs[mat] + (size_t)(rowbase[mat] + row) * KDIM + k0 + seg * 8;
            CP_ASYNC16(d, p);
        }
        asm volatile("cp.async.commit_group;");
    };

    load_stage(0, 0);
    load_stage(1, 32);
    load_stage(2, 64);

    for (int it = 0; it < KITERS; ++it) {
        if (it + 1 < KITERS) {
            asm volatile("cp.async.wait_group 2;");
        } else {
            asm volatile("cp.async.wait_group 0;");
        }
        __syncthreads();
        if (it + 3 < KITERS) {
            load_stage((it + 3) % GSTG, (it + 3) * 32);
        }

        const uint32_t st = sb + (it % GSTG) * STAGEB;
#pragma unroll
        for (int kk = 0; kk < 2; ++kk) {
            const uint32_t ksw = (uint32_t)(kk << 5);
            uint32_t bh[4][4], bl[4][4];
#pragma unroll
            for (int j2 = 0; j2 < 4; ++j2) {
                uint32_t ba = st + MATB + b_base + j2 * 1024 + (b_swz ^ ksw);
                LDM4(bh[j2], ba);
                if (TERMS == 2) LDM4(bl[j2], ba + MATB);
            }
#pragma unroll
            for (int i = 0; i < 4; ++i) {
                uint32_t ah[4];
                LDM4(ah, st + a_base + i * 1024 + (a_swz ^ ksw));
#pragma unroll
                for (int j = 0; j < 8; ++j) {
                    const uint32_t* bhp = &bh[j >> 1][(j & 1) * 2];
                    MMA_F16(g.c[i][j], ah, bhp[0], bhp[1]);
                    if (TERMS == 2) {
                        const uint32_t* blp = &bl[j >> 1][(j & 1) * 2];
                        MMA_F16(g.c[i][j], ah, blp[0], blp[1]);
                    }
                }
            }
        }
    }
}

// ---------------------------------------------------------------------------
// merged QKV projection: grid (24, 32), 128 threads
// Q -> 1-term, rope, 1/8, hi out; K -> 2-term, rope, hi+lo out; V -> 1-term, hi
// ---------------------------------------------------------------------------
__global__ __launch_bounds__(128, 2)
void qkv_gemm(const __half* __restrict__ Xh_g,
              const __half* __restrict__ Wqh_g,
              const __half* __restrict__ Wkh_g, const __half* __restrict__ Wkl_g,
              const __half* __restrict__ Wvh_g,
              __half* __restrict__ Qh,
              __half* __restrict__ Kh, __half* __restrict__ Kl,
              __half* __restrict__ Vh)
{
    extern __shared__ __align__(128) char smem[];
    const uint32_t sb = s2u(smem);

    const int tid  = threadIdx.x;
    const int lane = tid & 31;
    const int w    = tid >> 5;
    const int wm   = w & 1;
    const int wn   = w >> 1;
    const int bx   = blockIdx.x;
    const int m0   = blockIdx.y * 128;

    const __half *Bh_g;
    __half *dH, *dL;
    int n0, Hn;
    bool rope;
    float scale;
    GemmCore g;

    if (bx < 16) {
        Bh_g = Wqh_g; dH = Qh; dL = nullptr;
        n0 = bx * 128; Hn = HQ; rope = true; scale = 0.125f;
        gemm_mainloop<1>(sb, tid, lane, wm, wn, Xh_g, Bh_g, nullptr, m0, n0, g);
    } else if (bx < 20) {
        Bh_g = Wkh_g; dH = Kh; dL = Kl;
        n0 = (bx - 16) * 128; Hn = HKV; rope = true; scale = 1.0f;
        gemm_mainloop<2>(sb, tid, lane, wm, wn, Xh_g, Bh_g, Wkl_g, m0, n0, g);
    } else {
        Bh_g = Wvh_g; dH = Vh; dL = nullptr;
        n0 = (bx - 20) * 128; Hn = HKV; rope = false; scale = 1.0f;
        gemm_mainloop<1>(sb, tid, lane, wm, wn, Xh_g, Bh_g, nullptr, m0, n0, g);
    }

#pragma unroll
    for (int i = 0; i < 4; ++i) {
        const int r0 = m0 + wm * 64 + i * 16 + (lane >> 2);
#pragma unroll
        for (int j = 0; j < 8; ++j) {
            const int col = n0 + wn * 64 + j * 8 + (lane & 3) * 2;
#pragma unroll
            for (int half = 0; half < 2; ++half) {
                const int row = r0 + half * 8;
                float x1 = g.c[i][j][half * 2];
                float x2 = g.c[i][j][half * 2 + 1];
                const int bidx = row >> 11;
                const int sRow = row & (SS - 1);
                const int hh = col >> 6, d0 = col & 63;
                size_t base = ((((size_t)bidx * Hn + hh) * SS + sRow) << 6) + d0;
                if (rope) {
                    float inv = exp2f(-(float)d0 * (13.287712379549449f / 64.0f));
                    float sn, cs;
                    sincosf((float)sRow * inv, &sn, &cs);
                    float y1 = x1 * cs - x2 * sn;
                    float y2 = x1 * sn + x2 * cs;
                    x1 = y1 * scale;
                    x2 = y2 * scale;
                }
                if (dL) {
                    split2_store(dH, dL, base, x1, x2);
                } else {
                    *reinterpret_cast<__half2*>(dH + base) =
                        __floats2half2_rn(x1, x2);
                }
            }
        }
    }
}

// ---------------------------------------------------------------------------
// output projection (1-term fp16): fp32 flat result, 128 threads
// ---------------------------------------------------------------------------
__global__ __launch_bounds__(128, 2)
void wo_gemm(const __half* __restrict__ Ah_g,
             const __half* __restrict__ Bh_g,
             float* __restrict__ dst)
{
    extern __shared__ __align__(128) char smem[];
    const uint32_t sb = s2u(smem);

    const int tid  = threadIdx.x;
    const int lane = tid & 31;
    const int w    = tid >> 5;
    const int wm   = w & 1;
    const int wn   = w >> 1;
    const int m0   = blockIdx.y * 128;
    const int n0   = blockIdx.x * 128;

    GemmCore g;
    gemm_mainloop<1>(sb, tid, lane, wm, wn, Ah_g, Bh_g, nullptr, m0, n0, g);

#pragma unroll
    for (int i = 0; i < 4; ++i) {
        const int r0 = m0 + wm * 64 + i * 16 + (lane >> 2);
#pragma unroll
        for (int j = 0; j < 8; ++j) {
            const int col = n0 + wn * 64 + j * 8 + (lane & 3) * 2;
#pragma unroll
            for (int half = 0; half < 2; ++half) {
                const int row = r0 + half * 8;
                *reinterpret_cast<float2*>(dst + (size_t)row * DD + col) =
                    make_float2(g.c[i][j][half * 2], g.c[i][j][half * 2 + 1]);
            }
        }
    }
}

// ---------------------------------------------------------------------------
// MMA flash attention (causal, GQA): BM=128 (8 warps x 16 rows), BN=64, Dh=64
// fp16: Q hi; K hi+lo (2-term QK); V hi (1-term PV).
// 4-stage KV ring of 27KB slots {Kh,Kl,Vh}; Q staged through slot 0.
// smem 110592 -> 2 CTAs/SM; __launch_bounds__(256,2).
// ---------------------------------------------------------------------------
#define FROW   144
#define FTILE  9216                // 64 rows * 144 B (per matrix)
#define KVSTG  27648               // 3 * FTILE (Kh,Kl,Vh)
#define FSTG   4
#define FSMEM  (FSTG * KVSTG)      // 110592

__global__ __launch_bounds__(256, 2)
void flash_mma(const __half* __restrict__ Qh_g,
               const __half* __restrict__ Kh_g,
               const __half* __restrict__ Kl_g,
               const __half* __restrict__ Vh_g,
               __half* __restrict__ OhP)
{
    extern __shared__ __align__(128) char fsm[];
    const uint32_t sb = s2u(fsm);

    const int tid  = threadIdx.x;
    const int lane = tid & 31;
    const int w    = tid >> 5;
    const int qi   = gridDim.x - 1 - blockIdx.x;   // longest CTAs first
    const int qb   = qi * 128;
    const int h    = blockIdx.y;
    const int b    = blockIdx.z;
    const int kh   = h >> 2;

    const size_t qoff  = (((size_t)b * HQ + h) * SS + qb) * 64;
    const size_t kvrow = ((size_t)b * HKV + kh) * SS;

    const uint32_t a_off =
        (uint32_t)((w * 16 + (lane & 15)) * FROW + (lane >> 4) * 16);
    const uint32_t kb_off =
        (uint32_t)(((lane >> 4) * 8 + (lane & 7)) * FROW + ((lane >> 3) & 1) * 16);
    const uint32_t v_off =
        (uint32_t)((lane & 15) * FROW + (lane >> 4) * 16);

    // ---- prologue: Q hi staged through ring slots ----
#pragma unroll
    for (int i = 0; i < 4; ++i) {
        int idx = tid + 256 * i;
        int row = idx >> 3;
        int seg = idx & 7;
        uint32_t d = sb + row * FROW + seg * 16;
        CP_ASYNC16(d, Qh_g + qoff + row * 64 + seg * 8);
    }
    asm volatile("cp.async.commit_group;");
    asm volatile("cp.async.wait_group 0;");
    __syncthreads();

    uint32_t qh[4][4];
#pragma unroll
    for (int kc = 0; kc < 4; ++kc)
        LDM4(qh[kc], sb + a_off + kc * 32);
    __syncthreads();   // all warps own Q frags before slots are recycled

    auto load_kv = [&](int s, int j0) {
        const __half* srcs[3] = { Kh_g, Kl_g, Vh_g };
        const size_t off = (kvrow + j0) * 64;
#pragma unroll
        for (int i = 0; i < 6; ++i) {
            int idx = tid + 256 * i;
            int mat = idx >> 9;
            int rem = idx & 511;
            int row = rem >> 3;
            int seg = rem & 7;
            uint32_t d = sb + s * KVSTG + mat * FTILE + row * FROW + seg * 16;
            CP_ASYNC16(d, srcs[mat] + off + row * 64 + seg * 8);
        }
        asm volatile("cp.async.commit_group;");
    };

    const int nb = qb / 64 + 2;
    load_kv(0, 0);
    if (nb > 1) load_kv(1, 64);

    float o[8][4];
#pragma unroll
    for (int j = 0; j < 8; ++j)
#pragma unroll
        for (int r = 0; r < 4; ++r) o[j][r] = 0.f;
    float mi[2] = { -1e30f, -1e30f };
    float li[2] = { 0.f, 0.f };

    const int row0 = qb + w * 16 + (lane >> 2);

    for (int it = 0; it < nb; ++it) {
        if (it + 1 < nb) {
            asm volatile("cp.async.wait_group 1;");
        } else {
            asm volatile("cp.async.wait_group 0;");
        }
        __syncthreads();
        if (it + 2 < nb) load_kv((it + 2) % FSTG, (it + 2) * 64);

        const uint32_t kvb = sb + (it % FSTG) * KVSTG;
        const int j0 = it * 64;

        // ---- S = Q.K^T (2-term) ----
        float s[8][4];
#pragma unroll
        for (int j = 0; j < 8; ++j)
#pragma unroll
            for (int r = 0; r < 4; ++r) s[j][r] = 0.f;

#pragma unroll
        for (int kc = 0; kc < 4; ++kc) {
            uint32_t bh[4][4], bl[4][4];
#pragma unroll
            for (int j2 = 0; j2 < 4; ++j2) {
                uint32_t ba = kvb + j2 * (16 * FROW) + kb_off + kc * 32;
                LDM4(bh[j2], ba);
                LDM4(bl[j2], ba + FTILE);
            }
#pragma unroll
            for (int j = 0; j < 8; ++j) {
                const uint32_t* bhp = &bh[j >> 1][(j & 1) * 2];
                const uint32_t* blp = &bl[j >> 1][(j & 1) * 2];
                MMA_F16(s[j], qh[kc], bhp[0], bhp[1]);
                MMA_F16(s[j], qh[kc], blp[0], blp[1]);
            }
        }

        // ---- causal mask ----
        if (j0 + 63 > qb + w * 16) {
#pragma unroll
            for (int j = 0; j < 8; ++j)
#pragma unroll
                for (int r = 0; r < 4; ++r) {
                    int col = j0 + j * 8 + (lane & 3) * 2 + (r & 1);
                    int row = row0 + (r >> 1) * 8;
                    if (col > row) s[j][r] = -1e30f;
                }
        }

        // ---- online softmax ----
#pragma unroll
        for (int h2 = 0; h2 < 2; ++h2) {
            float mt = -1e30f;
#pragma unroll
            for (int j = 0; j < 8; ++j) {
                mt = fmaxf(mt, s[j][h2 * 2]);
                mt = fmaxf(mt, s[j][h2 * 2 + 1]);
            }
            mt = fmaxf(mt, __shfl_xor_sync(0xffffffffu, mt, 1));
            mt = fmaxf(mt, __shfl_xor_sync(0xffffffffu, mt, 2));
            float mnew  = fmaxf(mi[h2], mt);
            float alpha = __expf(mi[h2] - mnew);
            mi[h2] = mnew;
            float sum = 0.f;
#pragma unroll
            for (int j = 0; j < 8; ++j) {
                float p0 = __expf(s[j][h2 * 2]     - mnew);
                float p1 = __expf(s[j][h2 * 2 + 1] - mnew);
                s[j][h2 * 2]     = p0;
                s[j][h2 * 2 + 1] = p1;
                sum += p0 + p1;
                o[j][h2 * 2]     *= alpha;
                o[j][h2 * 2 + 1] *= alpha;
            }
            sum += __shfl_xor_sync(0xffffffffu, sum, 1);
            sum += __shfl_xor_sync(0xffffffffu, sum, 2);
            li[h2] = li[h2] * alpha + sum;
        }

        // ---- P fragments (hi only) ----
        uint32_t ph[4][4];
#pragma unroll
        for (int kc = 0; kc < 4; ++kc) {
            const int jt = 2 * kc;
            ph[kc][0] = pack_h2(s[jt][0],     s[jt][1]);
            ph[kc][1] = pack_h2(s[jt][2],     s[jt][3]);
            ph[kc][2] = pack_h2(s[jt + 1][0], s[jt + 1][1]);
            ph[kc][3] = pack_h2(s[jt + 1][2], s[jt + 1][3]);
        }

        // ---- O += P.V (1-term on V) ----
        const uint32_t vbase = kvb + 2 * FTILE;
#pragma unroll
        for (int kc = 0; kc < 4; ++kc) {
#pragma unroll
            for (int np = 0; np < 4; ++np) {
                uint32_t vh4[4];
                uint32_t va = vbase + kc * (16 * FROW) + v_off + np * 32;
                LDM4T(vh4, va);
                MMA_F16(o[2 * np],     ph[kc], vh4[0], vh4[1]);
                MMA_F16(o[2 * np + 1], ph[kc], vh4[2], vh4[3]);
            }
        }
    }

    // ---- finalize: fp16 attention output (flat [b][s][h*64+d]) ----
    float inv0 = 1.0f / li[0];
    float inv1 = 1.0f / li[1];
#pragma unroll
    for (int j = 0; j < 8; ++j) {
        const int col = j * 8 + (lane & 3) * 2;
        size_t base0 = ((size_t)(b * SS + row0)) * DD + h * 64 + col;
        size_t base1 = ((size_t)(b * SS + row0 + 8)) * DD + h * 64 + col;
        *reinterpret_cast<__half2*>(OhP + base0) =
            __floats2half2_rn(o[j][0] * inv0, o[j][1] * inv0);
        *reinterpret_cast<__half2*>(OhP + base1) =
            __floats2half2_rn(o[j][2] * inv1, o[j][3] * inv1);
    }
}

// ---------------------------------------------------------------------------
// Host
// ---------------------------------------------------------------------------
extern "C" void kernel_launch(void* const* d_in, const int* in_sizes, int n_in,
                              void* d_out, int out_size)
{
    const float* x  = (const float*)d_in[0];
    const float* Wq = (const float*)d_in[1];
    const float* Wk = (const float*)d_in[2];
    const float* Wv = (const float*)d_in[3];
    const float* Wo = (const float*)d_in[4];
    float* out = (float*)d_out;

    __half *Xh, *Wqh, *Wkh, *Wkl, *Wvh, *Woh, *Oh;
    __half *Qbh, *Kbh, *Kbl, *Vbh;
    cudaGetSymbolAddress((void**)&Xh, g_Xh);
    cudaGetSymbolAddress((void**)&Wqh, g_Wqh);
    cudaGetSymbolAddress((void**)&Wkh, g_Wkh);
    cudaGetSymbolAddress((void**)&Wkl, g_Wkl);
    cudaGetSymbolAddress((void**)&Wvh, g_Wvh);
    cudaGetSymbolAddress((void**)&Woh, g_Woh);
    cudaGetSymbolAddress((void**)&Oh, g_Oh);
    cudaGetSymbolAddress((void**)&Qbh, g_Qbh);
    cudaGetSymbolAddress((void**)&Kbh, g_Kbh);
    cudaGetSymbolAddress((void**)&Kbl, g_Kbl);
    cudaGetSymbolAddress((void**)&Vbh, g_Vbh);

    const int SMEM_DYN = GSTG * STAGEB;   // 98304 -> 2 CTAs/SM
    cudaFuncSetAttribute(qkv_gemm, cudaFuncAttributeMaxDynamicSharedMemorySize, SMEM_DYN);
    cudaFuncSetAttribute(wo_gemm,  cudaFuncAttributeMaxDynamicSharedMemorySize, SMEM_DYN);
    cudaFuncSetAttribute(flash_mma, cudaFuncAttributeMaxDynamicSharedMemorySize, FSMEM);

    // single merged split launch (lo only for Wk)
    {
        SplitJobs jobs;
        jobs.in[0] = (const float4*)x;  jobs.hi[0] = (__half2*)Xh;  jobs.lo[0] = nullptr;
        jobs.in[1] = (const float4*)Wq; jobs.hi[1] = (__half2*)Wqh; jobs.lo[1] = nullptr;
        jobs.in[2] = (const float4*)Wk; jobs.hi[2] = (__half2*)Wkh; jobs.lo[2] = (__half2*)Wkl;
        jobs.in[3] = (const float4*)Wv; jobs.hi[3] = (__half2*)Wvh; jobs.lo[3] = nullptr;
        jobs.in[4] = (const float4*)Wo; jobs.hi[4] = (__half2*)Woh; jobs.lo[4] = nullptr;
        int n4s[5] = { BB * SS * DD / 4, HQ * DH * DD / 4, HKV * DH * DD / 4,
                       HKV * DH * DD / 4, DD * DD / 4 };
        int cum = 0;
        for (int k = 0; k < 5; ++k) { cum += n4s[k] / 256; jobs.blk_end[k] = cum; }
        split_all<<<cum, 256>>>(jobs);
    }

    // merged QKV projection (fused RoPE/scale/convert epilogue)
    qkv_gemm<<<dim3(24, 32), 128, SMEM_DYN>>>(Xh,
        Wqh, Wkh, Wkl, Wvh,
        Qbh, Kbh, Kbl, Vbh);

    // MMA flash attention (causal), outputs fp16
    flash_mma<<<dim3(SS / 128, HQ, BB), 256, FSMEM>>>(Qbh, Kbh, Kbl, Vbh, Oh);

    // output projection (1-term) -> fp32 result
    wo_gemm<<<dim3(16, 32), 128, SMEM_DYN>>>(Oh, Woh, out);
}

// round 14
// speedup vs baseline: 2.8239x; 1.1507x over previous
#include <cuda_runtime.h>
#include <cuda_fp16.h>
#include <math.h>
#include <stdint.h>

#define BB   2
#define SS   2048
#define DD   2048
#define HQ   32
#define HKV  8
#define DH   64
#define KDIM 2048

// ---------------------------------------------------------------------------
// Scratch (allocation-free rule: __device__ globals) — pure fp16 pipeline
// ---------------------------------------------------------------------------
__device__ __half g_Xh[(size_t)BB * SS * DD];
__device__ __half g_Wqh[(size_t)HQ * DH * DD];
__device__ __half g_Wkh[(size_t)HKV * DH * DD];
__device__ __half g_Wvh[(size_t)HKV * DH * DD];
__device__ __half g_Woh[(size_t)DD * DD];
__device__ __half g_Oh[(size_t)BB * SS * DD];

__device__ __half g_Qbh[(size_t)BB * HQ  * SS * DH];
__device__ __half g_Kbh[(size_t)BB * HKV * SS * DH];
__device__ __half g_Vbh[(size_t)BB * HKV * SS * DH];

// ---------------------------------------------------------------------------
// helpers
// ---------------------------------------------------------------------------
__device__ __forceinline__ uint32_t s2u(const void* p) {
    uint32_t r;
    asm("{ .reg .u64 t; cvta.to.shared.u64 t, %1; cvt.u32.u64 %0, t; }"
        : "=r"(r) : "l"(p));
    return r;
}

#define LDM4(r, addr)                                                         \
    asm volatile("ldmatrix.sync.aligned.m8n8.x4.shared.b16 {%0,%1,%2,%3}, [%4];" \
        : "=r"((r)[0]), "=r"((r)[1]), "=r"((r)[2]), "=r"((r)[3]) : "r"(addr))

#define LDM4T(r, addr)                                                        \
    asm volatile("ldmatrix.sync.aligned.m8n8.x4.trans.shared.b16 {%0,%1,%2,%3}, [%4];" \
        : "=r"((r)[0]), "=r"((r)[1]), "=r"((r)[2]), "=r"((r)[3]) : "r"(addr))

#define MMA_F16(c, a, b0, b1)                                                 \
    asm volatile("mma.sync.aligned.m16n8k16.row.col.f32.f16.f16.f32 "         \
        "{%0,%1,%2,%3}, {%4,%5,%6,%7}, {%8,%9}, {%0,%1,%2,%3};"               \
        : "+f"((c)[0]), "+f"((c)[1]), "+f"((c)[2]), "+f"((c)[3])              \
        : "r"((a)[0]), "r"((a)[1]), "r"((a)[2]), "r"((a)[3]), "r"(b0), "r"(b1))

#define CP_ASYNC16(dst, src)                                                  \
    asm volatile("cp.async.cg.shared.global [%0], [%1], 16;" :: "r"(dst), "l"(src))

__device__ __forceinline__ uint32_t pack_h2(float a, float b) {
    __half2 t = __floats2half2_rn(a, b);
    return *reinterpret_cast<uint32_t*>(&t);
}

// ---------------------------------------------------------------------------
// merged input converts: one launch, fp32 -> fp16 for all five inputs
// ---------------------------------------------------------------------------
struct SplitJobs {
    const float4* in[5];
    __half2* hi[5];
    int blk_end[5];
};

__global__ void split_all(SplitJobs jobs)
{
    int bx = blockIdx.x;
    int job = 0;
#pragma unroll
    for (int k = 0; k < 5; ++k)
        if (bx >= jobs.blk_end[k]) job = k + 1;
    int blk0 = (job == 0) ? 0 : jobs.blk_end[job - 1];
    int i = (bx - blk0) * blockDim.x + threadIdx.x;

    float4 a = jobs.in[job][i];
    jobs.hi[job][2 * i + 0] = __floats2half2_rn(a.x, a.y);
    jobs.hi[job][2 * i + 1] = __floats2half2_rn(a.z, a.w);
}

// ---------------------------------------------------------------------------
// core fp16 MMA loop (CTA 128x128x2048), 1-term
// 4 warps, warp tile 64x64. Stage = {Ah, Bh} = 16KB.
// XOR-swizzled smem (64B rows), 6-stage ring, depth-3 prefetch, 1 sync/iter,
// 96KB -> 2 CTAs/SM.
// ---------------------------------------------------------------------------
#define MATB   8192                 // 128 rows * 64 B
#define STAGEB 16384                // 2 * MATB
#define GSTG   6
#define KITERS (KDIM / 32)

struct GemmCore {
    float c[4][8][4];
};

__device__ __forceinline__ void gemm_mainloop(
    uint32_t sb, int tid, int lane, int wm, int wn,
    const __half* Ah_g, const __half* Bh_g,
    int m0, int n0, GemmCore& g)
{
#pragma unroll
    for (int i = 0; i < 4; ++i)
#pragma unroll
        for (int j = 0; j < 8; ++j)
#pragma unroll
            for (int r = 0; r < 4; ++r) g.c[i][j][r] = 0.f;

    const int a_row = wm * 64 + (lane & 15);
    const uint32_t a_base = (uint32_t)a_row * 64;
    const uint32_t a_swz  = (uint32_t)(((lane >> 4) ^ ((a_row >> 1) & 3)) << 4);

    const int b_row = wn * 64 + (lane >> 4) * 8 + (lane & 7);
    const uint32_t b_base = (uint32_t)b_row * 64;
    const uint32_t b_swz  = (uint32_t)((((lane >> 3) & 1) ^ ((b_row >> 1) & 3)) << 4);

    const __half* srcs[2] = { Ah_g, Bh_g };
    const int rowbase[2] = { m0, n0 };

    auto load_stage = [&](int s, int k0) {
#pragma unroll
        for (int i = 0; i < 8; ++i) {
            const int idx = tid + 128 * i;
            const int mat = idx >> 9;
            const int rem = idx & 511;
            const int row = rem >> 2;
            const int seg = rem & 3;
            uint32_t d = sb + s * STAGEB + mat * MATB + row * 64 +
                         ((seg ^ ((row >> 1) & 3)) << 4);
            const __half* p =
                srcs[mat] + (size_t)(rowbase[mat] + row) * KDIM + k0 + seg * 8;
            CP_ASYNC16(d, p);
        }
        asm volatile("cp.async.commit_group;");
    };

    load_stage(0, 0);
    load_stage(1, 32);
    load_stage(2, 64);

    for (int it = 0; it < KITERS; ++it) {
        if (it + 2 < KITERS) {
            asm volatile("cp.async.wait_group 2;");
        } else {
            asm volatile("cp.async.wait_group 0;");
        }
        __syncthreads();
        if (it + 3 < KITERS) {
            load_stage((it + 3) % GSTG, (it + 3) * 32);
        }

        const uint32_t st = sb + (it % GSTG) * STAGEB;
#pragma unroll
        for (int kk = 0; kk < 2; ++kk) {
            const uint32_t ksw = (uint32_t)(kk << 5);
            uint32_t bh[4][4];
#pragma unroll
            for (int j2 = 0; j2 < 4; ++j2) {
                LDM4(bh[j2], st + MATB + b_base + j2 * 1024 + (b_swz ^ ksw));
            }
#pragma unroll
            for (int i = 0; i < 4; ++i) {
                uint32_t ah[4];
                LDM4(ah, st + a_base + i * 1024 + (a_swz ^ ksw));
#pragma unroll
                for (int j = 0; j < 8; ++j) {
                    const uint32_t* bhp = &bh[j >> 1][(j & 1) * 2];
                    MMA_F16(g.c[i][j], ah, bhp[0], bhp[1]);
                }
            }
        }
    }
}

// ---------------------------------------------------------------------------
// merged QKV projection: grid (24, 32), 128 threads, all 1-term
// Q (rope, 1/8), K (rope), V — all fp16 out, head layout
// ---------------------------------------------------------------------------
__global__ __launch_bounds__(128, 2)
void qkv_gemm(const __half* __restrict__ Xh_g,
              const __half* __restrict__ Wqh_g,
              const __half* __restrict__ Wkh_g,
              const __half* __restrict__ Wvh_g,
              __half* __restrict__ Qh,
              __half* __restrict__ Kh,
              __half* __restrict__ Vh)
{
    extern __shared__ __align__(128) char smem[];
    const uint32_t sb = s2u(smem);

    const int tid  = threadIdx.x;
    const int lane = tid & 31;
    const int w    = tid >> 5;
    const int wm   = w & 1;
    const int wn   = w >> 1;
    const int bx   = blockIdx.x;
    const int m0   = blockIdx.y * 128;

    const __half *Bh_g;
    __half *dH;
    int n0, Hn;
    bool rope;
    float scale;
    if (bx < 16) {
        Bh_g = Wqh_g; dH = Qh;
        n0 = bx * 128; Hn = HQ; rope = true; scale = 0.125f;
    } else if (bx < 20) {
        Bh_g = Wkh_g; dH = Kh;
        n0 = (bx - 16) * 128; Hn = HKV; rope = true; scale = 1.0f;
    } else {
        Bh_g = Wvh_g; dH = Vh;
        n0 = (bx - 20) * 128; Hn = HKV; rope = false; scale = 1.0f;
    }

    GemmCore g;
    gemm_mainloop(sb, tid, lane, wm, wn, Xh_g, Bh_g, m0, n0, g);

#pragma unroll
    for (int i = 0; i < 4; ++i) {
        const int r0 = m0 + wm * 64 + i * 16 + (lane >> 2);
#pragma unroll
        for (int j = 0; j < 8; ++j) {
            const int col = n0 + wn * 64 + j * 8 + (lane & 3) * 2;
#pragma unroll
            for (int half = 0; half < 2; ++half) {
                const int row = r0 + half * 8;
                float x1 = g.c[i][j][half * 2];
                float x2 = g.c[i][j][half * 2 + 1];
                const int bidx = row >> 11;
                const int sRow = row & (SS - 1);
                const int hh = col >> 6, d0 = col & 63;
                size_t base = ((((size_t)bidx * Hn + hh) * SS + sRow) << 6) + d0;
                if (rope) {
                    float inv = exp2f(-(float)d0 * (13.287712379549449f / 64.0f));
                    float sn, cs;
                    sincosf((float)sRow * inv, &sn, &cs);
                    float y1 = x1 * cs - x2 * sn;
                    float y2 = x1 * sn + x2 * cs;
                    x1 = y1 * scale;
                    x2 = y2 * scale;
                }
                *reinterpret_cast<__half2*>(dH + base) =
                    __floats2half2_rn(x1, x2);
            }
        }
    }
}

// ---------------------------------------------------------------------------
// output projection (1-term fp16): fp32 flat result, 128 threads
// ---------------------------------------------------------------------------
__global__ __launch_bounds__(128, 2)
void wo_gemm(const __half* __restrict__ Ah_g,
             const __half* __restrict__ Bh_g,
             float* __restrict__ dst)
{
    extern __shared__ __align__(128) char smem[];
    const uint32_t sb = s2u(smem);

    const int tid  = threadIdx.x;
    const int lane = tid & 31;
    const int w    = tid >> 5;
    const int wm   = w & 1;
    const int wn   = w >> 1;
    const int m0   = blockIdx.y * 128;
    const int n0   = blockIdx.x * 128;

    GemmCore g;
    gemm_mainloop(sb, tid, lane, wm, wn, Ah_g, Bh_g, m0, n0, g);

#pragma unroll
    for (int i = 0; i < 4; ++i) {
        const int r0 = m0 + wm * 64 + i * 16 + (lane >> 2);
#pragma unroll
        for (int j = 0; j < 8; ++j) {
            const int col = n0 + wn * 64 + j * 8 + (lane & 3) * 2;
#pragma unroll
            for (int half = 0; half < 2; ++half) {
                const int row = r0 + half * 8;
                *reinterpret_cast<float2*>(dst + (size_t)row * DD + col) =
                    make_float2(g.c[i][j][half * 2], g.c[i][j][half * 2 + 1]);
            }
        }
    }
}

// ---------------------------------------------------------------------------
// MMA flash attention (causal, GQA): BM=128 (8 warps x 16 rows), BN=64, Dh=64
// pure fp16 1-term QK and PV. 6-stage KV ring of 18KB slots {Kh,Vh};
// Q (18KB) staged through slot 0. smem 110592 -> 2 CTAs/SM.
// ---------------------------------------------------------------------------
#define FROW   144
#define FTILE  9216                // 64 rows * 144 B (per matrix)
#define KVSTG  18432               // 2 * FTILE (Kh,Vh)
#define FSTG   6
#define FSMEM  (FSTG * KVSTG)      // 110592

__global__ __launch_bounds__(256, 2)
void flash_mma(const __half* __restrict__ Qh_g,
               const __half* __restrict__ Kh_g,
               const __half* __restrict__ Vh_g,
               __half* __restrict__ OhP)
{
    extern __shared__ __align__(128) char fsm[];
    const uint32_t sb = s2u(fsm);

    const int tid  = threadIdx.x;
    const int lane = tid & 31;
    const int w    = tid >> 5;
    const int qi   = gridDim.x - 1 - blockIdx.x;   // longest CTAs first
    const int qb   = qi * 128;
    const int h    = blockIdx.y;
    const int b    = blockIdx.z;
    const int kh   = h >> 2;

    const size_t qoff  = (((size_t)b * HQ + h) * SS + qb) * 64;
    const size_t kvrow = ((size_t)b * HKV + kh) * SS;

    const uint32_t a_off =
        (uint32_t)((w * 16 + (lane & 15)) * FROW + (lane >> 4) * 16);
    const uint32_t kb_off =
        (uint32_t)(((lane >> 4) * 8 + (lane & 7)) * FROW + ((lane >> 3) & 1) * 16);
    const uint32_t v_off =
        (uint32_t)((lane & 15) * FROW + (lane >> 4) * 16);

    // ---- prologue: Q hi staged through slot 0 (exactly one ring slot) ----
#pragma unroll
    for (int i = 0; i < 4; ++i) {
        int idx = tid + 256 * i;
        int row = idx >> 3;
        int seg = idx & 7;
        uint32_t d = sb + row * FROW + seg * 16;
        CP_ASYNC16(d, Qh_g + qoff + row * 64 + seg * 8);
    }
    asm volatile("cp.async.commit_group;");
    asm volatile("cp.async.wait_group 0;");
    __syncthreads();

    uint32_t qh[4][4];
#pragma unroll
    for (int kc = 0; kc < 4; ++kc)
        LDM4(qh[kc], sb + a_off + kc * 32);
    __syncthreads();   // all warps own Q frags before slot 0 is recycled

    auto load_kv = [&](int s, int j0) {
        const __half* srcs[2] = { Kh_g, Vh_g };
        const size_t off = (kvrow + j0) * 64;
#pragma unroll
        for (int i = 0; i < 4; ++i) {
            int idx = tid + 256 * i;
            int mat = idx >> 9;
            int rem = idx & 511;
            int row = rem >> 3;
            int seg = rem & 7;
            uint32_t d = sb + s * KVSTG + mat * FTILE + row * FROW + seg * 16;
            CP_ASYNC16(d, srcs[mat] + off + row * 64 + seg * 8);
        }
        asm volatile("cp.async.commit_group;");
    };

    const int nb = qb / 64 + 2;
    load_kv(0, 0);
    if (nb > 1) load_kv(1, 64);
    if (nb > 2) load_kv(2, 128);

    float o[8][4];
#pragma unroll
    for (int j = 0; j < 8; ++j)
#pragma unroll
        for (int r = 0; r < 4; ++r) o[j][r] = 0.f;
    float mi[2] = { -1e30f, -1e30f };
    float li[2] = { 0.f, 0.f };

    const int row0 = qb + w * 16 + (lane >> 2);

    for (int it = 0; it < nb; ++it) {
        if (it + 2 < nb) {
            asm volatile("cp.async.wait_group 2;");
        } else {
            asm volatile("cp.async.wait_group 0;");
        }
        __syncthreads();
        if (it + 3 < nb) load_kv((it + 3) % FSTG, (it + 3) * 64);

        const uint32_t kvb = sb + (it % FSTG) * KVSTG;
        const int j0 = it * 64;

        // ---- S = Q.K^T (1-term) ----
        float s[8][4];
#pragma unroll
        for (int j = 0; j < 8; ++j)
#pragma unroll
            for (int r = 0; r < 4; ++r) s[j][r] = 0.f;

#pragma unroll
        for (int kc = 0; kc < 4; ++kc) {
            uint32_t bh[4][4];
#pragma unroll
            for (int j2 = 0; j2 < 4; ++j2) {
                LDM4(bh[j2], kvb + j2 * (16 * FROW) + kb_off + kc * 32);
            }
#pragma unroll
            for (int j = 0; j < 8; ++j) {
                const uint32_t* bhp = &bh[j >> 1][(j & 1) * 2];
                MMA_F16(s[j], qh[kc], bhp[0], bhp[1]);
            }
        }

        // ---- causal mask ----
        if (j0 + 63 > qb + w * 16) {
#pragma unroll
            for (int j = 0; j < 8; ++j)
#pragma unroll
                for (int r = 0; r < 4; ++r) {
                    int col = j0 + j * 8 + (lane & 3) * 2 + (r & 1);
                    int row = row0 + (r >> 1) * 8;
                    if (col > row) s[j][r] = -1e30f;
                }
        }

        // ---- online softmax ----
#pragma unroll
        for (int h2 = 0; h2 < 2; ++h2) {
            float mt = -1e30f;
#pragma unroll
            for (int j = 0; j < 8; ++j) {
                mt = fmaxf(mt, s[j][h2 * 2]);
                mt = fmaxf(mt, s[j][h2 * 2 + 1]);
            }
            mt = fmaxf(mt, __shfl_xor_sync(0xffffffffu, mt, 1));
            mt = fmaxf(mt, __shfl_xor_sync(0xffffffffu, mt, 2));
            float mnew  = fmaxf(mi[h2], mt);
            float alpha = __expf(mi[h2] - mnew);
            mi[h2] = mnew;
            float sum = 0.f;
#pragma unroll
            for (int j = 0; j < 8; ++j) {
                float p0 = __expf(s[j][h2 * 2]     - mnew);
                float p1 = __expf(s[j][h2 * 2 + 1] - mnew);
                s[j][h2 * 2]     = p0;
                s[j][h2 * 2 + 1] = p1;
                sum += p0 + p1;
                o[j][h2 * 2]     *= alpha;
                o[j][h2 * 2 + 1] *= alpha;
            }
            sum += __shfl_xor_sync(0xffffffffu, sum, 1);
            sum += __shfl_xor_sync(0xffffffffu, sum, 2);
            li[h2] = li[h2] * alpha + sum;
        }

        // ---- P fragments ----
        uint32_t ph[4][4];
#pragma unroll
        for (int kc = 0; kc < 4; ++kc) {
            const int jt = 2 * kc;
            ph[kc][0] = pack_h2(s[jt][0],     s[jt][1]);
            ph[kc][1] = pack_h2(s[jt][2],     s[jt][3]);
            ph[kc][2] = pack_h2(s[jt + 1][0], s[jt + 1][1]);
            ph[kc][3] = pack_h2(s[jt + 1][2], s[jt + 1][3]);
        }

        // ---- O += P.V (1-term) ----
        const uint32_t vbase = kvb + FTILE;
#pragma unroll
        for (int kc = 0; kc < 4; ++kc) {
#pragma unroll
            for (int np = 0; np < 4; ++np) {
                uint32_t vh4[4];
                LDM4T(vh4, vbase + kc * (16 * FROW) + v_off + np * 32);
                MMA_F16(o[2 * np],     ph[kc], vh4[0], vh4[1]);
                MMA_F16(o[2 * np + 1], ph[kc], vh4[2], vh4[3]);
            }
        }
    }

    // ---- finalize: fp16 attention output (flat [b][s][h*64+d]) ----
    float inv0 = 1.0f / li[0];
    float inv1 = 1.0f / li[1];
#pragma unroll
    for (int j = 0; j < 8; ++j) {
        const int col = j * 8 + (lane & 3) * 2;
        size_t base0 = ((size_t)(b * SS + row0)) * DD + h * 64 + col;
        size_t base1 = ((size_t)(b * SS + row0 + 8)) * DD + h * 64 + col;
        *reinterpret_cast<__half2*>(OhP + base0) =
            __floats2half2_rn(o[j][0] * inv0, o[j][1] * inv0);
        *reinterpret_cast<__half2*>(OhP + base1) =
            __floats2half2_rn(o[j][2] * inv1, o[j][3] * inv1);
    }
}

// ---------------------------------------------------------------------------
// Host
// ---------------------------------------------------------------------------
extern "C" void kernel_launch(void* const* d_in, const int* in_sizes, int n_in,
                              void* d_out, int out_size)
{
    const float* x  = (const float*)d_in[0];
    const float* Wq = (const float*)d_in[1];
    const float* Wk = (const float*)d_in[2];
    const float* Wv = (const float*)d_in[3];
    const float* Wo = (const float*)d_in[4];
    float* out = (float*)d_out;

    __half *Xh, *Wqh, *Wkh, *Wvh, *Woh, *Oh;
    __half *Qbh, *Kbh, *Vbh;
    cudaGetSymbolAddress((void**)&Xh, g_Xh);
    cudaGetSymbolAddress((void**)&Wqh, g_Wqh);
    cudaGetSymbolAddress((void**)&Wkh, g_Wkh);
    cudaGetSymbolAddress((void**)&Wvh, g_Wvh);
    cudaGetSymbolAddress((void**)&Woh, g_Woh);
    cudaGetSymbolAddress((void**)&Oh, g_Oh);
    cudaGetSymbolAddress((void**)&Qbh, g_Qbh);
    cudaGetSymbolAddress((void**)&Kbh, g_Kbh);
    cudaGetSymbolAddress((void**)&Vbh, g_Vbh);

    const int SMEM_DYN = GSTG * STAGEB;   // 98304 -> 2 CTAs/SM
    cudaFuncSetAttribute(qkv_gemm, cudaFuncAttributeMaxDynamicSharedMemorySize, SMEM_DYN);
    cudaFuncSetAttribute(wo_gemm,  cudaFuncAttributeMaxDynamicSharedMemorySize, SMEM_DYN);
    cudaFuncSetAttribute(flash_mma, cudaFuncAttributeMaxDynamicSharedMemorySize, FSMEM);

    // single merged convert launch
    {
        SplitJobs jobs;
        jobs.in[0] = (const float4*)x;  jobs.hi[0] = (__half2*)Xh;
        jobs.in[1] = (const float4*)Wq; jobs.hi[1] = (__half2*)Wqh;
        jobs.in[2] = (const float4*)Wk; jobs.hi[2] = (__half2*)Wkh;
        jobs.in[3] = (const float4*)Wv; jobs.hi[3] = (__half2*)Wvh;
        jobs.in[4] = (const float4*)Wo; jobs.hi[4] = (__half2*)Woh;
        int n4s[5] = { BB * SS * DD / 4, HQ * DH * DD / 4, HKV * DH * DD / 4,
                       HKV * DH * DD / 4, DD * DD / 4 };
        int cum = 0;
        for (int k = 0; k < 5; ++k) { cum += n4s[k] / 256; jobs.blk_end[k] = cum; }
        split_all<<<cum, 256>>>(jobs);
    }

    // merged QKV projection (fused RoPE/scale/convert epilogue)
    qkv_gemm<<<dim3(24, 32), 128, SMEM_DYN>>>(Xh, Wqh, Wkh, Wvh, Qbh, Kbh, Vbh);

    // MMA flash attention (causal), outputs fp16
    flash_mma<<<dim3(SS / 128, HQ, BB), 256, FSMEM>>>(Qbh, Kbh, Vbh, Oh);

    // output projection -> fp32 result
    wo_gemm<<<dim3(16, 32), 128, SMEM_DYN>>>(Oh, Woh, out);
}